// round 7
// baseline (speedup 1.0000x reference)
#include <cuda_runtime.h>

#define HD 128
#define NMAX 100000
#define EMAX 1600000
#define SCAN_B 1024

// -------- scratch (device globals; no allocations allowed) --------
__device__ float g_deg[NMAX];
__device__ float g_dinv[NMAX];
__device__ float g_A[(size_t)NMAX * HD];   // ping
__device__ float g_B[(size_t)NMAX * HD];   // pong
__device__ float g_as[NMAX];
__device__ float g_ad[NMAX];
__device__ int   g_cnt[NMAX];
__device__ int   g_rowptr[NMAX + 1];
__device__ int   g_cur[NMAX + 1];
__device__ int   g_bsum[128];
__device__ int   g_csr_src[EMAX];
__device__ float g_csr_coef[EMAX];

__device__ __forceinline__ float leaky(float x) { return x > 0.f ? x : 0.2f * x; }

// ================= CSR build =================
__global__ void k_zero(int n) {
    int i = blockIdx.x * blockDim.x + threadIdx.x;
    if (i < n) { g_cnt[i] = 0; g_deg[i] = 1.0f; }   // self-loop weight 1
    if (i == 0) { g_rowptr[0] = 0; g_cur[0] = 0; }
}

__global__ void k_count_deg(const int* __restrict__ dst, const float* __restrict__ ew, int e) {
    int i = blockIdx.x * blockDim.x + threadIdx.x;
    if (i >= e) return;
    int d = dst[i];
    atomicAdd(&g_cnt[d], 1);
    atomicAdd(&g_deg[d], ew[i]);
}

__global__ __launch_bounds__(SCAN_B) void k_scan1(int n) {
    __shared__ int s[SCAN_B];
    int t = threadIdx.x;
    int g = blockIdx.x * SCAN_B + t;
    int v = (g < n) ? g_cnt[g] : 0;
    s[t] = v;
    __syncthreads();
    #pragma unroll
    for (int o = 1; o < SCAN_B; o <<= 1) {
        int x = (t >= o) ? s[t - o] : 0;
        __syncthreads();
        s[t] += x;
        __syncthreads();
    }
    if (g < n) g_rowptr[g + 1] = s[t];            // block-local inclusive
    if (t == SCAN_B - 1) g_bsum[blockIdx.x] = s[t];
}

// scan of block sums folded in (each block redundantly scans <=128 sums)
__global__ __launch_bounds__(256) void k_scan3_dinv(int n, int nb) {
    __shared__ int s[128];
    int t = threadIdx.x;
    int v = 0;
    if (t < 128) { v = (t < nb) ? g_bsum[t] : 0; s[t] = v; }
    __syncthreads();
    #pragma unroll
    for (int o = 1; o < 128; o <<= 1) {
        int x = (t >= o && t < 128) ? s[t - o] : 0;
        __syncthreads();
        if (t < 128) s[t] += x;
        __syncthreads();
    }
    if (t < 128) s[t] -= v;                        // exclusive
    __syncthreads();
    int i = blockIdx.x * blockDim.x + t;
    if (i >= n) return;
    int val = g_rowptr[i + 1] + s[i >> 10];
    g_rowptr[i + 1] = val;
    g_cur[i + 1] = val;
    float d = g_deg[i];
    g_dinv[i] = d > 0.f ? rsqrtf(d) : 0.f;
}

__global__ void k_fill(const int* __restrict__ src, const int* __restrict__ dst,
                       const float* __restrict__ ew, int e) {
    int i = blockIdx.x * blockDim.x + threadIdx.x;
    if (i >= e) return;
    int s = src[i], d = dst[i];
    int pos = atomicAdd(&g_cur[d], 1);
    g_csr_src[pos] = s;
    g_csr_coef[pos] = g_dinv[s] * ew[i] * g_dinv[d];
}

// ======= per-node GCN aggregate (warp-collective): relu(bias + self + gather) =======
__device__ __forceinline__ float4 gcn_aggregate(const float* __restrict__ A, int node,
                                                int lane, float4 b) {
    int beg = g_rowptr[node], end = g_rowptr[node + 1];
    float di = g_dinv[node];
    float cself = di * di;
    float4 av = *(const float4*)(A + (size_t)node * HD + lane * 4);
    float4 acc;
    acc.x = fmaf(cself, av.x, b.x);
    acc.y = fmaf(cself, av.y, b.y);
    acc.z = fmaf(cself, av.z, b.z);
    acc.w = fmaf(cself, av.w, b.w);

    for (int j0 = beg; j0 < end; j0 += 32) {
        int idx = j0 + lane;
        int s = 0; float c = 0.f;
        if (idx < end) { s = g_csr_src[idx]; c = g_csr_coef[idx]; }
        int m = min(32, end - j0);
        int j = 0;
        for (; j + 1 < m; j += 2) {
            int   s0 = __shfl_sync(0xffffffffu, s, j);
            float c0 = __shfl_sync(0xffffffffu, c, j);
            int   s1 = __shfl_sync(0xffffffffu, s, j + 1);
            float c1 = __shfl_sync(0xffffffffu, c, j + 1);
            float4 v0 = *(const float4*)(A + (size_t)s0 * HD + lane * 4);
            float4 v1 = *(const float4*)(A + (size_t)s1 * HD + lane * 4);
            acc.x = fmaf(c0, v0.x, acc.x); acc.y = fmaf(c0, v0.y, acc.y);
            acc.z = fmaf(c0, v0.z, acc.z); acc.w = fmaf(c0, v0.w, acc.w);
            acc.x = fmaf(c1, v1.x, acc.x); acc.y = fmaf(c1, v1.y, acc.y);
            acc.z = fmaf(c1, v1.z, acc.z); acc.w = fmaf(c1, v1.w, acc.w);
        }
        if (j < m) {
            int   s0 = __shfl_sync(0xffffffffu, s, j);
            float c0 = __shfl_sync(0xffffffffu, c, j);
            float4 v0 = *(const float4*)(A + (size_t)s0 * HD + lane * 4);
            acc.x = fmaf(c0, v0.x, acc.x); acc.y = fmaf(c0, v0.y, acc.y);
            acc.z = fmaf(c0, v0.z, acc.z); acc.w = fmaf(c0, v0.w, acc.w);
        }
    }
    acc.x = fmaxf(acc.x, 0.f); acc.y = fmaxf(acc.y, 0.f);
    acc.z = fmaxf(acc.z, 0.f); acc.w = fmaxf(acc.w, 0.f);
    return acc;
}

// ======= shared GEMM compute: Y[tile] = xs(64x128) @ wsh(128x128) =======
template<bool DOTS>
__device__ __forceinline__ void gemm_compute(const float* __restrict__ xs,
                                             const float* __restrict__ wsh,
                                             float* __restrict__ Y,
                                             const float* __restrict__ asrc,
                                             const float* __restrict__ adst,
                                             int row0, int n, int t) {
    const int cx = t & 31;
    const int ry = t >> 5;

    float4 acc[8];
    #pragma unroll
    for (int j = 0; j < 8; j++) acc[j] = make_float4(0.f, 0.f, 0.f, 0.f);

    #pragma unroll 4
    for (int k0 = 0; k0 < HD; k0 += 4) {
        float4 w0 = *(const float4*)(wsh + (k0 + 0) * HD + cx * 4);
        float4 w1 = *(const float4*)(wsh + (k0 + 1) * HD + cx * 4);
        float4 w2 = *(const float4*)(wsh + (k0 + 2) * HD + cx * 4);
        float4 w3 = *(const float4*)(wsh + (k0 + 3) * HD + cx * 4);
        #pragma unroll
        for (int j = 0; j < 8; j++) {
            float4 xv = *(const float4*)(xs + (ry * 8 + j) * HD + k0);
            acc[j].x = fmaf(xv.x, w0.x, acc[j].x);
            acc[j].y = fmaf(xv.x, w0.y, acc[j].y);
            acc[j].z = fmaf(xv.x, w0.z, acc[j].z);
            acc[j].w = fmaf(xv.x, w0.w, acc[j].w);
            acc[j].x = fmaf(xv.y, w1.x, acc[j].x);
            acc[j].y = fmaf(xv.y, w1.y, acc[j].y);
            acc[j].z = fmaf(xv.y, w1.z, acc[j].z);
            acc[j].w = fmaf(xv.y, w1.w, acc[j].w);
            acc[j].x = fmaf(xv.z, w2.x, acc[j].x);
            acc[j].y = fmaf(xv.z, w2.y, acc[j].y);
            acc[j].z = fmaf(xv.z, w2.z, acc[j].z);
            acc[j].w = fmaf(xv.z, w2.w, acc[j].w);
            acc[j].x = fmaf(xv.w, w3.x, acc[j].x);
            acc[j].y = fmaf(xv.w, w3.y, acc[j].y);
            acc[j].z = fmaf(xv.w, w3.z, acc[j].z);
            acc[j].w = fmaf(xv.w, w3.w, acc[j].w);
        }
    }

    float4 s4, d4;
    if (DOTS) {
        s4 = *(const float4*)(asrc + cx * 4);
        d4 = *(const float4*)(adst + cx * 4);
    }

    #pragma unroll
    for (int j = 0; j < 8; j++) {
        int gr = row0 + ry * 8 + j;
        if (gr < n) *(float4*)(Y + (size_t)gr * HD + cx * 4) = acc[j];
        if (DOTS) {
            float ps = acc[j].x * s4.x + acc[j].y * s4.y + acc[j].z * s4.z + acc[j].w * s4.w;
            float pd = acc[j].x * d4.x + acc[j].y * d4.y + acc[j].z * d4.z + acc[j].w * d4.w;
            #pragma unroll
            for (int o = 16; o; o >>= 1) {
                ps += __shfl_xor_sync(0xffffffffu, ps, o);
                pd += __shfl_xor_sync(0xffffffffu, pd, o);
            }
            if (cx == 0 && gr < n) { g_as[gr] = ps; g_ad[gr] = pd; }
        }
    }
}

// ================= k1: pure GEMM (Y = X @ W), W staged in smem =================
__global__ __launch_bounds__(256) void k_gemm_plain(const float* __restrict__ X,
                                                    const float* __restrict__ W,
                                                    float* __restrict__ Y, int n) {
    extern __shared__ float smem[];
    float* xs  = smem;                // 64*128
    float* wsh = smem + 64 * HD;      // 128*128
    const int t = threadIdx.x;
    const int row0 = blockIdx.x * 64;

    #pragma unroll
    for (int i = t; i < 128 * 32; i += 256)
        ((float4*)wsh)[i] = ((const float4*)W)[i];

    #pragma unroll
    for (int i = t; i < 64 * 32; i += 256) {
        int r = i >> 5, c4 = i & 31;
        int gr = row0 + r;
        float4 v = make_float4(0.f, 0.f, 0.f, 0.f);
        if (gr < n) v = *(const float4*)(X + (size_t)gr * HD + c4 * 4);
        *(float4*)(xs + r * HD + c4 * 4) = v;
    }
    __syncthreads();

    gemm_compute<false>(xs, wsh, Y, nullptr, nullptr, row0, n, t);
}

// ====== k2/k3: fused GCN-aggregate + GEMM: Y = relu(b + A_hat @ Asrc) @ W ======
template<bool DOTS>
__global__ __launch_bounds__(256) void k_agg_gemm(const float* __restrict__ Asrc,
                                                  const float* __restrict__ W,
                                                  float* __restrict__ Y,
                                                  const float* __restrict__ bias,
                                                  const float* __restrict__ asrc,
                                                  const float* __restrict__ adst,
                                                  int n) {
    extern __shared__ float smem[];
    float* xs  = smem;
    float* wsh = smem + 64 * HD;
    const int t = threadIdx.x;
    const int row0 = blockIdx.x * 64;
    const int warp = t >> 5;
    const int lane = t & 31;

    #pragma unroll
    for (int i = t; i < 128 * 32; i += 256)
        ((float4*)wsh)[i] = ((const float4*)W)[i];

    float4 b = *(const float4*)(bias + lane * 4);
    #pragma unroll
    for (int j = 0; j < 8; j++) {
        int r = warp * 8 + j;
        int node = row0 + r;
        float4 acc = make_float4(0.f, 0.f, 0.f, 0.f);
        if (node < n) acc = gcn_aggregate(Asrc, node, lane, b);
        *(float4*)(xs + r * HD + lane * 4) = acc;
    }
    __syncthreads();

    gemm_compute<DOTS>(xs, wsh, Y, asrc, adst, row0, n, t);
}

// ====== k4: GAT softmax-aggregate + fused classifier (warp per node) ======
__global__ __launch_bounds__(256) void k_gat_out(const float* __restrict__ bg,
                                                 const float* __restrict__ Wc,
                                                 const float* __restrict__ bc,
                                                 float* __restrict__ out, int n) {
    int w = (blockIdx.x * blockDim.x + threadIdx.x) >> 5;
    if (w >= n) return;
    int lane = threadIdx.x & 31;
    int beg = g_rowptr[w], end = g_rowptr[w + 1];

    float ad_d = g_ad[w];
    float a_self = leaky(g_as[w] + ad_d);

    // pass 1: max over attention logits
    float mx = a_self;
    for (int idx = beg + lane; idx < end; idx += 32) {
        int s = g_csr_src[idx];
        mx = fmaxf(mx, leaky(g_as[s] + ad_d));
    }
    #pragma unroll
    for (int o = 16; o; o >>= 1)
        mx = fmaxf(mx, __shfl_xor_sync(0xffffffffu, mx, o));

    // pass 2: denom + weighted gather
    float wself = expf(a_self - mx);
    float denp = 0.f;
    float4 av = *(const float4*)(g_A + (size_t)w * HD + lane * 4);
    float4 acc;
    acc.x = wself * av.x; acc.y = wself * av.y;
    acc.z = wself * av.z; acc.w = wself * av.w;

    for (int j0 = beg; j0 < end; j0 += 32) {
        int idx = j0 + lane;
        int s = 0; float ww = 0.f;
        if (idx < end) {
            s = g_csr_src[idx];
            ww = expf(leaky(g_as[s] + ad_d) - mx);
            denp += ww;
        }
        int m = min(32, end - j0);
        int j = 0;
        for (; j + 1 < m; j += 2) {
            int   s0 = __shfl_sync(0xffffffffu, s, j);
            float w0 = __shfl_sync(0xffffffffu, ww, j);
            int   s1 = __shfl_sync(0xffffffffu, s, j + 1);
            float w1 = __shfl_sync(0xffffffffu, ww, j + 1);
            float4 v0 = *(const float4*)(g_A + (size_t)s0 * HD + lane * 4);
            float4 v1 = *(const float4*)(g_A + (size_t)s1 * HD + lane * 4);
            acc.x = fmaf(w0, v0.x, acc.x); acc.y = fmaf(w0, v0.y, acc.y);
            acc.z = fmaf(w0, v0.z, acc.z); acc.w = fmaf(w0, v0.w, acc.w);
            acc.x = fmaf(w1, v1.x, acc.x); acc.y = fmaf(w1, v1.y, acc.y);
            acc.z = fmaf(w1, v1.z, acc.z); acc.w = fmaf(w1, v1.w, acc.w);
        }
        if (j < m) {
            int   s0 = __shfl_sync(0xffffffffu, s, j);
            float w0 = __shfl_sync(0xffffffffu, ww, j);
            float4 v0 = *(const float4*)(g_A + (size_t)s0 * HD + lane * 4);
            acc.x = fmaf(w0, v0.x, acc.x); acc.y = fmaf(w0, v0.y, acc.y);
            acc.z = fmaf(w0, v0.z, acc.z); acc.w = fmaf(w0, v0.w, acc.w);
        }
    }
    #pragma unroll
    for (int o = 16; o; o >>= 1)
        denp += __shfl_xor_sync(0xffffffffu, denp, o);
    float inv = 1.0f / (denp + wself);

    // relu(gat + bg), then classifier: out[16] = v @ Wc + bc
    float4 b = *(const float4*)(bg + lane * 4);
    float vv[4];
    vv[0] = fmaxf(fmaf(acc.x, inv, b.x), 0.f);
    vv[1] = fmaxf(fmaf(acc.y, inv, b.y), 0.f);
    vv[2] = fmaxf(fmaf(acc.z, inv, b.z), 0.f);
    vv[3] = fmaxf(fmaf(acc.w, inv, b.w), 0.f);

    float o16[16];
    #pragma unroll
    for (int c = 0; c < 16; c++) o16[c] = 0.f;
    #pragma unroll
    for (int kk = 0; kk < 4; kk++) {
        const float4* wr = (const float4*)(Wc + (size_t)(lane * 4 + kk) * 16);
        float4 w0 = wr[0], w1 = wr[1], w2 = wr[2], w3 = wr[3];
        float f = vv[kk];
        o16[0]  = fmaf(f, w0.x, o16[0]);  o16[1]  = fmaf(f, w0.y, o16[1]);
        o16[2]  = fmaf(f, w0.z, o16[2]);  o16[3]  = fmaf(f, w0.w, o16[3]);
        o16[4]  = fmaf(f, w1.x, o16[4]);  o16[5]  = fmaf(f, w1.y, o16[5]);
        o16[6]  = fmaf(f, w1.z, o16[6]);  o16[7]  = fmaf(f, w1.w, o16[7]);
        o16[8]  = fmaf(f, w2.x, o16[8]);  o16[9]  = fmaf(f, w2.y, o16[9]);
        o16[10] = fmaf(f, w2.z, o16[10]); o16[11] = fmaf(f, w2.w, o16[11]);
        o16[12] = fmaf(f, w3.x, o16[12]); o16[13] = fmaf(f, w3.y, o16[13]);
        o16[14] = fmaf(f, w3.z, o16[14]); o16[15] = fmaf(f, w3.w, o16[15]);
    }
    #pragma unroll
    for (int c = 0; c < 16; c++) {
        #pragma unroll
        for (int o = 16; o; o >>= 1)
            o16[c] += __shfl_xor_sync(0xffffffffu, o16[c], o);
    }
    if (lane == 0) {
        float4 bc0 = ((const float4*)bc)[0];
        float4 bc1 = ((const float4*)bc)[1];
        float4 bc2 = ((const float4*)bc)[2];
        float4 bc3 = ((const float4*)bc)[3];
        float4* op = (float4*)(out + (size_t)w * 16);
        op[0] = make_float4(o16[0] + bc0.x, o16[1] + bc0.y, o16[2] + bc0.z, o16[3] + bc0.w);
        op[1] = make_float4(o16[4] + bc1.x, o16[5] + bc1.y, o16[6] + bc1.z, o16[7] + bc1.w);
        op[2] = make_float4(o16[8] + bc2.x, o16[9] + bc2.y, o16[10] + bc2.z, o16[11] + bc2.w);
        op[3] = make_float4(o16[12] + bc3.x, o16[13] + bc3.y, o16[14] + bc3.z, o16[15] + bc3.w);
    }
}

static inline int ceildiv(int a, int b) { return (a + b - 1) / b; }

extern "C" void kernel_launch(void* const* d_in, const int* in_sizes, int n_in,
                              void* d_out, int out_size) {
    const float* x       = (const float*)d_in[0];
    const int*   ei      = (const int*)d_in[1];
    const float* ew      = (const float*)d_in[2];
    const float* W1      = (const float*)d_in[3];
    const float* b1      = (const float*)d_in[4];
    const float* W2      = (const float*)d_in[5];
    const float* b2      = (const float*)d_in[6];
    const float* Wg      = (const float*)d_in[7];
    const float* att_src = (const float*)d_in[8];
    const float* att_dst = (const float*)d_in[9];
    const float* bg      = (const float*)d_in[10];
    const float* Wc      = (const float*)d_in[11];
    const float* bc      = (const float*)d_in[12];

    int n = in_sizes[0] / HD;
    int e = in_sizes[2];
    const int* src = ei;
    const int* dst = ei + e;

    float *dA = nullptr, *dB = nullptr;
    cudaGetSymbolAddress((void**)&dA, g_A);
    cudaGetSymbolAddress((void**)&dB, g_B);

    const int SMEM = (64 * HD + 128 * HD) * (int)sizeof(float);   // 98304
    static bool attr_done = false;
    if (!attr_done) {
        cudaFuncSetAttribute(k_gemm_plain, cudaFuncAttributeMaxDynamicSharedMemorySize, SMEM);
        cudaFuncSetAttribute(k_agg_gemm<false>, cudaFuncAttributeMaxDynamicSharedMemorySize, SMEM);
        cudaFuncSetAttribute(k_agg_gemm<true>, cudaFuncAttributeMaxDynamicSharedMemorySize, SMEM);
        attr_done = true;
    }

    const int tb = 256;
    const int gb = ceildiv(n, 64);
    const int nb = ceildiv(n, SCAN_B);

    // ---- CSR build + normalization ----
    k_zero<<<ceildiv(n, tb), tb>>>(n);
    k_count_deg<<<ceildiv(e, tb), tb>>>(dst, ew, e);
    k_scan1<<<nb, SCAN_B>>>(n);
    k_scan3_dinv<<<ceildiv(n, tb), tb>>>(n, nb);
    k_fill<<<ceildiv(e, tb), tb>>>(src, dst, ew, e);

    // ---- GCN layer 1: A = x @ W1 ----
    k_gemm_plain<<<gb, tb, SMEM>>>(x, W1, dA, n);
    // ---- GCN layer 2 fused: B = relu(b1 + A_hat A) @ W2 ----
    k_agg_gemm<false><<<gb, tb, SMEM>>>(dA, W2, dB, b1, nullptr, nullptr, n);
    // ---- GAT projection fused: A = relu(b2 + A_hat B) @ Wg  (+ attention dots) ----
    k_agg_gemm<true><<<gb, tb, SMEM>>>(dB, Wg, dA, b2, att_src, att_dst, n);
    // ---- GAT softmax-aggregate + classifier ----
    k_gat_out<<<ceildiv(n, 8), tb>>>(bg, Wc, bc, (float*)d_out, n);
}

// round 8
// speedup vs baseline: 1.2368x; 1.2368x over previous
#include <cuda_runtime.h>

#define HD 128
#define NMAX 100000
#define EMAX 1600000
#define SCAN_B 1024

typedef unsigned long long ull;

// -------- scratch (device globals; no allocations allowed) --------
__device__ float g_deg[NMAX];
__device__ float g_dinv[NMAX];
__device__ float g_A[(size_t)NMAX * HD];   // ping
__device__ float g_B[(size_t)NMAX * HD];   // pong
__device__ float g_as[NMAX];
__device__ float g_ad[NMAX];
__device__ int   g_cnt[NMAX];
__device__ int   g_rowptr[NMAX + 1];
__device__ int   g_cur[NMAX + 1];
__device__ int   g_bsum[128];
__device__ int   g_csr_src[EMAX];
__device__ float g_csr_coef[EMAX];

__device__ __forceinline__ float leaky(float x) { return x > 0.f ? x : 0.2f * x; }

__device__ __forceinline__ ull fma2(ull a, ull b, ull c) {
    ull d;
    asm("fma.rn.f32x2 %0, %1, %2, %3;" : "=l"(d) : "l"(a), "l"(b), "l"(c));
    return d;
}
__device__ __forceinline__ ull pack2(float v) {
    ull d;
    asm("mov.b64 %0, {%1, %1};" : "=l"(d) : "f"(v));
    return d;
}
__device__ __forceinline__ float2 unpack2(ull v) {
    float2 r;
    asm("mov.b64 {%0, %1}, %2;" : "=f"(r.x), "=f"(r.y) : "l"(v));
    return r;
}

// ================= CSR build =================
__global__ void k_zero(int n) {
    int i = blockIdx.x * blockDim.x + threadIdx.x;
    if (i < n) { g_cnt[i] = 0; g_deg[i] = 1.0f; }   // self-loop weight 1
    if (i == 0) { g_rowptr[0] = 0; g_cur[0] = 0; }
}

__global__ void k_count_deg(const int* __restrict__ dst, const float* __restrict__ ew, int e) {
    int i = blockIdx.x * blockDim.x + threadIdx.x;
    if (i >= e) return;
    int d = dst[i];
    atomicAdd(&g_cnt[d], 1);
    atomicAdd(&g_deg[d], ew[i]);
}

__global__ __launch_bounds__(SCAN_B) void k_scan1(int n) {
    __shared__ int s[SCAN_B];
    int t = threadIdx.x;
    int g = blockIdx.x * SCAN_B + t;
    int v = (g < n) ? g_cnt[g] : 0;
    s[t] = v;
    __syncthreads();
    #pragma unroll
    for (int o = 1; o < SCAN_B; o <<= 1) {
        int x = (t >= o) ? s[t - o] : 0;
        __syncthreads();
        s[t] += x;
        __syncthreads();
    }
    if (g < n) g_rowptr[g + 1] = s[t];            // block-local inclusive
    if (t == SCAN_B - 1) g_bsum[blockIdx.x] = s[t];
}

// scan of block sums folded in (each block redundantly scans <=128 sums)
__global__ __launch_bounds__(256) void k_scan3_dinv(int n, int nb) {
    __shared__ int s[128];
    int t = threadIdx.x;
    int v = 0;
    if (t < 128) { v = (t < nb) ? g_bsum[t] : 0; s[t] = v; }
    __syncthreads();
    #pragma unroll
    for (int o = 1; o < 128; o <<= 1) {
        int x = (t >= o && t < 128) ? s[t - o] : 0;
        __syncthreads();
        if (t < 128) s[t] += x;
        __syncthreads();
    }
    if (t < 128) s[t] -= v;                        // exclusive
    __syncthreads();
    int i = blockIdx.x * blockDim.x + t;
    if (i >= n) return;
    int val = g_rowptr[i + 1] + s[i >> 10];
    g_rowptr[i + 1] = val;
    g_cur[i + 1] = val;
    float d = g_deg[i];
    g_dinv[i] = d > 0.f ? rsqrtf(d) : 0.f;
}

__global__ void k_fill(const int* __restrict__ src, const int* __restrict__ dst,
                       const float* __restrict__ ew, int e) {
    int i = blockIdx.x * blockDim.x + threadIdx.x;
    if (i >= e) return;
    int s = src[i], d = dst[i];
    int pos = atomicAdd(&g_cur[d], 1);
    g_csr_src[pos] = s;
    g_csr_coef[pos] = g_dinv[s] * ew[i] * g_dinv[d];
}

// ================= GEMM: Y = (relu?)X @ W  (f32x2 packed FMA, W in smem) =================
template<bool RELU, bool DOTS>
__global__ __launch_bounds__(256) void k_gemm128(const float* __restrict__ X,
                                                 const float* __restrict__ W,
                                                 float* __restrict__ Y,
                                                 const float* __restrict__ asrc,
                                                 const float* __restrict__ adst,
                                                 int n) {
    extern __shared__ float smem[];
    float* xs  = smem;                // 64*128
    float* wsh = smem + 64 * HD;      // 128*128
    const int t = threadIdx.x;
    const int row0 = blockIdx.x * 64;

    #pragma unroll
    for (int i = t; i < 128 * 32; i += 256)
        ((float4*)wsh)[i] = ((const float4*)W)[i];

    #pragma unroll
    for (int i = t; i < 64 * 32; i += 256) {
        int r = i >> 5, c4 = i & 31;
        int gr = row0 + r;
        float4 v = make_float4(0.f, 0.f, 0.f, 0.f);
        if (gr < n) v = *(const float4*)(X + (size_t)gr * HD + c4 * 4);
        if (RELU) {
            v.x = fmaxf(v.x, 0.f); v.y = fmaxf(v.y, 0.f);
            v.z = fmaxf(v.z, 0.f); v.w = fmaxf(v.w, 0.f);
        }
        *(float4*)(xs + r * HD + c4 * 4) = v;
    }
    __syncthreads();

    const int cx = t & 31;
    const int ry = t >> 5;

    ull acc[8][2];
    #pragma unroll
    for (int j = 0; j < 8; j++) { acc[j][0] = 0ull; acc[j][1] = 0ull; }

    #pragma unroll 4
    for (int k0 = 0; k0 < HD; k0 += 4) {
        ulonglong2 w0 = *(const ulonglong2*)(wsh + (k0 + 0) * HD + cx * 4);
        ulonglong2 w1 = *(const ulonglong2*)(wsh + (k0 + 1) * HD + cx * 4);
        ulonglong2 w2 = *(const ulonglong2*)(wsh + (k0 + 2) * HD + cx * 4);
        ulonglong2 w3 = *(const ulonglong2*)(wsh + (k0 + 3) * HD + cx * 4);
        #pragma unroll
        for (int j = 0; j < 8; j++) {
            float4 xv = *(const float4*)(xs + (ry * 8 + j) * HD + k0);
            ull x0 = pack2(xv.x), x1 = pack2(xv.y), x2 = pack2(xv.z), x3 = pack2(xv.w);
            acc[j][0] = fma2(x0, w0.x, acc[j][0]);
            acc[j][1] = fma2(x0, w0.y, acc[j][1]);
            acc[j][0] = fma2(x1, w1.x, acc[j][0]);
            acc[j][1] = fma2(x1, w1.y, acc[j][1]);
            acc[j][0] = fma2(x2, w2.x, acc[j][0]);
            acc[j][1] = fma2(x2, w2.y, acc[j][1]);
            acc[j][0] = fma2(x3, w3.x, acc[j][0]);
            acc[j][1] = fma2(x3, w3.y, acc[j][1]);
        }
    }

    float4 s4, d4;
    if (DOTS) {
        s4 = *(const float4*)(asrc + cx * 4);
        d4 = *(const float4*)(adst + cx * 4);
    }

    #pragma unroll
    for (int j = 0; j < 8; j++) {
        int gr = row0 + ry * 8 + j;
        float2 lo = unpack2(acc[j][0]);
        float2 hi = unpack2(acc[j][1]);
        float4 r = make_float4(lo.x, lo.y, hi.x, hi.y);
        if (gr < n) *(float4*)(Y + (size_t)gr * HD + cx * 4) = r;
        if (DOTS) {
            float ps = r.x * s4.x + r.y * s4.y + r.z * s4.z + r.w * s4.w;
            float pd = r.x * d4.x + r.y * d4.y + r.z * d4.z + r.w * d4.w;
            #pragma unroll
            for (int o = 16; o; o >>= 1) {
                ps += __shfl_xor_sync(0xffffffffu, ps, o);
                pd += __shfl_xor_sync(0xffffffffu, pd, o);
            }
            if (cx == 0 && gr < n) { g_as[gr] = ps; g_ad[gr] = pd; }
        }
    }
}

// ================= GCN aggregation (gather, warp per dst node, high occupancy) =================
__global__ __launch_bounds__(256) void k_gcn_agg(const float* __restrict__ bias, int n) {
    int w = (blockIdx.x * blockDim.x + threadIdx.x) >> 5;
    if (w >= n) return;
    int lane = threadIdx.x & 31;
    int beg = g_rowptr[w], end = g_rowptr[w + 1];

    float di = g_dinv[w];
    float cself = di * di;
    float4 av = *(const float4*)(g_A + (size_t)w * HD + lane * 4);
    float4 b  = *(const float4*)(bias + lane * 4);
    float4 acc;
    acc.x = fmaf(cself, av.x, b.x);
    acc.y = fmaf(cself, av.y, b.y);
    acc.z = fmaf(cself, av.z, b.z);
    acc.w = fmaf(cself, av.w, b.w);

    for (int j0 = beg; j0 < end; j0 += 32) {
        int idx = j0 + lane;
        int s = 0; float c = 0.f;
        if (idx < end) { s = g_csr_src[idx]; c = g_csr_coef[idx]; }
        int m = min(32, end - j0);
        int j = 0;
        for (; j + 1 < m; j += 2) {
            int   s0 = __shfl_sync(0xffffffffu, s, j);
            float c0 = __shfl_sync(0xffffffffu, c, j);
            int   s1 = __shfl_sync(0xffffffffu, s, j + 1);
            float c1 = __shfl_sync(0xffffffffu, c, j + 1);
            float4 v0 = *(const float4*)(g_A + (size_t)s0 * HD + lane * 4);
            float4 v1 = *(const float4*)(g_A + (size_t)s1 * HD + lane * 4);
            acc.x = fmaf(c0, v0.x, acc.x); acc.y = fmaf(c0, v0.y, acc.y);
            acc.z = fmaf(c0, v0.z, acc.z); acc.w = fmaf(c0, v0.w, acc.w);
            acc.x = fmaf(c1, v1.x, acc.x); acc.y = fmaf(c1, v1.y, acc.y);
            acc.z = fmaf(c1, v1.z, acc.z); acc.w = fmaf(c1, v1.w, acc.w);
        }
        if (j < m) {
            int   s0 = __shfl_sync(0xffffffffu, s, j);
            float c0 = __shfl_sync(0xffffffffu, c, j);
            float4 v0 = *(const float4*)(g_A + (size_t)s0 * HD + lane * 4);
            acc.x = fmaf(c0, v0.x, acc.x); acc.y = fmaf(c0, v0.y, acc.y);
            acc.z = fmaf(c0, v0.z, acc.z); acc.w = fmaf(c0, v0.w, acc.w);
        }
    }
    *(float4*)(g_B + (size_t)w * HD + lane * 4) = acc;   // pre-relu; next GEMM applies relu
}

// ====== GAT softmax-aggregate + fused classifier (warp per node) ======
__global__ __launch_bounds__(256) void k_gat_out(const float* __restrict__ bg,
                                                 const float* __restrict__ Wc,
                                                 const float* __restrict__ bc,
                                                 float* __restrict__ out, int n) {
    int w = (blockIdx.x * blockDim.x + threadIdx.x) >> 5;
    if (w >= n) return;
    int lane = threadIdx.x & 31;
    int beg = g_rowptr[w], end = g_rowptr[w + 1];

    float ad_d = g_ad[w];
    float a_self = leaky(g_as[w] + ad_d);

    // pass 1: max over attention logits
    float mx = a_self;
    for (int idx = beg + lane; idx < end; idx += 32) {
        int s = g_csr_src[idx];
        mx = fmaxf(mx, leaky(g_as[s] + ad_d));
    }
    #pragma unroll
    for (int o = 16; o; o >>= 1)
        mx = fmaxf(mx, __shfl_xor_sync(0xffffffffu, mx, o));

    // pass 2: denom + weighted gather
    float wself = expf(a_self - mx);
    float denp = 0.f;
    float4 av = *(const float4*)(g_A + (size_t)w * HD + lane * 4);
    float4 acc;
    acc.x = wself * av.x; acc.y = wself * av.y;
    acc.z = wself * av.z; acc.w = wself * av.w;

    for (int j0 = beg; j0 < end; j0 += 32) {
        int idx = j0 + lane;
        int s = 0; float ww = 0.f;
        if (idx < end) {
            s = g_csr_src[idx];
            ww = expf(leaky(g_as[s] + ad_d) - mx);
            denp += ww;
        }
        int m = min(32, end - j0);
        int j = 0;
        for (; j + 1 < m; j += 2) {
            int   s0 = __shfl_sync(0xffffffffu, s, j);
            float w0 = __shfl_sync(0xffffffffu, ww, j);
            int   s1 = __shfl_sync(0xffffffffu, s, j + 1);
            float w1 = __shfl_sync(0xffffffffu, ww, j + 1);
            float4 v0 = *(const float4*)(g_A + (size_t)s0 * HD + lane * 4);
            float4 v1 = *(const float4*)(g_A + (size_t)s1 * HD + lane * 4);
            acc.x = fmaf(w0, v0.x, acc.x); acc.y = fmaf(w0, v0.y, acc.y);
            acc.z = fmaf(w0, v0.z, acc.z); acc.w = fmaf(w0, v0.w, acc.w);
            acc.x = fmaf(w1, v1.x, acc.x); acc.y = fmaf(w1, v1.y, acc.y);
            acc.z = fmaf(w1, v1.z, acc.z); acc.w = fmaf(w1, v1.w, acc.w);
        }
        if (j < m) {
            int   s0 = __shfl_sync(0xffffffffu, s, j);
            float w0 = __shfl_sync(0xffffffffu, ww, j);
            float4 v0 = *(const float4*)(g_A + (size_t)s0 * HD + lane * 4);
            acc.x = fmaf(w0, v0.x, acc.x); acc.y = fmaf(w0, v0.y, acc.y);
            acc.z = fmaf(w0, v0.z, acc.z); acc.w = fmaf(w0, v0.w, acc.w);
        }
    }
    #pragma unroll
    for (int o = 16; o; o >>= 1)
        denp += __shfl_xor_sync(0xffffffffu, denp, o);
    float inv = 1.0f / (denp + wself);

    // relu(gat + bg), then classifier: out[16] = v @ Wc + bc
    float4 b = *(const float4*)(bg + lane * 4);
    float vv[4];
    vv[0] = fmaxf(fmaf(acc.x, inv, b.x), 0.f);
    vv[1] = fmaxf(fmaf(acc.y, inv, b.y), 0.f);
    vv[2] = fmaxf(fmaf(acc.z, inv, b.z), 0.f);
    vv[3] = fmaxf(fmaf(acc.w, inv, b.w), 0.f);

    float o16[16];
    #pragma unroll
    for (int c = 0; c < 16; c++) o16[c] = 0.f;
    #pragma unroll
    for (int kk = 0; kk < 4; kk++) {
        const float4* wr = (const float4*)(Wc + (size_t)(lane * 4 + kk) * 16);
        float4 w0 = wr[0], w1 = wr[1], w2 = wr[2], w3 = wr[3];
        float f = vv[kk];
        o16[0]  = fmaf(f, w0.x, o16[0]);  o16[1]  = fmaf(f, w0.y, o16[1]);
        o16[2]  = fmaf(f, w0.z, o16[2]);  o16[3]  = fmaf(f, w0.w, o16[3]);
        o16[4]  = fmaf(f, w1.x, o16[4]);  o16[5]  = fmaf(f, w1.y, o16[5]);
        o16[6]  = fmaf(f, w1.z, o16[6]);  o16[7]  = fmaf(f, w1.w, o16[7]);
        o16[8]  = fmaf(f, w2.x, o16[8]);  o16[9]  = fmaf(f, w2.y, o16[9]);
        o16[10] = fmaf(f, w2.z, o16[10]); o16[11] = fmaf(f, w2.w, o16[11]);
        o16[12] = fmaf(f, w3.x, o16[12]); o16[13] = fmaf(f, w3.y, o16[13]);
        o16[14] = fmaf(f, w3.z, o16[14]); o16[15] = fmaf(f, w3.w, o16[15]);
    }
    #pragma unroll
    for (int c = 0; c < 16; c++) {
        #pragma unroll
        for (int o = 16; o; o >>= 1)
            o16[c] += __shfl_xor_sync(0xffffffffu, o16[c], o);
    }
    if (lane == 0) {
        float4 bc0 = ((const float4*)bc)[0];
        float4 bc1 = ((const float4*)bc)[1];
        float4 bc2 = ((const float4*)bc)[2];
        float4 bc3 = ((const float4*)bc)[3];
        float4* op = (float4*)(out + (size_t)w * 16);
        op[0] = make_float4(o16[0] + bc0.x, o16[1] + bc0.y, o16[2] + bc0.z, o16[3] + bc0.w);
        op[1] = make_float4(o16[4] + bc1.x, o16[5] + bc1.y, o16[6] + bc1.z, o16[7] + bc1.w);
        op[2] = make_float4(o16[8] + bc2.x, o16[9] + bc2.y, o16[10] + bc2.z, o16[11] + bc2.w);
        op[3] = make_float4(o16[12] + bc3.x, o16[13] + bc3.y, o16[14] + bc3.z, o16[15] + bc3.w);
    }
}

static inline int ceildiv(int a, int b) { return (a + b - 1) / b; }

extern "C" void kernel_launch(void* const* d_in, const int* in_sizes, int n_in,
                              void* d_out, int out_size) {
    const float* x       = (const float*)d_in[0];
    const int*   ei      = (const int*)d_in[1];
    const float* ew      = (const float*)d_in[2];
    const float* W1      = (const float*)d_in[3];
    const float* b1      = (const float*)d_in[4];
    const float* W2      = (const float*)d_in[5];
    const float* b2      = (const float*)d_in[6];
    const float* Wg      = (const float*)d_in[7];
    const float* att_src = (const float*)d_in[8];
    const float* att_dst = (const float*)d_in[9];
    const float* bg      = (const float*)d_in[10];
    const float* Wc      = (const float*)d_in[11];
    const float* bc      = (const float*)d_in[12];

    int n = in_sizes[0] / HD;
    int e = in_sizes[2];
    const int* src = ei;
    const int* dst = ei + e;

    float *dA = nullptr, *dB = nullptr;
    cudaGetSymbolAddress((void**)&dA, g_A);
    cudaGetSymbolAddress((void**)&dB, g_B);

    const int SMEM = (64 * HD + 128 * HD) * (int)sizeof(float);   // 98304
    cudaFuncSetAttribute(k_gemm128<false, false>, cudaFuncAttributeMaxDynamicSharedMemorySize, SMEM);
    cudaFuncSetAttribute(k_gemm128<true, false>,  cudaFuncAttributeMaxDynamicSharedMemorySize, SMEM);
    cudaFuncSetAttribute(k_gemm128<true, true>,   cudaFuncAttributeMaxDynamicSharedMemorySize, SMEM);

    const int tb = 256;
    const int gb = ceildiv(n, 64);
    const int ga = ceildiv(n, 8);       // warp-per-node: 8 nodes/block, high occupancy
    const int nb = ceildiv(n, SCAN_B);

    // ---- CSR build + normalization ----
    k_zero<<<ceildiv(n, tb), tb>>>(n);
    k_count_deg<<<ceildiv(e, tb), tb>>>(dst, ew, e);
    k_scan1<<<nb, SCAN_B>>>(n);
    k_scan3_dinv<<<ceildiv(n, tb), tb>>>(n, nb);
    k_fill<<<ceildiv(e, tb), tb>>>(src, dst, ew, e);

    // ---- GCN layer 1 ----
    k_gemm128<false, false><<<gb, tb, SMEM>>>(x, W1, dA, nullptr, nullptr, n);
    k_gcn_agg<<<ga, tb>>>(b1, n);
    // ---- GCN layer 2 (relu fused into GEMM load) ----
    k_gemm128<true, false><<<gb, tb, SMEM>>>(dB, W2, dA, nullptr, nullptr, n);
    k_gcn_agg<<<ga, tb>>>(b2, n);
    // ---- GAT projection (+ attention dots in epilogue) ----
    k_gemm128<true, true><<<gb, tb, SMEM>>>(dB, Wg, dA, att_src, att_dst, n);
    // ---- GAT softmax-aggregate + classifier ----
    k_gat_out<<<ga, tb>>>(bg, Wc, bc, (float*)d_out, n);
}

// round 9
// speedup vs baseline: 1.2774x; 1.0328x over previous
#include <cuda_runtime.h>
#include <cuda_fp16.h>

#define HD 128
#define NMAX 100000
#define EMAX 1600000
#define SCAN_B 1024

// -------- scratch (device globals; no allocations allowed) --------
__device__ float  g_deg[NMAX];
__device__ float  g_dinv[NMAX];
__device__ __half g_Ah[(size_t)NMAX * HD];   // fp16 gather source (GEMM outputs)
__device__ float  g_B[(size_t)NMAX * HD];    // fp32 aggregation output (GEMM input)
__device__ float  g_as[NMAX];
__device__ float  g_ad[NMAX];
__device__ int    g_cnt[NMAX];
__device__ int    g_rowptr[NMAX + 1];
__device__ int    g_cur[NMAX + 1];
__device__ int    g_bsum[128];
__device__ int    g_csr_src[EMAX];
__device__ float  g_csr_coef[EMAX];

__device__ __forceinline__ float leaky(float x) { return x > 0.f ? x : 0.2f * x; }

// load 4 consecutive fp16 elements (lane-owned quad) of a row as float4
__device__ __forceinline__ float4 ldrow4h(const __half* __restrict__ base, int node, int lane) {
    uint2 u = *(const uint2*)(base + (size_t)node * HD + lane * 4);
    __half2 h0 = *(__half2*)&u.x;
    __half2 h1 = *(__half2*)&u.y;
    float2 f0 = __half22float2(h0);
    float2 f1 = __half22float2(h1);
    return make_float4(f0.x, f0.y, f1.x, f1.y);
}

// ================= CSR build =================
__global__ void k_zero(int n) {
    int i = blockIdx.x * blockDim.x + threadIdx.x;
    if (i < n) { g_cnt[i] = 0; g_deg[i] = 1.0f; }   // self-loop weight 1
    if (i == 0) { g_rowptr[0] = 0; g_cur[0] = 0; }
}

__global__ void k_count_deg(const int* __restrict__ dst, const float* __restrict__ ew, int e) {
    int i = blockIdx.x * blockDim.x + threadIdx.x;
    if (i >= e) return;
    int d = dst[i];
    atomicAdd(&g_cnt[d], 1);
    atomicAdd(&g_deg[d], ew[i]);
}

__global__ __launch_bounds__(SCAN_B) void k_scan1(int n) {
    __shared__ int s[SCAN_B];
    int t = threadIdx.x;
    int g = blockIdx.x * SCAN_B + t;
    int v = (g < n) ? g_cnt[g] : 0;
    s[t] = v;
    __syncthreads();
    #pragma unroll
    for (int o = 1; o < SCAN_B; o <<= 1) {
        int x = (t >= o) ? s[t - o] : 0;
        __syncthreads();
        s[t] += x;
        __syncthreads();
    }
    if (g < n) g_rowptr[g + 1] = s[t];            // block-local inclusive
    if (t == SCAN_B - 1) g_bsum[blockIdx.x] = s[t];
}

// scan of block sums folded in (each block redundantly scans <=128 sums)
__global__ __launch_bounds__(256) void k_scan3_dinv(int n, int nb) {
    __shared__ int s[128];
    int t = threadIdx.x;
    int v = 0;
    if (t < 128) { v = (t < nb) ? g_bsum[t] : 0; s[t] = v; }
    __syncthreads();
    #pragma unroll
    for (int o = 1; o < 128; o <<= 1) {
        int x = (t >= o && t < 128) ? s[t - o] : 0;
        __syncthreads();
        if (t < 128) s[t] += x;
        __syncthreads();
    }
    if (t < 128) s[t] -= v;                        // exclusive
    __syncthreads();
    int i = blockIdx.x * blockDim.x + t;
    if (i >= n) return;
    int val = g_rowptr[i + 1] + s[i >> 10];
    g_rowptr[i + 1] = val;
    g_cur[i + 1] = val;
    float d = g_deg[i];
    g_dinv[i] = d > 0.f ? rsqrtf(d) : 0.f;
}

__global__ void k_fill(const int* __restrict__ src, const int* __restrict__ dst,
                       const float* __restrict__ ew, int e) {
    int i = blockIdx.x * blockDim.x + threadIdx.x;
    if (i >= e) return;
    int s = src[i], d = dst[i];
    int pos = atomicAdd(&g_cur[d], 1);
    g_csr_src[pos] = s;
    g_csr_coef[pos] = g_dinv[s] * ew[i] * g_dinv[d];
}

// ====== GEMM (round-5 body): Yh = (relu?)X @ W, fp16 output, optional dots ======
template<bool RELU, bool DOTS>
__global__ __launch_bounds__(256) void k_gemm128(const float* __restrict__ X,
                                                 const float* __restrict__ W,
                                                 __half* __restrict__ Y,
                                                 const float* __restrict__ asrc,
                                                 const float* __restrict__ adst,
                                                 int n) {
    __shared__ float xs[64][132];
    const int t = threadIdx.x;
    const int row0 = blockIdx.x * 64;

    #pragma unroll
    for (int i = t; i < 64 * 32; i += 256) {
        int r = i >> 5, c4 = i & 31;
        int gr = row0 + r;
        float4 v = make_float4(0.f, 0.f, 0.f, 0.f);
        if (gr < n) v = *(const float4*)(X + (size_t)gr * HD + c4 * 4);
        if (RELU) {
            v.x = fmaxf(v.x, 0.f); v.y = fmaxf(v.y, 0.f);
            v.z = fmaxf(v.z, 0.f); v.w = fmaxf(v.w, 0.f);
        }
        *(float4*)&xs[r][c4 * 4] = v;
    }
    __syncthreads();

    const int cx = t & 31;
    const int ry = t >> 5;

    float4 acc[8];
    #pragma unroll
    for (int j = 0; j < 8; j++) acc[j] = make_float4(0.f, 0.f, 0.f, 0.f);

    #pragma unroll 4
    for (int k0 = 0; k0 < HD; k0 += 4) {
        float4 w0 = *(const float4*)(W + (size_t)(k0 + 0) * HD + cx * 4);
        float4 w1 = *(const float4*)(W + (size_t)(k0 + 1) * HD + cx * 4);
        float4 w2 = *(const float4*)(W + (size_t)(k0 + 2) * HD + cx * 4);
        float4 w3 = *(const float4*)(W + (size_t)(k0 + 3) * HD + cx * 4);
        #pragma unroll
        for (int j = 0; j < 8; j++) {
            float4 xv = *(const float4*)&xs[ry * 8 + j][k0];
            acc[j].x = fmaf(xv.x, w0.x, acc[j].x);
            acc[j].y = fmaf(xv.x, w0.y, acc[j].y);
            acc[j].z = fmaf(xv.x, w0.z, acc[j].z);
            acc[j].w = fmaf(xv.x, w0.w, acc[j].w);
            acc[j].x = fmaf(xv.y, w1.x, acc[j].x);
            acc[j].y = fmaf(xv.y, w1.y, acc[j].y);
            acc[j].z = fmaf(xv.y, w1.z, acc[j].z);
            acc[j].w = fmaf(xv.y, w1.w, acc[j].w);
            acc[j].x = fmaf(xv.z, w2.x, acc[j].x);
            acc[j].y = fmaf(xv.z, w2.y, acc[j].y);
            acc[j].z = fmaf(xv.z, w2.z, acc[j].z);
            acc[j].w = fmaf(xv.z, w2.w, acc[j].w);
            acc[j].x = fmaf(xv.w, w3.x, acc[j].x);
            acc[j].y = fmaf(xv.w, w3.y, acc[j].y);
            acc[j].z = fmaf(xv.w, w3.z, acc[j].z);
            acc[j].w = fmaf(xv.w, w3.w, acc[j].w);
        }
    }

    float4 s4, d4;
    if (DOTS) {
        s4 = *(const float4*)(asrc + cx * 4);
        d4 = *(const float4*)(adst + cx * 4);
    }

    #pragma unroll
    for (int j = 0; j < 8; j++) {
        int gr = row0 + ry * 8 + j;
        if (gr < n) {
            __half2 h0 = __floats2half2_rn(acc[j].x, acc[j].y);
            __half2 h1 = __floats2half2_rn(acc[j].z, acc[j].w);
            uint2 u;
            u.x = *(unsigned*)&h0;
            u.y = *(unsigned*)&h1;
            *(uint2*)(Y + (size_t)gr * HD + cx * 4) = u;
        }
        if (DOTS) {
            float ps = acc[j].x * s4.x + acc[j].y * s4.y + acc[j].z * s4.z + acc[j].w * s4.w;
            float pd = acc[j].x * d4.x + acc[j].y * d4.y + acc[j].z * d4.z + acc[j].w * d4.w;
            #pragma unroll
            for (int o = 16; o; o >>= 1) {
                ps += __shfl_xor_sync(0xffffffffu, ps, o);
                pd += __shfl_xor_sync(0xffffffffu, pd, o);
            }
            if (cx == 0 && gr < n) { g_as[gr] = ps; g_ad[gr] = pd; }
        }
    }
}

// ====== GCN aggregation (fp16 gather, warp per dst node, high occupancy) ======
__global__ __launch_bounds__(256) void k_gcn_agg(const float* __restrict__ bias, int n) {
    int w = (blockIdx.x * blockDim.x + threadIdx.x) >> 5;
    if (w >= n) return;
    int lane = threadIdx.x & 31;
    int beg = g_rowptr[w], end = g_rowptr[w + 1];

    float di = g_dinv[w];
    float cself = di * di;
    float4 av = ldrow4h(g_Ah, w, lane);
    float4 b  = *(const float4*)(bias + lane * 4);
    float4 acc;
    acc.x = fmaf(cself, av.x, b.x);
    acc.y = fmaf(cself, av.y, b.y);
    acc.z = fmaf(cself, av.z, b.z);
    acc.w = fmaf(cself, av.w, b.w);

    for (int j0 = beg; j0 < end; j0 += 32) {
        int idx = j0 + lane;
        int s = 0; float c = 0.f;
        if (idx < end) { s = g_csr_src[idx]; c = g_csr_coef[idx]; }
        int m = min(32, end - j0);
        int j = 0;
        for (; j + 1 < m; j += 2) {
            int   s0 = __shfl_sync(0xffffffffu, s, j);
            float c0 = __shfl_sync(0xffffffffu, c, j);
            int   s1 = __shfl_sync(0xffffffffu, s, j + 1);
            float c1 = __shfl_sync(0xffffffffu, c, j + 1);
            float4 v0 = ldrow4h(g_Ah, s0, lane);
            float4 v1 = ldrow4h(g_Ah, s1, lane);
            acc.x = fmaf(c0, v0.x, acc.x); acc.y = fmaf(c0, v0.y, acc.y);
            acc.z = fmaf(c0, v0.z, acc.z); acc.w = fmaf(c0, v0.w, acc.w);
            acc.x = fmaf(c1, v1.x, acc.x); acc.y = fmaf(c1, v1.y, acc.y);
            acc.z = fmaf(c1, v1.z, acc.z); acc.w = fmaf(c1, v1.w, acc.w);
        }
        if (j < m) {
            int   s0 = __shfl_sync(0xffffffffu, s, j);
            float c0 = __shfl_sync(0xffffffffu, c, j);
            float4 v0 = ldrow4h(g_Ah, s0, lane);
            acc.x = fmaf(c0, v0.x, acc.x); acc.y = fmaf(c0, v0.y, acc.y);
            acc.z = fmaf(c0, v0.z, acc.z); acc.w = fmaf(c0, v0.w, acc.w);
        }
    }
    // pre-relu; the next GEMM applies relu on load
    *(float4*)(g_B + (size_t)w * HD + lane * 4) = acc;
}

// ====== GAT softmax-aggregate + fused classifier (warp per node, fp16 gather) ======
__global__ __launch_bounds__(256) void k_gat_out(const float* __restrict__ bg,
                                                 const float* __restrict__ Wc,
                                                 const float* __restrict__ bc,
                                                 float* __restrict__ out, int n) {
    int w = (blockIdx.x * blockDim.x + threadIdx.x) >> 5;
    if (w >= n) return;
    int lane = threadIdx.x & 31;
    int beg = g_rowptr[w], end = g_rowptr[w + 1];

    float ad_d = g_ad[w];
    float a_self = leaky(g_as[w] + ad_d);

    // pass 1: max over attention logits
    float mx = a_self;
    for (int idx = beg + lane; idx < end; idx += 32) {
        int s = g_csr_src[idx];
        mx = fmaxf(mx, leaky(g_as[s] + ad_d));
    }
    #pragma unroll
    for (int o = 16; o; o >>= 1)
        mx = fmaxf(mx, __shfl_xor_sync(0xffffffffu, mx, o));

    // pass 2: denom + weighted gather
    float wself = expf(a_self - mx);
    float denp = 0.f;
    float4 av = ldrow4h(g_Ah, w, lane);
    float4 acc;
    acc.x = wself * av.x; acc.y = wself * av.y;
    acc.z = wself * av.z; acc.w = wself * av.w;

    for (int j0 = beg; j0 < end; j0 += 32) {
        int idx = j0 + lane;
        int s = 0; float ww = 0.f;
        if (idx < end) {
            s = g_csr_src[idx];
            ww = expf(leaky(g_as[s] + ad_d) - mx);
            denp += ww;
        }
        int m = min(32, end - j0);
        int j = 0;
        for (; j + 1 < m; j += 2) {
            int   s0 = __shfl_sync(0xffffffffu, s, j);
            float w0 = __shfl_sync(0xffffffffu, ww, j);
            int   s1 = __shfl_sync(0xffffffffu, s, j + 1);
            float w1 = __shfl_sync(0xffffffffu, ww, j + 1);
            float4 v0 = ldrow4h(g_Ah, s0, lane);
            float4 v1 = ldrow4h(g_Ah, s1, lane);
            acc.x = fmaf(w0, v0.x, acc.x); acc.y = fmaf(w0, v0.y, acc.y);
            acc.z = fmaf(w0, v0.z, acc.z); acc.w = fmaf(w0, v0.w, acc.w);
            acc.x = fmaf(w1, v1.x, acc.x); acc.y = fmaf(w1, v1.y, acc.y);
            acc.z = fmaf(w1, v1.z, acc.z); acc.w = fmaf(w1, v1.w, acc.w);
        }
        if (j < m) {
            int   s0 = __shfl_sync(0xffffffffu, s, j);
            float w0 = __shfl_sync(0xffffffffu, ww, j);
            float4 v0 = ldrow4h(g_Ah, s0, lane);
            acc.x = fmaf(w0, v0.x, acc.x); acc.y = fmaf(w0, v0.y, acc.y);
            acc.z = fmaf(w0, v0.z, acc.z); acc.w = fmaf(w0, v0.w, acc.w);
        }
    }
    #pragma unroll
    for (int o = 16; o; o >>= 1)
        denp += __shfl_xor_sync(0xffffffffu, denp, o);
    float inv = 1.0f / (denp + wself);

    // relu(gat + bg), then classifier: out[16] = v @ Wc + bc
    float4 b = *(const float4*)(bg + lane * 4);
    float vv[4];
    vv[0] = fmaxf(fmaf(acc.x, inv, b.x), 0.f);
    vv[1] = fmaxf(fmaf(acc.y, inv, b.y), 0.f);
    vv[2] = fmaxf(fmaf(acc.z, inv, b.z), 0.f);
    vv[3] = fmaxf(fmaf(acc.w, inv, b.w), 0.f);

    float o16[16];
    #pragma unroll
    for (int c = 0; c < 16; c++) o16[c] = 0.f;
    #pragma unroll
    for (int kk = 0; kk < 4; kk++) {
        const float4* wr = (const float4*)(Wc + (size_t)(lane * 4 + kk) * 16);
        float4 w0 = wr[0], w1 = wr[1], w2 = wr[2], w3 = wr[3];
        float f = vv[kk];
        o16[0]  = fmaf(f, w0.x, o16[0]);  o16[1]  = fmaf(f, w0.y, o16[1]);
        o16[2]  = fmaf(f, w0.z, o16[2]);  o16[3]  = fmaf(f, w0.w, o16[3]);
        o16[4]  = fmaf(f, w1.x, o16[4]);  o16[5]  = fmaf(f, w1.y, o16[5]);
        o16[6]  = fmaf(f, w1.z, o16[6]);  o16[7]  = fmaf(f, w1.w, o16[7]);
        o16[8]  = fmaf(f, w2.x, o16[8]);  o16[9]  = fmaf(f, w2.y, o16[9]);
        o16[10] = fmaf(f, w2.z, o16[10]); o16[11] = fmaf(f, w2.w, o16[11]);
        o16[12] = fmaf(f, w3.x, o16[12]); o16[13] = fmaf(f, w3.y, o16[13]);
        o16[14] = fmaf(f, w3.z, o16[14]); o16[15] = fmaf(f, w3.w, o16[15]);
    }
    #pragma unroll
    for (int c = 0; c < 16; c++) {
        #pragma unroll
        for (int o = 16; o; o >>= 1)
            o16[c] += __shfl_xor_sync(0xffffffffu, o16[c], o);
    }
    if (lane == 0) {
        float4 bc0 = ((const float4*)bc)[0];
        float4 bc1 = ((const float4*)bc)[1];
        float4 bc2 = ((const float4*)bc)[2];
        float4 bc3 = ((const float4*)bc)[3];
        float4* op = (float4*)(out + (size_t)w * 16);
        op[0] = make_float4(o16[0] + bc0.x, o16[1] + bc0.y, o16[2] + bc0.z, o16[3] + bc0.w);
        op[1] = make_float4(o16[4] + bc1.x, o16[5] + bc1.y, o16[6] + bc1.z, o16[7] + bc1.w);
        op[2] = make_float4(o16[8] + bc2.x, o16[9] + bc2.y, o16[10] + bc2.z, o16[11] + bc2.w);
        op[3] = make_float4(o16[12] + bc3.x, o16[13] + bc3.y, o16[14] + bc3.z, o16[15] + bc3.w);
    }
}

static inline int ceildiv(int a, int b) { return (a + b - 1) / b; }

extern "C" void kernel_launch(void* const* d_in, const int* in_sizes, int n_in,
                              void* d_out, int out_size) {
    const float* x       = (const float*)d_in[0];
    const int*   ei      = (const int*)d_in[1];
    const float* ew      = (const float*)d_in[2];
    const float* W1      = (const float*)d_in[3];
    const float* b1      = (const float*)d_in[4];
    const float* W2      = (const float*)d_in[5];
    const float* b2      = (const float*)d_in[6];
    const float* Wg      = (const float*)d_in[7];
    const float* att_src = (const float*)d_in[8];
    const float* att_dst = (const float*)d_in[9];
    const float* bg      = (const float*)d_in[10];
    const float* Wc      = (const float*)d_in[11];
    const float* bc      = (const float*)d_in[12];

    int n = in_sizes[0] / HD;
    int e = in_sizes[2];
    const int* src = ei;
    const int* dst = ei + e;

    __half* dAh = nullptr;
    float*  dB  = nullptr;
    cudaGetSymbolAddress((void**)&dAh, g_Ah);
    cudaGetSymbolAddress((void**)&dB,  g_B);

    const int tb = 256;
    const int gb = ceildiv(n, 64);
    const int ga = ceildiv(n, 8);       // warp-per-node: 8 nodes/block, high occupancy
    const int nb = ceildiv(n, SCAN_B);

    // ---- CSR build + normalization ----
    k_zero<<<ceildiv(n, tb), tb>>>(n);
    k_count_deg<<<ceildiv(e, tb), tb>>>(dst, ew, e);
    k_scan1<<<nb, SCAN_B>>>(n);
    k_scan3_dinv<<<ceildiv(n, tb), tb>>>(n, nb);
    k_fill<<<ceildiv(e, tb), tb>>>(src, dst, ew, e);

    // ---- GCN layer 1 ----
    k_gemm128<false, false><<<gb, tb>>>(x, W1, dAh, nullptr, nullptr, n);
    k_gcn_agg<<<ga, tb>>>(b1, n);
    // ---- GCN layer 2 (relu fused into GEMM load) ----
    k_gemm128<true, false><<<gb, tb>>>(dB, W2, dAh, nullptr, nullptr, n);
    k_gcn_agg<<<ga, tb>>>(b2, n);
    // ---- GAT projection (+ attention dots in epilogue) ----
    k_gemm128<true, true><<<gb, tb>>>(dB, Wg, dAh, att_src, att_dst, n);
    // ---- GAT softmax-aggregate + classifier ----
    k_gat_out<<<ga, tb>>>(bg, Wc, bc, (float*)d_out, n);
}

// round 10
// speedup vs baseline: 1.6579x; 1.2979x over previous
#include <cuda_runtime.h>
#include <cuda_fp16.h>

#define HD 128
#define NMAX 100000
#define EMAX 1600000
#define SCAN_B 1024

// -------- scratch (device globals; no allocations allowed) --------
__device__ float  g_deg[NMAX];
__device__ float  g_dinv[NMAX];
__device__ __half g_Ah[(size_t)NMAX * HD];   // fp16 gather source (GEMM outputs)
__device__ float  g_B[(size_t)NMAX * HD];    // fp32 aggregation output (GEMM input)
__device__ float  g_as[NMAX];
__device__ float  g_ad[NMAX];
__device__ int    g_cnt[NMAX];
__device__ int    g_rowptr[NMAX + 1];
__device__ int    g_cur[NMAX + 1];
__device__ int    g_bsum[128];
__device__ int    g_csr_src[EMAX];
__device__ float  g_csr_coef[EMAX];

__device__ __forceinline__ float leaky(float x) { return x > 0.f ? x : 0.2f * x; }

// load 4 consecutive fp16 elements (lane-owned quad) of a row as float4
__device__ __forceinline__ float4 ldrow4h(const __half* __restrict__ base, int node, int lane) {
    uint2 u = *(const uint2*)(base + (size_t)node * HD + lane * 4);
    __half2 h0 = *(__half2*)&u.x;
    __half2 h1 = *(__half2*)&u.y;
    float2 f0 = __half22float2(h0);
    float2 f1 = __half22float2(h1);
    return make_float4(f0.x, f0.y, f1.x, f1.y);
}

// ================= CSR build =================
__global__ void k_zero(int n) {
    int i = blockIdx.x * blockDim.x + threadIdx.x;
    if (i < n) { g_cnt[i] = 0; g_deg[i] = 1.0f; }   // self-loop weight 1
    if (i == 0) { g_rowptr[0] = 0; g_cur[0] = 0; }
}

__global__ void k_count_deg(const int* __restrict__ dst, const float* __restrict__ ew, int e) {
    int i = blockIdx.x * blockDim.x + threadIdx.x;
    if (i >= e) return;
    int d = dst[i];
    atomicAdd(&g_cnt[d], 1);
    atomicAdd(&g_deg[d], ew[i]);
}

__global__ __launch_bounds__(SCAN_B) void k_scan1(int n) {
    __shared__ int s[SCAN_B];
    int t = threadIdx.x;
    int g = blockIdx.x * SCAN_B + t;
    int v = (g < n) ? g_cnt[g] : 0;
    s[t] = v;
    __syncthreads();
    #pragma unroll
    for (int o = 1; o < SCAN_B; o <<= 1) {
        int x = (t >= o) ? s[t - o] : 0;
        __syncthreads();
        s[t] += x;
        __syncthreads();
    }
    if (g < n) g_rowptr[g + 1] = s[t];            // block-local inclusive
    if (t == SCAN_B - 1) g_bsum[blockIdx.x] = s[t];
}

// scan of block sums folded in (each block redundantly scans <=128 sums)
__global__ __launch_bounds__(256) void k_scan3_dinv(int n, int nb) {
    __shared__ int s[128];
    int t = threadIdx.x;
    int v = 0;
    if (t < 128) { v = (t < nb) ? g_bsum[t] : 0; s[t] = v; }
    __syncthreads();
    #pragma unroll
    for (int o = 1; o < 128; o <<= 1) {
        int x = (t >= o && t < 128) ? s[t - o] : 0;
        __syncthreads();
        if (t < 128) s[t] += x;
        __syncthreads();
    }
    if (t < 128) s[t] -= v;                        // exclusive
    __syncthreads();
    int i = blockIdx.x * blockDim.x + t;
    if (i >= n) return;
    int val = g_rowptr[i + 1] + s[i >> 10];
    g_rowptr[i + 1] = val;
    g_cur[i + 1] = val;
    float d = g_deg[i];
    g_dinv[i] = d > 0.f ? rsqrtf(d) : 0.f;
}

__global__ void k_fill(const int* __restrict__ src, const int* __restrict__ dst,
                       const float* __restrict__ ew, int e) {
    int i = blockIdx.x * blockDim.x + threadIdx.x;
    if (i >= e) return;
    int s = src[i], d = dst[i];
    int pos = atomicAdd(&g_cur[d], 1);
    g_csr_src[pos] = s;
    g_csr_coef[pos] = g_dinv[s] * ew[i] * g_dinv[d];
}

// ====== GEMM (round-5 body): Yh = (relu?)X @ W, fp16 output ======
template<bool RELU>
__global__ __launch_bounds__(256) void k_gemm128(const float* __restrict__ X,
                                                 const float* __restrict__ W,
                                                 __half* __restrict__ Y, int n) {
    __shared__ float xs[64][132];
    const int t = threadIdx.x;
    const int row0 = blockIdx.x * 64;

    #pragma unroll
    for (int i = t; i < 64 * 32; i += 256) {
        int r = i >> 5, c4 = i & 31;
        int gr = row0 + r;
        float4 v = make_float4(0.f, 0.f, 0.f, 0.f);
        if (gr < n) v = *(const float4*)(X + (size_t)gr * HD + c4 * 4);
        if (RELU) {
            v.x = fmaxf(v.x, 0.f); v.y = fmaxf(v.y, 0.f);
            v.z = fmaxf(v.z, 0.f); v.w = fmaxf(v.w, 0.f);
        }
        *(float4*)&xs[r][c4 * 4] = v;
    }
    __syncthreads();

    const int cx = t & 31;
    const int ry = t >> 5;

    float4 acc[8];
    #pragma unroll
    for (int j = 0; j < 8; j++) acc[j] = make_float4(0.f, 0.f, 0.f, 0.f);

    #pragma unroll 4
    for (int k0 = 0; k0 < HD; k0 += 4) {
        float4 w0 = *(const float4*)(W + (size_t)(k0 + 0) * HD + cx * 4);
        float4 w1 = *(const float4*)(W + (size_t)(k0 + 1) * HD + cx * 4);
        float4 w2 = *(const float4*)(W + (size_t)(k0 + 2) * HD + cx * 4);
        float4 w3 = *(const float4*)(W + (size_t)(k0 + 3) * HD + cx * 4);
        #pragma unroll
        for (int j = 0; j < 8; j++) {
            float4 xv = *(const float4*)&xs[ry * 8 + j][k0];
            acc[j].x = fmaf(xv.x, w0.x, acc[j].x);
            acc[j].y = fmaf(xv.x, w0.y, acc[j].y);
            acc[j].z = fmaf(xv.x, w0.z, acc[j].z);
            acc[j].w = fmaf(xv.x, w0.w, acc[j].w);
            acc[j].x = fmaf(xv.y, w1.x, acc[j].x);
            acc[j].y = fmaf(xv.y, w1.y, acc[j].y);
            acc[j].z = fmaf(xv.y, w1.z, acc[j].z);
            acc[j].w = fmaf(xv.y, w1.w, acc[j].w);
            acc[j].x = fmaf(xv.z, w2.x, acc[j].x);
            acc[j].y = fmaf(xv.z, w2.y, acc[j].y);
            acc[j].z = fmaf(xv.z, w2.z, acc[j].z);
            acc[j].w = fmaf(xv.z, w2.w, acc[j].w);
            acc[j].x = fmaf(xv.w, w3.x, acc[j].x);
            acc[j].y = fmaf(xv.w, w3.y, acc[j].y);
            acc[j].z = fmaf(xv.w, w3.z, acc[j].z);
            acc[j].w = fmaf(xv.w, w3.w, acc[j].w);
        }
    }

    #pragma unroll
    for (int j = 0; j < 8; j++) {
        int gr = row0 + ry * 8 + j;
        if (gr < n) {
            __half2 h0 = __floats2half2_rn(acc[j].x, acc[j].y);
            __half2 h1 = __floats2half2_rn(acc[j].z, acc[j].w);
            uint2 u;
            u.x = *(unsigned*)&h0;
            u.y = *(unsigned*)&h1;
            *(uint2*)(Y + (size_t)gr * HD + cx * 4) = u;
        }
    }
}

// ====== GCN aggregation (fp16 gather, warp per dst node, high occupancy) ======
__global__ __launch_bounds__(256) void k_gcn_agg(const float* __restrict__ bias, int n) {
    int w = (blockIdx.x * blockDim.x + threadIdx.x) >> 5;
    if (w >= n) return;
    int lane = threadIdx.x & 31;
    int beg = g_rowptr[w], end = g_rowptr[w + 1];

    float di = g_dinv[w];
    float cself = di * di;
    float4 av = ldrow4h(g_Ah, w, lane);
    float4 b  = *(const float4*)(bias + lane * 4);
    float4 acc;
    acc.x = fmaf(cself, av.x, b.x);
    acc.y = fmaf(cself, av.y, b.y);
    acc.z = fmaf(cself, av.z, b.z);
    acc.w = fmaf(cself, av.w, b.w);

    for (int j0 = beg; j0 < end; j0 += 32) {
        int idx = j0 + lane;
        int s = 0; float c = 0.f;
        if (idx < end) { s = g_csr_src[idx]; c = g_csr_coef[idx]; }
        int m = min(32, end - j0);
        int j = 0;
        for (; j + 1 < m; j += 2) {
            int   s0 = __shfl_sync(0xffffffffu, s, j);
            float c0 = __shfl_sync(0xffffffffu, c, j);
            int   s1 = __shfl_sync(0xffffffffu, s, j + 1);
            float c1 = __shfl_sync(0xffffffffu, c, j + 1);
            float4 v0 = ldrow4h(g_Ah, s0, lane);
            float4 v1 = ldrow4h(g_Ah, s1, lane);
            acc.x = fmaf(c0, v0.x, acc.x); acc.y = fmaf(c0, v0.y, acc.y);
            acc.z = fmaf(c0, v0.z, acc.z); acc.w = fmaf(c0, v0.w, acc.w);
            acc.x = fmaf(c1, v1.x, acc.x); acc.y = fmaf(c1, v1.y, acc.y);
            acc.z = fmaf(c1, v1.z, acc.z); acc.w = fmaf(c1, v1.w, acc.w);
        }
        if (j < m) {
            int   s0 = __shfl_sync(0xffffffffu, s, j);
            float c0 = __shfl_sync(0xffffffffu, c, j);
            float4 v0 = ldrow4h(g_Ah, s0, lane);
            acc.x = fmaf(c0, v0.x, acc.x); acc.y = fmaf(c0, v0.y, acc.y);
            acc.z = fmaf(c0, v0.z, acc.z); acc.w = fmaf(c0, v0.w, acc.w);
        }
    }
    // pre-relu; the next GEMM applies relu on load
    *(float4*)(g_B + (size_t)w * HD + lane * 4) = acc;
}

// ====== attention dots (warp per node, fp16 source) ======
__global__ __launch_bounds__(256) void k_dots(const float* __restrict__ asrc,
                                              const float* __restrict__ adst, int n) {
    int gw = (blockIdx.x * blockDim.x + threadIdx.x) >> 5;
    if (gw >= n) return;
    int lane = threadIdx.x & 31;
    float4 gv = ldrow4h(g_Ah, gw, lane);
    float4 s = *(const float4*)(asrc + lane * 4);
    float4 d = *(const float4*)(adst + lane * 4);
    float vs = gv.x * s.x + gv.y * s.y + gv.z * s.z + gv.w * s.w;
    float vd = gv.x * d.x + gv.y * d.y + gv.z * d.z + gv.w * d.w;
    #pragma unroll
    for (int o = 16; o; o >>= 1) {
        vs += __shfl_xor_sync(0xffffffffu, vs, o);
        vd += __shfl_xor_sync(0xffffffffu, vd, o);
    }
    if (lane == 0) { g_as[gw] = vs; g_ad[gw] = vd; }
}

// ====== GAT: fused softmax + aggregation (warp per dst node, fp16 gather) ======
__global__ __launch_bounds__(256) void k_gat_agg(const float* __restrict__ bg, int n) {
    int w = (blockIdx.x * blockDim.x + threadIdx.x) >> 5;
    if (w >= n) return;
    int lane = threadIdx.x & 31;
    int beg = g_rowptr[w], end = g_rowptr[w + 1];

    float ad_d = g_ad[w];
    float a_self = leaky(g_as[w] + ad_d);

    // pass 1: max over attention logits
    float mx = a_self;
    for (int idx = beg + lane; idx < end; idx += 32) {
        int s = g_csr_src[idx];
        mx = fmaxf(mx, leaky(g_as[s] + ad_d));
    }
    #pragma unroll
    for (int o = 16; o; o >>= 1)
        mx = fmaxf(mx, __shfl_xor_sync(0xffffffffu, mx, o));

    // pass 2: denom + weighted gather
    float wself = expf(a_self - mx);
    float denp = 0.f;
    float4 av = ldrow4h(g_Ah, w, lane);
    float4 acc;
    acc.x = wself * av.x; acc.y = wself * av.y;
    acc.z = wself * av.z; acc.w = wself * av.w;

    for (int j0 = beg; j0 < end; j0 += 32) {
        int idx = j0 + lane;
        int s = 0; float ww = 0.f;
        if (idx < end) {
            s = g_csr_src[idx];
            ww = expf(leaky(g_as[s] + ad_d) - mx);
            denp += ww;
        }
        int m = min(32, end - j0);
        int j = 0;
        for (; j + 1 < m; j += 2) {
            int   s0 = __shfl_sync(0xffffffffu, s, j);
            float w0 = __shfl_sync(0xffffffffu, ww, j);
            int   s1 = __shfl_sync(0xffffffffu, s, j + 1);
            float w1 = __shfl_sync(0xffffffffu, ww, j + 1);
            float4 v0 = ldrow4h(g_Ah, s0, lane);
            float4 v1 = ldrow4h(g_Ah, s1, lane);
            acc.x = fmaf(w0, v0.x, acc.x); acc.y = fmaf(w0, v0.y, acc.y);
            acc.z = fmaf(w0, v0.z, acc.z); acc.w = fmaf(w0, v0.w, acc.w);
            acc.x = fmaf(w1, v1.x, acc.x); acc.y = fmaf(w1, v1.y, acc.y);
            acc.z = fmaf(w1, v1.z, acc.z); acc.w = fmaf(w1, v1.w, acc.w);
        }
        if (j < m) {
            int   s0 = __shfl_sync(0xffffffffu, s, j);
            float w0 = __shfl_sync(0xffffffffu, ww, j);
            float4 v0 = ldrow4h(g_Ah, s0, lane);
            acc.x = fmaf(w0, v0.x, acc.x); acc.y = fmaf(w0, v0.y, acc.y);
            acc.z = fmaf(w0, v0.z, acc.z); acc.w = fmaf(w0, v0.w, acc.w);
        }
    }
    #pragma unroll
    for (int o = 16; o; o >>= 1)
        denp += __shfl_xor_sync(0xffffffffu, denp, o);
    float inv = 1.0f / (denp + wself);

    float4 b = *(const float4*)(bg + lane * 4);
    acc.x = fmaf(acc.x, inv, b.x);
    acc.y = fmaf(acc.y, inv, b.y);
    acc.z = fmaf(acc.z, inv, b.z);
    acc.w = fmaf(acc.w, inv, b.w);
    *(float4*)(g_B + (size_t)w * HD + lane * 4) = acc;
}

// ================= final: out = relu(B) @ Wc + bc =================
__global__ __launch_bounds__(256) void k_out(const float* __restrict__ Wc,
                                             const float* __restrict__ bc,
                                             float* __restrict__ out, int n) {
    __shared__ float4 ws[512];   // Wc[128][16] as float4
    for (int i = threadIdx.x; i < 512; i += 256) ws[i] = ((const float4*)Wc)[i];
    __syncthreads();
    int i = blockIdx.x * blockDim.x + threadIdx.x;
    if (i >= n) return;
    float4 a0 = ((const float4*)bc)[0];
    float4 a1 = ((const float4*)bc)[1];
    float4 a2 = ((const float4*)bc)[2];
    float4 a3 = ((const float4*)bc)[3];
    const float4* brow = (const float4*)(g_B + (size_t)i * HD);
    #pragma unroll 4
    for (int k0 = 0; k0 < 32; k0++) {
        float4 v = brow[k0];
        v.x = fmaxf(v.x, 0.f); v.y = fmaxf(v.y, 0.f);
        v.z = fmaxf(v.z, 0.f); v.w = fmaxf(v.w, 0.f);
        float bvals[4] = {v.x, v.y, v.z, v.w};
        #pragma unroll
        for (int kk = 0; kk < 4; kk++) {
            float bv = bvals[kk];
            const float4* wp = &ws[(k0 * 4 + kk) * 4];
            float4 w0 = wp[0], w1 = wp[1], w2 = wp[2], w3 = wp[3];
            a0.x = fmaf(bv, w0.x, a0.x); a0.y = fmaf(bv, w0.y, a0.y);
            a0.z = fmaf(bv, w0.z, a0.z); a0.w = fmaf(bv, w0.w, a0.w);
            a1.x = fmaf(bv, w1.x, a1.x); a1.y = fmaf(bv, w1.y, a1.y);
            a1.z = fmaf(bv, w1.z, a1.z); a1.w = fmaf(bv, w1.w, a1.w);
            a2.x = fmaf(bv, w2.x, a2.x); a2.y = fmaf(bv, w2.y, a2.y);
            a2.z = fmaf(bv, w2.z, a2.z); a2.w = fmaf(bv, w2.w, a2.w);
            a3.x = fmaf(bv, w3.x, a3.x); a3.y = fmaf(bv, w3.y, a3.y);
            a3.z = fmaf(bv, w3.z, a3.z); a3.w = fmaf(bv, w3.w, a3.w);
        }
    }
    float4* op = (float4*)(out + (size_t)i * 16);
    op[0] = a0; op[1] = a1; op[2] = a2; op[3] = a3;
}

static inline int ceildiv(int a, int b) { return (a + b - 1) / b; }

extern "C" void kernel_launch(void* const* d_in, const int* in_sizes, int n_in,
                              void* d_out, int out_size) {
    const float* x       = (const float*)d_in[0];
    const int*   ei      = (const int*)d_in[1];
    const float* ew      = (const float*)d_in[2];
    const float* W1      = (const float*)d_in[3];
    const float* b1      = (const float*)d_in[4];
    const float* W2      = (const float*)d_in[5];
    const float* b2      = (const float*)d_in[6];
    const float* Wg      = (const float*)d_in[7];
    const float* att_src = (const float*)d_in[8];
    const float* att_dst = (const float*)d_in[9];
    const float* bg      = (const float*)d_in[10];
    const float* Wc      = (const float*)d_in[11];
    const float* bc      = (const float*)d_in[12];

    int n = in_sizes[0] / HD;
    int e = in_sizes[2];
    const int* src = ei;
    const int* dst = ei + e;

    __half* dAh = nullptr;
    float*  dB  = nullptr;
    cudaGetSymbolAddress((void**)&dAh, g_Ah);
    cudaGetSymbolAddress((void**)&dB,  g_B);

    const int tb = 256;
    const int gb = ceildiv(n, 64);
    const int ga = ceildiv(n, 8);       // warp-per-node: 8 nodes/block
    const int nb = ceildiv(n, SCAN_B);

    // ---- CSR build start (gemm1 hoisted to 4th launch for ncu capture) ----
    k_zero<<<ceildiv(n, tb), tb>>>(n);
    k_count_deg<<<ceildiv(e, tb), tb>>>(dst, ew, e);
    k_scan1<<<nb, SCAN_B>>>(n);

    // ---- GCN layer 1 GEMM (independent of CSR; 4th launch = profiled) ----
    k_gemm128<false><<<gb, tb>>>(x, W1, dAh, n);

    // ---- CSR build finish ----
    k_scan3_dinv<<<ceildiv(n, tb), tb>>>(n, nb);
    k_fill<<<ceildiv(e, tb), tb>>>(src, dst, ew, e);

    // ---- GCN layer 1 aggregate ----
    k_gcn_agg<<<ga, tb>>>(b1, n);
    // ---- GCN layer 2 ----
    k_gemm128<true><<<gb, tb>>>(dB, W2, dAh, n);
    k_gcn_agg<<<ga, tb>>>(b2, n);
    // ---- GAT projection ----
    k_gemm128<true><<<gb, tb>>>(dB, Wg, dAh, n);
    k_dots<<<ga, tb>>>(att_src, att_dst, n);
    // ---- GAT softmax-aggregate ----
    k_gat_agg<<<ga, tb>>>(bg, n);
    // ---- classifier ----
    k_out<<<ceildiv(n, tb), tb>>>(Wc, bc, (float*)d_out, n);
}

// round 12
// speedup vs baseline: 2.0940x; 1.2630x over previous
#include <cuda_runtime.h>
#include <cuda_fp16.h>
#include <cstdint>

#define HD 128
#define NMAX 100000
#define EMAX 1600000
#define SCAN_B 1024
#define LDW 136   // padded smem row stride in halves (272 B: conflict-free ldmatrix)

// -------- scratch (device globals; no allocations allowed) --------
__device__ float  g_deg[NMAX];
__device__ float  g_dinv[NMAX];
__device__ __half g_Ah[(size_t)NMAX * HD];   // GEMM outputs (gather source)
__device__ __half g_Bh[(size_t)NMAX * HD];   // GCN agg outputs, relu'd (GEMM input)
__device__ float  g_B[(size_t)NMAX * HD];    // GAT agg output (fp32, feeds k_out)
__device__ float  g_as[NMAX];
__device__ float  g_ad[NMAX];
__device__ int    g_cnt[NMAX];
__device__ int    g_rowptr[NMAX + 1];
__device__ int    g_cur[NMAX + 1];
__device__ int    g_bsum[128];
__device__ int    g_csr_src[EMAX];
__device__ float  g_csr_coef[EMAX];

__device__ __forceinline__ float leaky(float x) { return x > 0.f ? x : 0.2f * x; }

__device__ __forceinline__ unsigned sptr(const void* p) {
    return (unsigned)__cvta_generic_to_shared(p);
}

__device__ __forceinline__ void ldsm_x4(unsigned& r0, unsigned& r1, unsigned& r2, unsigned& r3,
                                        unsigned addr) {
    asm volatile("ldmatrix.sync.aligned.m8n8.x4.shared.b16 {%0,%1,%2,%3}, [%4];"
                 : "=r"(r0), "=r"(r1), "=r"(r2), "=r"(r3) : "r"(addr));
}

__device__ __forceinline__ void ldsm_x4_t(unsigned& r0, unsigned& r1, unsigned& r2, unsigned& r3,
                                          unsigned addr) {
    asm volatile("ldmatrix.sync.aligned.m8n8.x4.trans.shared.b16 {%0,%1,%2,%3}, [%4];"
                 : "=r"(r0), "=r"(r1), "=r"(r2), "=r"(r3) : "r"(addr));
}

__device__ __forceinline__ void mma16816(float& c0, float& c1, float& c2, float& c3,
                                         unsigned a0, unsigned a1, unsigned a2, unsigned a3,
                                         unsigned b0, unsigned b1) {
    asm volatile("mma.sync.aligned.m16n8k16.row.col.f32.f16.f16.f32 "
                 "{%0,%1,%2,%3}, {%4,%5,%6,%7}, {%8,%9}, {%0,%1,%2,%3};"
                 : "+f"(c0), "+f"(c1), "+f"(c2), "+f"(c3)
                 : "r"(a0), "r"(a1), "r"(a2), "r"(a3), "r"(b0), "r"(b1));
}

__device__ __forceinline__ unsigned packh2(float a, float b) {
    __half2 h = __floats2half2_rn(a, b);
    return *(unsigned*)&h;
}

// load 4 consecutive fp16 elements (lane-owned quad) of a row as float4
__device__ __forceinline__ float4 ldrow4h(const __half* __restrict__ base, int node, int lane) {
    uint2 u = *(const uint2*)(base + (size_t)node * HD + lane * 4);
    __half2 h0 = *(__half2*)&u.x;
    __half2 h1 = *(__half2*)&u.y;
    float2 f0 = __half22float2(h0);
    float2 f1 = __half22float2(h1);
    return make_float4(f0.x, f0.y, f1.x, f1.y);
}

// ================= CSR build =================
__global__ void k_zero(int n) {
    int i = blockIdx.x * blockDim.x + threadIdx.x;
    if (i < n) { g_cnt[i] = 0; g_deg[i] = 1.0f; }
    if (i == 0) { g_rowptr[0] = 0; g_cur[0] = 0; }
}

__global__ void k_count_deg(const int* __restrict__ dst, const float* __restrict__ ew, int e) {
    int i = blockIdx.x * blockDim.x + threadIdx.x;
    if (i >= e) return;
    int d = dst[i];
    atomicAdd(&g_cnt[d], 1);
    atomicAdd(&g_deg[d], ew[i]);
}

__global__ __launch_bounds__(SCAN_B) void k_scan1(int n) {
    __shared__ int s[SCAN_B];
    int t = threadIdx.x;
    int g = blockIdx.x * SCAN_B + t;
    int v = (g < n) ? g_cnt[g] : 0;
    s[t] = v;
    __syncthreads();
    for (int o = 1; o < SCAN_B; o <<= 1) {
        int x = (t >= o) ? s[t - o] : 0;
        __syncthreads();
        s[t] += x;
        __syncthreads();
    }
    if (g < n) g_rowptr[g + 1] = s[t];
    if (t == SCAN_B - 1) g_bsum[blockIdx.x] = s[t];
}

__global__ __launch_bounds__(256) void k_scan3_dinv(int n, int nb) {
    __shared__ int s[128];
    int t = threadIdx.x;
    int v = 0;
    if (t < 128) { v = (t < nb) ? g_bsum[t] : 0; s[t] = v; }
    __syncthreads();
    for (int o = 1; o < 128; o <<= 1) {
        int x = (t >= o && t < 128) ? s[t - o] : 0;
        __syncthreads();
        if (t < 128) s[t] += x;
        __syncthreads();
    }
    if (t < 128) s[t] -= v;
    __syncthreads();
    int i = blockIdx.x * blockDim.x + t;
    if (i >= n) return;
    int val = g_rowptr[i + 1] + s[i >> 10];
    g_rowptr[i + 1] = val;
    g_cur[i + 1] = val;
    float d = g_deg[i];
    g_dinv[i] = d > 0.f ? rsqrtf(d) : 0.f;
}

__global__ void k_fill(const int* __restrict__ src, const int* __restrict__ dst,
                       const float* __restrict__ ew, int e) {
    int i = blockIdx.x * blockDim.x + threadIdx.x;
    if (i >= e) return;
    int s = src[i], d = dst[i];
    int pos = atomicAdd(&g_cur[d], 1);
    g_csr_src[pos] = s;
    g_csr_coef[pos] = g_dinv[s] * ew[i] * g_dinv[d];
}

// ======= tensor-core GEMM: Yh[128-tile,128] = X @ W (fp16 in, fp32 accum, fp16 out) =======
// block = 256 threads (8 warps); warp w computes rows [w*16, w*16+16) x all 128 cols.
template<bool FP16IN>
__global__ __launch_bounds__(256, 2) void k_gemm_tc(const void* __restrict__ Xv,
                                                    const float* __restrict__ W,
                                                    __half* __restrict__ Y, int n) {
    extern __shared__ __half smbuf[];
    __half* xs = smbuf;                 // 128 x LDW
    __half* wt = smbuf + 128 * LDW;     // 128 x LDW, row-major [k][n]
    const int t = threadIdx.x;
    const int row0 = blockIdx.x * 128;

    // stage W (fp32 -> fp16), row-major
    for (int i = t; i < 128 * 16; i += 256) {
        int k = i >> 4;
        int c8 = i & 15;
        float4 a = ((const float4*)W)[k * 32 + c8 * 2];
        float4 b = ((const float4*)W)[k * 32 + c8 * 2 + 1];
        uint4 q;
        q.x = packh2(a.x, a.y);
        q.y = packh2(a.z, a.w);
        q.z = packh2(b.x, b.y);
        q.w = packh2(b.z, b.w);
        *(uint4*)(wt + k * LDW + c8 * 8) = q;
    }

    // stage X tile (zero-pad beyond n)
    for (int i = t; i < 128 * 16; i += 256) {
        int r = i >> 4;
        int c8 = i & 15;
        int gr = row0 + r;
        uint4 q = make_uint4(0u, 0u, 0u, 0u);
        if (gr < n) {
            if (FP16IN) {
                q = *(const uint4*)((const __half*)Xv + (size_t)gr * HD + c8 * 8);
            } else {
                const float4* p = (const float4*)((const float*)Xv + (size_t)gr * HD + c8 * 8);
                float4 a = p[0];
                float4 b = p[1];
                q.x = packh2(a.x, a.y);
                q.y = packh2(a.z, a.w);
                q.z = packh2(b.x, b.y);
                q.w = packh2(b.z, b.w);
            }
        }
        *(uint4*)(xs + r * LDW + c8 * 8) = q;
    }
    __syncthreads();

    const int warp = t >> 5;
    const int lane = t & 31;
    const int mrow = warp * 16;

    // ldmatrix lane addressing: lanes 0-7 -> rows 0-7 col 0; 8-15 -> rows 8-15 col 0;
    // 16-23 -> rows 0-7 col 8; 24-31 -> rows 8-15 col 8.
    const int lrow = (lane & 7) + ((lane >> 3) & 1) * 8;
    const int lcol = (lane >> 4) * 8;
    const unsigned a_addr = sptr(xs + (mrow + lrow) * LDW + lcol);
    const unsigned b_addr = sptr(wt + lrow * LDW + lcol);

    float acc[16][4];
    for (int f = 0; f < 16; f++) {
        acc[f][0] = 0.f; acc[f][1] = 0.f; acc[f][2] = 0.f; acc[f][3] = 0.f;
    }

    #pragma unroll
    for (int ks = 0; ks < 8; ks++) {
        unsigned a0, a1, a2, a3;
        ldsm_x4(a0, a1, a2, a3, a_addr + ks * 32);            // +16 halves along k
        unsigned bkrow = b_addr + (unsigned)(ks * 16 * LDW * 2); // +16 k-rows
        #pragma unroll
        for (int np = 0; np < 8; np++) {
            unsigned b0, b1, b2, b3;
            ldsm_x4_t(b0, b1, b2, b3, bkrow + np * 32);       // +16 halves along n
            mma16816(acc[np * 2][0], acc[np * 2][1], acc[np * 2][2], acc[np * 2][3],
                     a0, a1, a2, a3, b0, b1);
            mma16816(acc[np * 2 + 1][0], acc[np * 2 + 1][1], acc[np * 2 + 1][2], acc[np * 2 + 1][3],
                     a0, a1, a2, a3, b2, b3);
        }
    }

    // epilogue: write fp16
    const int rl = mrow + (lane >> 2);
    const int cb = (lane & 3) * 2;
    #pragma unroll
    for (int f = 0; f < 16; f++) {
        int gr = row0 + rl;
        if (gr < n) {
            unsigned h = packh2(acc[f][0], acc[f][1]);
            *(unsigned*)(Y + (size_t)gr * HD + f * 8 + cb) = h;
        }
        int gr2 = gr + 8;
        if (gr2 < n) {
            unsigned h = packh2(acc[f][2], acc[f][3]);
            *(unsigned*)(Y + (size_t)gr2 * HD + f * 8 + cb) = h;
        }
    }
}

// ====== GCN aggregation (fp16 gather, warp per dst node) — stores relu'd fp16 ======
__global__ __launch_bounds__(256) void k_gcn_agg(const float* __restrict__ bias, int n) {
    int w = (blockIdx.x * blockDim.x + threadIdx.x) >> 5;
    if (w >= n) return;
    int lane = threadIdx.x & 31;
    int beg = g_rowptr[w];
    int end = g_rowptr[w + 1];

    float di = g_dinv[w];
    float cself = di * di;
    float4 av = ldrow4h(g_Ah, w, lane);
    float4 b  = *(const float4*)(bias + lane * 4);
    float4 acc;
    acc.x = fmaf(cself, av.x, b.x);
    acc.y = fmaf(cself, av.y, b.y);
    acc.z = fmaf(cself, av.z, b.z);
    acc.w = fmaf(cself, av.w, b.w);

    for (int j0 = beg; j0 < end; j0 += 32) {
        int idx = j0 + lane;
        int s = 0;
        float c = 0.f;
        if (idx < end) { s = g_csr_src[idx]; c = g_csr_coef[idx]; }
        int m = min(32, end - j0);
        int j = 0;
        for (; j + 1 < m; j += 2) {
            int   s0 = __shfl_sync(0xffffffffu, s, j);
            float c0 = __shfl_sync(0xffffffffu, c, j);
            int   s1 = __shfl_sync(0xffffffffu, s, j + 1);
            float c1 = __shfl_sync(0xffffffffu, c, j + 1);
            float4 v0 = ldrow4h(g_Ah, s0, lane);
            float4 v1 = ldrow4h(g_Ah, s1, lane);
            acc.x = fmaf(c0, v0.x, acc.x); acc.y = fmaf(c0, v0.y, acc.y);
            acc.z = fmaf(c0, v0.z, acc.z); acc.w = fmaf(c0, v0.w, acc.w);
            acc.x = fmaf(c1, v1.x, acc.x); acc.y = fmaf(c1, v1.y, acc.y);
            acc.z = fmaf(c1, v1.z, acc.z); acc.w = fmaf(c1, v1.w, acc.w);
        }
        if (j < m) {
            int   s0 = __shfl_sync(0xffffffffu, s, j);
            float c0 = __shfl_sync(0xffffffffu, c, j);
            float4 v0 = ldrow4h(g_Ah, s0, lane);
            acc.x = fmaf(c0, v0.x, acc.x); acc.y = fmaf(c0, v0.y, acc.y);
            acc.z = fmaf(c0, v0.z, acc.z); acc.w = fmaf(c0, v0.w, acc.w);
        }
    }
    // relu fused here; next GEMM consumes fp16 directly
    uint2 u;
    u.x = packh2(fmaxf(acc.x, 0.f), fmaxf(acc.y, 0.f));
    u.y = packh2(fmaxf(acc.z, 0.f), fmaxf(acc.w, 0.f));
    *(uint2*)(g_Bh + (size_t)w * HD + lane * 4) = u;
}

// ====== attention dots (warp per node, fp16 source) ======
__global__ __launch_bounds__(256) void k_dots(const float* __restrict__ asrc,
                                              const float* __restrict__ adst, int n) {
    int gw = (blockIdx.x * blockDim.x + threadIdx.x) >> 5;
    if (gw >= n) return;
    int lane = threadIdx.x & 31;
    float4 gv = ldrow4h(g_Ah, gw, lane);
    float4 s = *(const float4*)(asrc + lane * 4);
    float4 d = *(const float4*)(adst + lane * 4);
    float vs = gv.x * s.x + gv.y * s.y + gv.z * s.z + gv.w * s.w;
    float vd = gv.x * d.x + gv.y * d.y + gv.z * d.z + gv.w * d.w;
    for (int o = 16; o; o >>= 1) {
        vs += __shfl_xor_sync(0xffffffffu, vs, o);
        vd += __shfl_xor_sync(0xffffffffu, vd, o);
    }
    if (lane == 0) { g_as[gw] = vs; g_ad[gw] = vd; }
}

// ====== GAT: fused softmax + aggregation (warp per dst node, fp16 gather) ======
__global__ __launch_bounds__(256) void k_gat_agg(const float* __restrict__ bg, int n) {
    int w = (blockIdx.x * blockDim.x + threadIdx.x) >> 5;
    if (w >= n) return;
    int lane = threadIdx.x & 31;
    int beg = g_rowptr[w];
    int end = g_rowptr[w + 1];

    float ad_d = g_ad[w];
    float a_self = leaky(g_as[w] + ad_d);

    float mx = a_self;
    for (int idx = beg + lane; idx < end; idx += 32) {
        int s = g_csr_src[idx];
        mx = fmaxf(mx, leaky(g_as[s] + ad_d));
    }
    for (int o = 16; o; o >>= 1)
        mx = fmaxf(mx, __shfl_xor_sync(0xffffffffu, mx, o));

    float wself = expf(a_self - mx);
    float denp = 0.f;
    float4 av = ldrow4h(g_Ah, w, lane);
    float4 acc;
    acc.x = wself * av.x; acc.y = wself * av.y;
    acc.z = wself * av.z; acc.w = wself * av.w;

    for (int j0 = beg; j0 < end; j0 += 32) {
        int idx = j0 + lane;
        int s = 0;
        float ww = 0.f;
        if (idx < end) {
            s = g_csr_src[idx];
            ww = expf(leaky(g_as[s] + ad_d) - mx);
            denp += ww;
        }
        int m = min(32, end - j0);
        int j = 0;
        for (; j + 1 < m; j += 2) {
            int   s0 = __shfl_sync(0xffffffffu, s, j);
            float w0 = __shfl_sync(0xffffffffu, ww, j);
            int   s1 = __shfl_sync(0xffffffffu, s, j + 1);
            float w1 = __shfl_sync(0xffffffffu, ww, j + 1);
            float4 v0 = ldrow4h(g_Ah, s0, lane);
            float4 v1 = ldrow4h(g_Ah, s1, lane);
            acc.x = fmaf(w0, v0.x, acc.x); acc.y = fmaf(w0, v0.y, acc.y);
            acc.z = fmaf(w0, v0.z, acc.z); acc.w = fmaf(w0, v0.w, acc.w);
            acc.x = fmaf(w1, v1.x, acc.x); acc.y = fmaf(w1, v1.y, acc.y);
            acc.z = fmaf(w1, v1.z, acc.z); acc.w = fmaf(w1, v1.w, acc.w);
        }
        if (j < m) {
            int   s0 = __shfl_sync(0xffffffffu, s, j);
            float w0 = __shfl_sync(0xffffffffu, ww, j);
            float4 v0 = ldrow4h(g_Ah, s0, lane);
            acc.x = fmaf(w0, v0.x, acc.x); acc.y = fmaf(w0, v0.y, acc.y);
            acc.z = fmaf(w0, v0.z, acc.z); acc.w = fmaf(w0, v0.w, acc.w);
        }
    }
    for (int o = 16; o; o >>= 1)
        denp += __shfl_xor_sync(0xffffffffu, denp, o);
    float inv = 1.0f / (denp + wself);

    float4 b = *(const float4*)(bg + lane * 4);
    acc.x = fmaf(acc.x, inv, b.x);
    acc.y = fmaf(acc.y, inv, b.y);
    acc.z = fmaf(acc.z, inv, b.z);
    acc.w = fmaf(acc.w, inv, b.w);
    *(float4*)(g_B + (size_t)w * HD + lane * 4) = acc;
}

// ================= final: out = relu(B) @ Wc + bc =================
__global__ __launch_bounds__(256) void k_out(const float* __restrict__ Wc,
                                             const float* __restrict__ bc,
                                             float* __restrict__ out, int n) {
    __shared__ float ws[128 * 16];
    for (int i = threadIdx.x; i < 128 * 16 / 4; i += 256)
        ((float4*)ws)[i] = ((const float4*)Wc)[i];
    __syncthreads();
    int i = blockIdx.x * blockDim.x + threadIdx.x;
    if (i >= n) return;

    float o16[16];
    for (int c = 0; c < 16; c++) o16[c] = bc[c];

    const float* brow = g_B + (size_t)i * HD;
    #pragma unroll 4
    for (int k = 0; k < 128; k++) {
        float bv = fmaxf(brow[k], 0.f);
        const float* wrow = ws + k * 16;
        #pragma unroll
        for (int c = 0; c < 16; c++)
            o16[c] = fmaf(bv, wrow[c], o16[c]);
    }
    float* op = out + (size_t)i * 16;
    for (int c = 0; c < 16; c++) op[c] = o16[c];
}

static inline int ceildiv(int a, int b) { return (a + b - 1) / b; }

extern "C" void kernel_launch(void* const* d_in, const int* in_sizes, int n_in,
                              void* d_out, int out_size) {
    const float* x       = (const float*)d_in[0];
    const int*   ei      = (const int*)d_in[1];
    const float* ew      = (const float*)d_in[2];
    const float* W1      = (const float*)d_in[3];
    const float* b1      = (const float*)d_in[4];
    const float* W2      = (const float*)d_in[5];
    const float* b2      = (const float*)d_in[6];
    const float* Wg      = (const float*)d_in[7];
    const float* att_src = (const float*)d_in[8];
    const float* att_dst = (const float*)d_in[9];
    const float* bg      = (const float*)d_in[10];
    const float* Wc      = (const float*)d_in[11];
    const float* bc      = (const float*)d_in[12];

    int n = in_sizes[0] / HD;
    int e = in_sizes[2];
    const int* src = ei;
    const int* dst = ei + e;

    __half* dAh = nullptr;
    __half* dBh = nullptr;
    cudaGetSymbolAddress((void**)&dAh, g_Ah);
    cudaGetSymbolAddress((void**)&dBh, g_Bh);

    const int SMEM = 2 * 128 * LDW * (int)sizeof(__half);   // 69632
    cudaFuncSetAttribute(k_gemm_tc<false>, cudaFuncAttributeMaxDynamicSharedMemorySize, SMEM);
    cudaFuncSetAttribute(k_gemm_tc<true>,  cudaFuncAttributeMaxDynamicSharedMemorySize, SMEM);

    const int tb = 256;
    const int gt = ceildiv(n, 128);     // tensor GEMM: 128-row tiles
    const int ga = ceildiv(n, 8);       // warp-per-node kernels
    const int nb = ceildiv(n, SCAN_B);

    // ---- CSR build start (gemm1 hoisted to 4th launch for ncu capture) ----
    k_zero<<<ceildiv(n, tb), tb>>>(n);
    k_count_deg<<<ceildiv(e, tb), tb>>>(dst, ew, e);
    k_scan1<<<nb, SCAN_B>>>(n);

    // ---- GCN layer 1 GEMM (tensor cores; 4th launch = profiled) ----
    k_gemm_tc<false><<<gt, tb, SMEM>>>(x, W1, dAh, n);

    // ---- CSR build finish ----
    k_scan3_dinv<<<ceildiv(n, tb), tb>>>(n, nb);
    k_fill<<<ceildiv(e, tb), tb>>>(src, dst, ew, e);

    // ---- GCN layer 1 aggregate (writes relu'd fp16) ----
    k_gcn_agg<<<ga, tb>>>(b1, n);
    // ---- GCN layer 2 ----
    k_gemm_tc<true><<<gt, tb, SMEM>>>(dBh, W2, dAh, n);
    k_gcn_agg<<<ga, tb>>>(b2, n);
    // ---- GAT projection ----
    k_gemm_tc<true><<<gt, tb, SMEM>>>(dBh, Wg, dAh, n);
    k_dots<<<ga, tb>>>(att_src, att_dst, n);
    // ---- GAT softmax-aggregate ----
    k_gat_agg<<<ga, tb>>>(bg, n);
    // ---- classifier ----
    k_out<<<ceildiv(n, tb), tb>>>(Wc, bc, (float*)d_out, n);
}

// round 13
// speedup vs baseline: 2.3751x; 1.1342x over previous
#include <cuda_runtime.h>
#include <cuda_fp16.h>
#include <cstdint>

#define HD 128
#define NMAX 100000
#define EMAX 1600000
#define SCAN_B 1024
#define LDW 136   // padded smem row stride in halves (272 B: conflict-free ldmatrix)

// -------- scratch (device globals; no allocations allowed) --------
__device__ float  g_deg[NMAX];
__device__ float  g_dinv[NMAX];
__device__ __half g_Ah[(size_t)NMAX * HD];   // GEMM outputs (gather source)
__device__ __half g_Bh[(size_t)NMAX * HD];   // agg outputs fp16 (GEMM/classifier input)
__device__ __half g_Wh[3 * 128 * 128];       // pre-converted fp16 weights
__device__ float  g_as[NMAX];
__device__ float  g_ad[NMAX];
__device__ int    g_cnt[NMAX];
__device__ int    g_rowptr[NMAX + 1];
__device__ int    g_cur[NMAX + 1];
__device__ int    g_bsum[128];
__device__ int    g_csr_src[EMAX];
__device__ float  g_csr_coef[EMAX];

__device__ __forceinline__ float leaky(float x) { return x > 0.f ? x : 0.2f * x; }

__device__ __forceinline__ unsigned sptr(const void* p) {
    return (unsigned)__cvta_generic_to_shared(p);
}

__device__ __forceinline__ void ldsm_x4(unsigned& r0, unsigned& r1, unsigned& r2, unsigned& r3,
                                        unsigned addr) {
    asm volatile("ldmatrix.sync.aligned.m8n8.x4.shared.b16 {%0,%1,%2,%3}, [%4];"
                 : "=r"(r0), "=r"(r1), "=r"(r2), "=r"(r3) : "r"(addr));
}

__device__ __forceinline__ void ldsm_x4_t(unsigned& r0, unsigned& r1, unsigned& r2, unsigned& r3,
                                          unsigned addr) {
    asm volatile("ldmatrix.sync.aligned.m8n8.x4.trans.shared.b16 {%0,%1,%2,%3}, [%4];"
                 : "=r"(r0), "=r"(r1), "=r"(r2), "=r"(r3) : "r"(addr));
}

__device__ __forceinline__ void mma16816(float& c0, float& c1, float& c2, float& c3,
                                         unsigned a0, unsigned a1, unsigned a2, unsigned a3,
                                         unsigned b0, unsigned b1) {
    asm volatile("mma.sync.aligned.m16n8k16.row.col.f32.f16.f16.f32 "
                 "{%0,%1,%2,%3}, {%4,%5,%6,%7}, {%8,%9}, {%0,%1,%2,%3};"
                 : "+f"(c0), "+f"(c1), "+f"(c2), "+f"(c3)
                 : "r"(a0), "r"(a1), "r"(a2), "r"(a3), "r"(b0), "r"(b1));
}

__device__ __forceinline__ unsigned packh2(float a, float b) {
    __half2 h = __floats2half2_rn(a, b);
    return *(unsigned*)&h;
}

__device__ __forceinline__ void cpa16(unsigned dst, const void* src, int szbytes) {
    asm volatile("cp.async.cg.shared.global [%0], [%1], 16, %2;"
                 :: "r"(dst), "l"(src), "r"(szbytes));
}

__device__ __forceinline__ void cpa_commit_wait() {
    asm volatile("cp.async.commit_group;" ::: "memory");
    asm volatile("cp.async.wait_group 0;" ::: "memory");
}

// load 4 consecutive fp16 elements (lane-owned quad) of a row as float4
__device__ __forceinline__ float4 ldrow4h(const __half* __restrict__ base, int node, int lane) {
    uint2 u = *(const uint2*)(base + (size_t)node * HD + lane * 4);
    __half2 h0 = *(__half2*)&u.x;
    __half2 h1 = *(__half2*)&u.y;
    float2 f0 = __half22float2(h0);
    float2 f1 = __half22float2(h1);
    return make_float4(f0.x, f0.y, f1.x, f1.y);
}

// ================= weight pre-conversion (fp32 -> fp16, once) =================
__global__ void k_cvtw(const float* __restrict__ W1, const float* __restrict__ W2,
                       const float* __restrict__ Wg) {
    int idx = blockIdx.x * blockDim.x + threadIdx.x;
    if (idx >= 3 * 2048) return;
    int layer = idx / 2048;
    int off = (idx % 2048) * 8;
    const float* W = (layer == 0) ? W1 : ((layer == 1) ? W2 : Wg);
    float4 a = *(const float4*)(W + off);
    float4 b = *(const float4*)(W + off + 4);
    uint4 q;
    q.x = packh2(a.x, a.y);
    q.y = packh2(a.z, a.w);
    q.z = packh2(b.x, b.y);
    q.w = packh2(b.z, b.w);
    *(uint4*)(g_Wh + layer * 16384 + off) = q;
}

// ================= CSR build =================
__global__ void k_zero(int n) {
    int i = blockIdx.x * blockDim.x + threadIdx.x;
    if (i < n) { g_cnt[i] = 0; g_deg[i] = 1.0f; }
    if (i == 0) { g_rowptr[0] = 0; g_cur[0] = 0; }
}

__global__ void k_count_deg(const int* __restrict__ dst, const float* __restrict__ ew, int e) {
    int i = blockIdx.x * blockDim.x + threadIdx.x;
    if (i >= e) return;
    int d = dst[i];
    atomicAdd(&g_cnt[d], 1);
    atomicAdd(&g_deg[d], ew[i]);
}

__global__ __launch_bounds__(SCAN_B) void k_scan1(int n) {
    __shared__ int s[SCAN_B];
    int t = threadIdx.x;
    int g = blockIdx.x * SCAN_B + t;
    int v = (g < n) ? g_cnt[g] : 0;
    s[t] = v;
    __syncthreads();
    for (int o = 1; o < SCAN_B; o <<= 1) {
        int x = (t >= o) ? s[t - o] : 0;
        __syncthreads();
        s[t] += x;
        __syncthreads();
    }
    if (g < n) g_rowptr[g + 1] = s[t];
    if (t == SCAN_B - 1) g_bsum[blockIdx.x] = s[t];
}

__global__ __launch_bounds__(256) void k_scan3_dinv(int n, int nb) {
    __shared__ int s[128];
    int t = threadIdx.x;
    int v = 0;
    if (t < 128) { v = (t < nb) ? g_bsum[t] : 0; s[t] = v; }
    __syncthreads();
    for (int o = 1; o < 128; o <<= 1) {
        int x = (t >= o && t < 128) ? s[t - o] : 0;
        __syncthreads();
        if (t < 128) s[t] += x;
        __syncthreads();
    }
    if (t < 128) s[t] -= v;
    __syncthreads();
    int i = blockIdx.x * blockDim.x + t;
    if (i >= n) return;
    int val = g_rowptr[i + 1] + s[i >> 10];
    g_rowptr[i + 1] = val;
    g_cur[i + 1] = val;
    float d = g_deg[i];
    g_dinv[i] = d > 0.f ? rsqrtf(d) : 0.f;
}

__global__ void k_fill(const int* __restrict__ src, const int* __restrict__ dst,
                       const float* __restrict__ ew, int e) {
    int i = blockIdx.x * blockDim.x + threadIdx.x;
    if (i >= e) return;
    int s = src[i], d = dst[i];
    int pos = atomicAdd(&g_cur[d], 1);
    g_csr_src[pos] = s;
    g_csr_coef[pos] = g_dinv[s] * ew[i] * g_dinv[d];
}

// ======= tensor-core GEMM: Yh[128-tile,128] = X @ W (fp16 in/out, fp32 accum) =======
// W pre-converted fp16 (Wh). cp.async staging. Optional fused attention dots (DOTS).
template<bool FP16IN, bool DOTS>
__global__ __launch_bounds__(256, 2) void k_gemm_tc(const void* __restrict__ Xv,
                                                    const __half* __restrict__ Wh,
                                                    __half* __restrict__ Y,
                                                    const float* __restrict__ asrc,
                                                    const float* __restrict__ adst,
                                                    int n) {
    extern __shared__ __half smbuf[];
    __half* xs = smbuf;                 // 128 x LDW
    __half* wt = smbuf + 128 * LDW;     // 128 x LDW, row-major [k][n]
    const int t = threadIdx.x;
    const int row0 = blockIdx.x * 128;

    // stage W (fp16, cp.async)
    for (int i = t; i < 128 * 16; i += 256) {
        int k = i >> 4;
        int c8 = i & 15;
        cpa16(sptr(wt + k * LDW + c8 * 8), Wh + k * 128 + c8 * 8, 16);
    }

    // stage X tile
    if (FP16IN) {
        const __half* X = (const __half*)Xv;
        for (int i = t; i < 128 * 16; i += 256) {
            int r = i >> 4;
            int c8 = i & 15;
            int gr = row0 + r;
            int grc = (gr < n) ? gr : (n - 1);           // keep address valid
            cpa16(sptr(xs + r * LDW + c8 * 8),
                  X + (size_t)grc * HD + c8 * 8, (gr < n) ? 16 : 0);
        }
        cpa_commit_wait();
    } else {
        const float* X = (const float*)Xv;
        for (int i = t; i < 128 * 16; i += 256) {
            int r = i >> 4;
            int c8 = i & 15;
            int gr = row0 + r;
            uint4 q = make_uint4(0u, 0u, 0u, 0u);
            if (gr < n) {
                const float4* p = (const float4*)(X + (size_t)gr * HD + c8 * 8);
                float4 a = p[0];
                float4 b = p[1];
                q.x = packh2(a.x, a.y);
                q.y = packh2(a.z, a.w);
                q.z = packh2(b.x, b.y);
                q.w = packh2(b.z, b.w);
            }
            *(uint4*)(xs + r * LDW + c8 * 8) = q;
        }
        cpa_commit_wait();
    }
    __syncthreads();

    const int warp = t >> 5;
    const int lane = t & 31;
    const int mrow = warp * 16;

    const int lrow = (lane & 7) + ((lane >> 3) & 1) * 8;
    const int lcol = (lane >> 4) * 8;
    const unsigned a_addr = sptr(xs + (mrow + lrow) * LDW + lcol);
    const unsigned b_addr = sptr(wt + lrow * LDW + lcol);

    float acc[16][4];
    for (int f = 0; f < 16; f++) {
        acc[f][0] = 0.f; acc[f][1] = 0.f; acc[f][2] = 0.f; acc[f][3] = 0.f;
    }

    #pragma unroll
    for (int ks = 0; ks < 8; ks++) {
        unsigned a0, a1, a2, a3;
        ldsm_x4(a0, a1, a2, a3, a_addr + ks * 32);
        unsigned bkrow = b_addr + (unsigned)(ks * 16 * LDW * 2);
        #pragma unroll
        for (int np = 0; np < 8; np++) {
            unsigned b0, b1, b2, b3;
            ldsm_x4_t(b0, b1, b2, b3, bkrow + np * 32);
            mma16816(acc[np * 2][0], acc[np * 2][1], acc[np * 2][2], acc[np * 2][3],
                     a0, a1, a2, a3, b0, b1);
            mma16816(acc[np * 2 + 1][0], acc[np * 2 + 1][1], acc[np * 2 + 1][2], acc[np * 2 + 1][3],
                     a0, a1, a2, a3, b2, b3);
        }
    }

    const int rl = mrow + (lane >> 2);
    const int cb = (lane & 3) * 2;

    // fused attention dots (GEMM3 only): per-row dot with att_src/att_dst from fp32 acc
    if (DOTS) {
        float ps1 = 0.f, pd1 = 0.f, ps2 = 0.f, pd2 = 0.f;
        #pragma unroll
        for (int f = 0; f < 16; f++) {
            float s0 = __ldg(asrc + f * 8 + cb);
            float s1 = __ldg(asrc + f * 8 + cb + 1);
            float d0 = __ldg(adst + f * 8 + cb);
            float d1 = __ldg(adst + f * 8 + cb + 1);
            ps1 += acc[f][0] * s0 + acc[f][1] * s1;
            pd1 += acc[f][0] * d0 + acc[f][1] * d1;
            ps2 += acc[f][2] * s0 + acc[f][3] * s1;
            pd2 += acc[f][2] * d0 + acc[f][3] * d1;
        }
        for (int o = 1; o <= 2; o <<= 1) {
            ps1 += __shfl_xor_sync(0xffffffffu, ps1, o);
            pd1 += __shfl_xor_sync(0xffffffffu, pd1, o);
            ps2 += __shfl_xor_sync(0xffffffffu, ps2, o);
            pd2 += __shfl_xor_sync(0xffffffffu, pd2, o);
        }
        if ((lane & 3) == 0) {
            int gr = row0 + rl;
            if (gr < n) { g_as[gr] = ps1; g_ad[gr] = pd1; }
            if (gr + 8 < n) { g_as[gr + 8] = ps2; g_ad[gr + 8] = pd2; }
        }
    }

    // epilogue: write fp16
    #pragma unroll
    for (int f = 0; f < 16; f++) {
        int gr = row0 + rl;
        if (gr < n) {
            unsigned h = packh2(acc[f][0], acc[f][1]);
            *(unsigned*)(Y + (size_t)gr * HD + f * 8 + cb) = h;
        }
        int gr2 = gr + 8;
        if (gr2 < n) {
            unsigned h = packh2(acc[f][2], acc[f][3]);
            *(unsigned*)(Y + (size_t)gr2 * HD + f * 8 + cb) = h;
        }
    }
}

// ====== GCN aggregation (fp16 gather, warp per dst node) — stores relu'd fp16 ======
__global__ __launch_bounds__(256) void k_gcn_agg(const float* __restrict__ bias, int n) {
    int w = (blockIdx.x * blockDim.x + threadIdx.x) >> 5;
    if (w >= n) return;
    int lane = threadIdx.x & 31;
    int beg = g_rowptr[w];
    int end = g_rowptr[w + 1];

    float di = g_dinv[w];
    float cself = di * di;
    float4 av = ldrow4h(g_Ah, w, lane);
    float4 b  = *(const float4*)(bias + lane * 4);
    float4 acc;
    acc.x = fmaf(cself, av.x, b.x);
    acc.y = fmaf(cself, av.y, b.y);
    acc.z = fmaf(cself, av.z, b.z);
    acc.w = fmaf(cself, av.w, b.w);

    for (int j0 = beg; j0 < end; j0 += 32) {
        int idx = j0 + lane;
        int s = 0;
        float c = 0.f;
        if (idx < end) { s = g_csr_src[idx]; c = g_csr_coef[idx]; }
        int m = min(32, end - j0);
        int j = 0;
        for (; j + 1 < m; j += 2) {
            int   s0 = __shfl_sync(0xffffffffu, s, j);
            float c0 = __shfl_sync(0xffffffffu, c, j);
            int   s1 = __shfl_sync(0xffffffffu, s, j + 1);
            float c1 = __shfl_sync(0xffffffffu, c, j + 1);
            float4 v0 = ldrow4h(g_Ah, s0, lane);
            float4 v1 = ldrow4h(g_Ah, s1, lane);
            acc.x = fmaf(c0, v0.x, acc.x); acc.y = fmaf(c0, v0.y, acc.y);
            acc.z = fmaf(c0, v0.z, acc.z); acc.w = fmaf(c0, v0.w, acc.w);
            acc.x = fmaf(c1, v1.x, acc.x); acc.y = fmaf(c1, v1.y, acc.y);
            acc.z = fmaf(c1, v1.z, acc.z); acc.w = fmaf(c1, v1.w, acc.w);
        }
        if (j < m) {
            int   s0 = __shfl_sync(0xffffffffu, s, j);
            float c0 = __shfl_sync(0xffffffffu, c, j);
            float4 v0 = ldrow4h(g_Ah, s0, lane);
            acc.x = fmaf(c0, v0.x, acc.x); acc.y = fmaf(c0, v0.y, acc.y);
            acc.z = fmaf(c0, v0.z, acc.z); acc.w = fmaf(c0, v0.w, acc.w);
        }
    }
    uint2 u;
    u.x = packh2(fmaxf(acc.x, 0.f), fmaxf(acc.y, 0.f));
    u.y = packh2(fmaxf(acc.z, 0.f), fmaxf(acc.w, 0.f));
    *(uint2*)(g_Bh + (size_t)w * HD + lane * 4) = u;
}

// ====== GAT: fused softmax + aggregation (warp per dst node, fp16 gather) ======
// writes bg + softmax-weighted sum as fp16 into g_Bh (pre-relu; k_out applies relu)
__global__ __launch_bounds__(256) void k_gat_agg(const float* __restrict__ bg, int n) {
    int w = (blockIdx.x * blockDim.x + threadIdx.x) >> 5;
    if (w >= n) return;
    int lane = threadIdx.x & 31;
    int beg = g_rowptr[w];
    int end = g_rowptr[w + 1];

    float ad_d = g_ad[w];
    float a_self = leaky(g_as[w] + ad_d);

    float mx = a_self;
    for (int idx = beg + lane; idx < end; idx += 32) {
        int s = g_csr_src[idx];
        mx = fmaxf(mx, leaky(g_as[s] + ad_d));
    }
    for (int o = 16; o; o >>= 1)
        mx = fmaxf(mx, __shfl_xor_sync(0xffffffffu, mx, o));

    float wself = expf(a_self - mx);
    float denp = 0.f;
    float4 av = ldrow4h(g_Ah, w, lane);
    float4 acc;
    acc.x = wself * av.x; acc.y = wself * av.y;
    acc.z = wself * av.z; acc.w = wself * av.w;

    for (int j0 = beg; j0 < end; j0 += 32) {
        int idx = j0 + lane;
        int s = 0;
        float ww = 0.f;
        if (idx < end) {
            s = g_csr_src[idx];
            ww = expf(leaky(g_as[s] + ad_d) - mx);
            denp += ww;
        }
        int m = min(32, end - j0);
        int j = 0;
        for (; j + 1 < m; j += 2) {
            int   s0 = __shfl_sync(0xffffffffu, s, j);
            float w0 = __shfl_sync(0xffffffffu, ww, j);
            int   s1 = __shfl_sync(0xffffffffu, s, j + 1);
            float w1 = __shfl_sync(0xffffffffu, ww, j + 1);
            float4 v0 = ldrow4h(g_Ah, s0, lane);
            float4 v1 = ldrow4h(g_Ah, s1, lane);
            acc.x = fmaf(w0, v0.x, acc.x); acc.y = fmaf(w0, v0.y, acc.y);
            acc.z = fmaf(w0, v0.z, acc.z); acc.w = fmaf(w0, v0.w, acc.w);
            acc.x = fmaf(w1, v1.x, acc.x); acc.y = fmaf(w1, v1.y, acc.y);
            acc.z = fmaf(w1, v1.z, acc.z); acc.w = fmaf(w1, v1.w, acc.w);
        }
        if (j < m) {
            int   s0 = __shfl_sync(0xffffffffu, s, j);
            float w0 = __shfl_sync(0xffffffffu, ww, j);
            float4 v0 = ldrow4h(g_Ah, s0, lane);
            acc.x = fmaf(w0, v0.x, acc.x); acc.y = fmaf(w0, v0.y, acc.y);
            acc.z = fmaf(w0, v0.z, acc.z); acc.w = fmaf(w0, v0.w, acc.w);
        }
    }
    for (int o = 16; o; o >>= 1)
        denp += __shfl_xor_sync(0xffffffffu, denp, o);
    float inv = 1.0f / (denp + wself);

    float4 b = *(const float4*)(bg + lane * 4);
    uint2 u;
    u.x = packh2(fmaf(acc.x, inv, b.x), fmaf(acc.y, inv, b.y));
    u.y = packh2(fmaf(acc.z, inv, b.z), fmaf(acc.w, inv, b.w));
    *(uint2*)(g_Bh + (size_t)w * HD + lane * 4) = u;
}

// ================= final: out = relu(Bh) @ Wc + bc (fp16 input) =================
__global__ __launch_bounds__(256) void k_out(const float* __restrict__ Wc,
                                             const float* __restrict__ bc,
                                             float* __restrict__ out, int n) {
    __shared__ float ws[128 * 16];
    for (int i = threadIdx.x; i < 128 * 16 / 4; i += 256)
        ((float4*)ws)[i] = ((const float4*)Wc)[i];
    __syncthreads();
    int i = blockIdx.x * blockDim.x + threadIdx.x;
    if (i >= n) return;

    float o16[16];
    for (int c = 0; c < 16; c++) o16[c] = bc[c];

    const __half* brow = g_Bh + (size_t)i * HD;
    #pragma unroll 4
    for (int k2 = 0; k2 < 64; k2++) {
        __half2 h = *(const __half2*)(brow + k2 * 2);
        float2 f = __half22float2(h);
        float b0 = fmaxf(f.x, 0.f);
        float b1 = fmaxf(f.y, 0.f);
        const float* w0 = ws + (k2 * 2) * 16;
        const float* w1 = w0 + 16;
        #pragma unroll
        for (int c = 0; c < 16; c++)
            o16[c] = fmaf(b0, w0[c], fmaf(b1, w1[c], o16[c]));
    }
    float* op = out + (size_t)i * 16;
    for (int c = 0; c < 16; c++) op[c] = o16[c];
}

static inline int ceildiv(int a, int b) { return (a + b - 1) / b; }

extern "C" void kernel_launch(void* const* d_in, const int* in_sizes, int n_in,
                              void* d_out, int out_size) {
    const float* x       = (const float*)d_in[0];
    const int*   ei      = (const int*)d_in[1];
    const float* ew      = (const float*)d_in[2];
    const float* W1      = (const float*)d_in[3];
    const float* b1      = (const float*)d_in[4];
    const float* W2      = (const float*)d_in[5];
    const float* b2      = (const float*)d_in[6];
    const float* Wg      = (const float*)d_in[7];
    const float* att_src = (const float*)d_in[8];
    const float* att_dst = (const float*)d_in[9];
    const float* bg      = (const float*)d_in[10];
    const float* Wc      = (const float*)d_in[11];
    const float* bc      = (const float*)d_in[12];

    int n = in_sizes[0] / HD;
    int e = in_sizes[2];
    const int* src = ei;
    const int* dst = ei + e;

    __half* dAh = nullptr;
    __half* dBh = nullptr;
    __half* dWh = nullptr;
    cudaGetSymbolAddress((void**)&dAh, g_Ah);
    cudaGetSymbolAddress((void**)&dBh, g_Bh);
    cudaGetSymbolAddress((void**)&dWh, g_Wh);

    const int SMEM = 2 * 128 * LDW * (int)sizeof(__half);   // 69632
    cudaFuncSetAttribute(k_gemm_tc<false, false>, cudaFuncAttributeMaxDynamicSharedMemorySize, SMEM);
    cudaFuncSetAttribute(k_gemm_tc<true,  false>, cudaFuncAttributeMaxDynamicSharedMemorySize, SMEM);
    cudaFuncSetAttribute(k_gemm_tc<true,  true>,  cudaFuncAttributeMaxDynamicSharedMemorySize, SMEM);
    cudaFuncSetAttribute(k_gemm_tc<false, false>, cudaFuncAttributePreferredSharedMemoryCarveout, 100);
    cudaFuncSetAttribute(k_gemm_tc<true,  false>, cudaFuncAttributePreferredSharedMemoryCarveout, 100);
    cudaFuncSetAttribute(k_gemm_tc<true,  true>,  cudaFuncAttributePreferredSharedMemoryCarveout, 100);

    const int tb = 256;
    const int gt = ceildiv(n, 128);     // tensor GEMM: 128-row tiles
    const int ga = ceildiv(n, 8);       // warp-per-node kernels
    const int nb = ceildiv(n, SCAN_B);

    // 1) weight conversion
    k_cvtw<<<24, tb>>>(W1, W2, Wg);
    // 2-3) CSR build start
    k_zero<<<ceildiv(n, tb), tb>>>(n);
    k_count_deg<<<ceildiv(e, tb), tb>>>(dst, ew, e);
    // 4) GCN layer 1 GEMM (profiled launch)
    k_gemm_tc<false, false><<<gt, tb, SMEM>>>(x, dWh, dAh, nullptr, nullptr, n);
    // 5-7) CSR build finish
    k_scan1<<<nb, SCAN_B>>>(n);
    k_scan3_dinv<<<ceildiv(n, tb), tb>>>(n, nb);
    k_fill<<<ceildiv(e, tb), tb>>>(src, dst, ew, e);
    // 8) GCN layer 1 aggregate (relu'd fp16 out)
    k_gcn_agg<<<ga, tb>>>(b1, n);
    // 9-10) GCN layer 2
    k_gemm_tc<true, false><<<gt, tb, SMEM>>>(dBh, dWh + 16384, dAh, nullptr, nullptr, n);
    k_gcn_agg<<<ga, tb>>>(b2, n);
    // 11) GAT projection + fused attention dots
    k_gemm_tc<true, true><<<gt, tb, SMEM>>>(dBh, dWh + 32768, dAh, att_src, att_dst, n);
    // 12) GAT softmax-aggregate (fp16 out)
    k_gat_agg<<<ga, tb>>>(bg, n);
    // 13) classifier
    k_out<<<ceildiv(n, tb), tb>>>(Wc, bc, (float*)d_out, n);
}

// round 14
// speedup vs baseline: 2.4125x; 1.0157x over previous
#include <cuda_runtime.h>
#include <cuda_fp16.h>
#include <cstdint>

#define HD 128
#define NMAX 100000
#define EMAX 1600000
#define SCAN_B 1024
#define LDW 136   // padded smem row stride in halves (272 B: conflict-free ldmatrix)

// -------- scratch (device globals; no allocations allowed) --------
__device__ float  g_deg[NMAX];
__device__ float  g_dinv[NMAX];
__device__ __half g_Ah[(size_t)NMAX * HD];   // GEMM outputs (gather source)
__device__ __half g_Bh[(size_t)NMAX * HD];   // x-fp16 / agg outputs (GEMM + classifier input)
__device__ __half g_Wh[3 * 128 * 128];       // pre-converted fp16 weights
__device__ float  g_as[NMAX];
__device__ float  g_ad[NMAX];
__device__ int    g_cnt[NMAX];
__device__ int    g_rowptr[NMAX + 1];
__device__ int    g_cur[NMAX + 1];
__device__ int    g_bsum[128];
__device__ int    g_csr_src[EMAX];
__device__ float  g_csr_coef[EMAX];

__device__ __forceinline__ float leaky(float x) { return x > 0.f ? x : 0.2f * x; }

__device__ __forceinline__ unsigned sptr(const void* p) {
    return (unsigned)__cvta_generic_to_shared(p);
}

__device__ __forceinline__ void ldsm_x4(unsigned& r0, unsigned& r1, unsigned& r2, unsigned& r3,
                                        unsigned addr) {
    asm volatile("ldmatrix.sync.aligned.m8n8.x4.shared.b16 {%0,%1,%2,%3}, [%4];"
                 : "=r"(r0), "=r"(r1), "=r"(r2), "=r"(r3) : "r"(addr));
}

__device__ __forceinline__ void ldsm_x4_t(unsigned& r0, unsigned& r1, unsigned& r2, unsigned& r3,
                                          unsigned addr) {
    asm volatile("ldmatrix.sync.aligned.m8n8.x4.trans.shared.b16 {%0,%1,%2,%3}, [%4];"
                 : "=r"(r0), "=r"(r1), "=r"(r2), "=r"(r3) : "r"(addr));
}

__device__ __forceinline__ void mma16816(float& c0, float& c1, float& c2, float& c3,
                                         unsigned a0, unsigned a1, unsigned a2, unsigned a3,
                                         unsigned b0, unsigned b1) {
    asm volatile("mma.sync.aligned.m16n8k16.row.col.f32.f16.f16.f32 "
                 "{%0,%1,%2,%3}, {%4,%5,%6,%7}, {%8,%9}, {%0,%1,%2,%3};"
                 : "+f"(c0), "+f"(c1), "+f"(c2), "+f"(c3)
                 : "r"(a0), "r"(a1), "r"(a2), "r"(a3), "r"(b0), "r"(b1));
}

__device__ __forceinline__ unsigned packh2(float a, float b) {
    __half2 h = __floats2half2_rn(a, b);
    return *(unsigned*)&h;
}

__device__ __forceinline__ void cpa16(unsigned dst, const void* src, int szbytes) {
    asm volatile("cp.async.cg.shared.global [%0], [%1], 16, %2;"
                 :: "r"(dst), "l"(src), "r"(szbytes));
}

// load 4 consecutive fp16 elements (lane-owned quad) of a row as float4
__device__ __forceinline__ float4 ldrow4h(const __half* __restrict__ base, int node, int lane) {
    uint2 u = *(const uint2*)(base + (size_t)node * HD + lane * 4);
    __half2 h0 = *(__half2*)&u.x;
    __half2 h1 = *(__half2*)&u.y;
    float2 f0 = __half22float2(h0);
    float2 f1 = __half22float2(h1);
    return make_float4(f0.x, f0.y, f1.x, f1.y);
}

// ========= prep: x -> fp16 (into g_Bh), W1/W2/Wg -> fp16, zero counters =========
__global__ void k_prep(const float* __restrict__ x, const float* __restrict__ W1,
                       const float* __restrict__ W2, const float* __restrict__ Wg, int n) {
    int idx = blockIdx.x * blockDim.x + threadIdx.x;
    if (idx < n * 32) {
        int node = idx >> 5;
        int c4 = idx & 31;
        float4 a = *(const float4*)(x + (size_t)node * HD + c4 * 4);
        uint2 u;
        u.x = packh2(a.x, a.y);
        u.y = packh2(a.z, a.w);
        *(uint2*)(g_Bh + (size_t)node * HD + c4 * 4) = u;
    }
    if (idx < 3 * 2048) {
        int layer = idx / 2048;
        int off = (idx % 2048) * 8;
        const float* W = (layer == 0) ? W1 : ((layer == 1) ? W2 : Wg);
        float4 a = *(const float4*)(W + off);
        float4 b = *(const float4*)(W + off + 4);
        uint4 q;
        q.x = packh2(a.x, a.y);
        q.y = packh2(a.z, a.w);
        q.z = packh2(b.x, b.y);
        q.w = packh2(b.z, b.w);
        *(uint4*)(g_Wh + layer * 16384 + off) = q;
    }
    if (idx < n) { g_cnt[idx] = 0; g_deg[idx] = 1.0f; }
    if (idx == 0) { g_rowptr[0] = 0; g_cur[0] = 0; }
}

// ================= CSR build =================
__global__ void k_count_deg(const int* __restrict__ dst, const float* __restrict__ ew, int e) {
    int i = blockIdx.x * blockDim.x + threadIdx.x;
    if (i >= e) return;
    int d = dst[i];
    atomicAdd(&g_cnt[d], 1);
    atomicAdd(&g_deg[d], ew[i]);
}

__global__ __launch_bounds__(SCAN_B) void k_scan1(int n) {
    __shared__ int s[SCAN_B];
    int t = threadIdx.x;
    int g = blockIdx.x * SCAN_B + t;
    int v = (g < n) ? g_cnt[g] : 0;
    s[t] = v;
    __syncthreads();
    for (int o = 1; o < SCAN_B; o <<= 1) {
        int x = (t >= o) ? s[t - o] : 0;
        __syncthreads();
        s[t] += x;
        __syncthreads();
    }
    if (g < n) g_rowptr[g + 1] = s[t];
    if (t == SCAN_B - 1) g_bsum[blockIdx.x] = s[t];
}

__global__ __launch_bounds__(256) void k_scan3_dinv(int n, int nb) {
    __shared__ int s[128];
    int t = threadIdx.x;
    int v = 0;
    if (t < 128) { v = (t < nb) ? g_bsum[t] : 0; s[t] = v; }
    __syncthreads();
    for (int o = 1; o < 128; o <<= 1) {
        int x = (t >= o && t < 128) ? s[t - o] : 0;
        __syncthreads();
        if (t < 128) s[t] += x;
        __syncthreads();
    }
    if (t < 128) s[t] -= v;
    __syncthreads();
    int i = blockIdx.x * blockDim.x + t;
    if (i >= n) return;
    int val = g_rowptr[i + 1] + s[i >> 10];
    g_rowptr[i + 1] = val;
    g_cur[i + 1] = val;
    float d = g_deg[i];
    g_dinv[i] = d > 0.f ? rsqrtf(d) : 0.f;
}

__global__ void k_fill(const int* __restrict__ src, const int* __restrict__ dst,
                       const float* __restrict__ ew, int e) {
    int i = blockIdx.x * blockDim.x + threadIdx.x;
    if (i >= e) return;
    int s = src[i], d = dst[i];
    int pos = atomicAdd(&g_cur[d], 1);
    g_csr_src[pos] = s;
    g_csr_coef[pos] = g_dinv[s] * ew[i] * g_dinv[d];
}

// ======= persistent tensor-core GEMM: multi-tile, W staged once, double-buffered X =======
// grid blocks each process tiles {bid, bid+grid, ...}; smem = W + 2 X buffers.
template<bool DOTS>
__global__ __launch_bounds__(256, 2) void k_gemm_tc(const __half* __restrict__ X,
                                                    const __half* __restrict__ Wh,
                                                    __half* __restrict__ Y,
                                                    const float* __restrict__ asrc,
                                                    const float* __restrict__ adst,
                                                    int n, int tot_tiles) {
    extern __shared__ __half smbuf[];
    __half* wt = smbuf;                                   // 128 x LDW
    __half* xb0 = smbuf + 128 * LDW;                      // X buffer 0
    __half* xb1 = smbuf + 2 * 128 * LDW;                  // X buffer 1
    const int t = threadIdx.x;
    const int bid = blockIdx.x;
    const int grid = gridDim.x;

    // this block's tile count
    int myt = (bid < tot_tiles) ? ((tot_tiles - 1 - bid) / grid + 1) : 0;

    // stage W (once per block)
    for (int i = t; i < 2048; i += 256) {
        int k = i >> 4;
        int c8 = i & 15;
        cpa16(sptr(wt + k * LDW + c8 * 8), Wh + k * 128 + c8 * 8, 16);
    }
    // stage first X tile into buf0
    if (myt > 0) {
        int row0 = bid * 128;
        for (int i = t; i < 2048; i += 256) {
            int r = i >> 4;
            int c8 = i & 15;
            int gr = row0 + r;
            int grc = min(gr, n - 1);
            cpa16(sptr(xb0 + r * LDW + c8 * 8), X + (size_t)grc * HD + c8 * 8, (gr < n) ? 16 : 0);
        }
    }
    asm volatile("cp.async.commit_group;" ::: "memory");
    if (myt == 0) {
        asm volatile("cp.async.wait_group 0;" ::: "memory");
        return;
    }

    const int warp = t >> 5;
    const int lane = t & 31;
    const int mrow = warp * 16;
    const int lrow = (lane & 7) + ((lane >> 3) & 1) * 8;
    const int lcol = (lane >> 4) * 8;
    const unsigned b_addr = sptr(wt + lrow * LDW + lcol);
    const int rl = mrow + (lane >> 2);
    const int cb = (lane & 3) * 2;

    int tile = bid;
    for (int it = 0; it < myt; it++, tile += grid) {
        // prefetch next tile into the other buffer
        if (it + 1 < myt) {
            int row0n = (tile + grid) * 128;
            __half* dstb = ((it + 1) & 1) ? xb1 : xb0;
            for (int i = t; i < 2048; i += 256) {
                int r = i >> 4;
                int c8 = i & 15;
                int gr = row0n + r;
                int grc = min(gr, n - 1);
                cpa16(sptr(dstb + r * LDW + c8 * 8), X + (size_t)grc * HD + c8 * 8,
                      (gr < n) ? 16 : 0);
            }
            asm volatile("cp.async.commit_group;" ::: "memory");
            asm volatile("cp.async.wait_group 1;" ::: "memory");
        } else {
            asm volatile("cp.async.wait_group 0;" ::: "memory");
        }
        __syncthreads();

        const __half* xs = (it & 1) ? xb1 : xb0;
        const int row0 = tile * 128;
        const unsigned a_addr = sptr(xs + (mrow + lrow) * LDW + lcol);

        float acc[16][4];
        #pragma unroll
        for (int f = 0; f < 16; f++) {
            acc[f][0] = 0.f; acc[f][1] = 0.f; acc[f][2] = 0.f; acc[f][3] = 0.f;
        }

        #pragma unroll
        for (int ks = 0; ks < 8; ks++) {
            unsigned a0, a1, a2, a3;
            ldsm_x4(a0, a1, a2, a3, a_addr + ks * 32);
            unsigned bkrow = b_addr + (unsigned)(ks * 16 * LDW * 2);
            #pragma unroll
            for (int np = 0; np < 8; np++) {
                unsigned b0, b1, b2, b3;
                ldsm_x4_t(b0, b1, b2, b3, bkrow + np * 32);
                mma16816(acc[np * 2][0], acc[np * 2][1], acc[np * 2][2], acc[np * 2][3],
                         a0, a1, a2, a3, b0, b1);
                mma16816(acc[np * 2 + 1][0], acc[np * 2 + 1][1], acc[np * 2 + 1][2],
                         acc[np * 2 + 1][3], a0, a1, a2, a3, b2, b3);
            }
        }

        // fused attention dots (GEMM3 only)
        if (DOTS) {
            float ps1 = 0.f, pd1 = 0.f, ps2 = 0.f, pd2 = 0.f;
            #pragma unroll
            for (int f = 0; f < 16; f++) {
                float s0 = __ldg(asrc + f * 8 + cb);
                float s1 = __ldg(asrc + f * 8 + cb + 1);
                float d0 = __ldg(adst + f * 8 + cb);
                float d1 = __ldg(adst + f * 8 + cb + 1);
                ps1 += acc[f][0] * s0 + acc[f][1] * s1;
                pd1 += acc[f][0] * d0 + acc[f][1] * d1;
                ps2 += acc[f][2] * s0 + acc[f][3] * s1;
                pd2 += acc[f][2] * d0 + acc[f][3] * d1;
            }
            for (int o = 1; o <= 2; o <<= 1) {
                ps1 += __shfl_xor_sync(0xffffffffu, ps1, o);
                pd1 += __shfl_xor_sync(0xffffffffu, pd1, o);
                ps2 += __shfl_xor_sync(0xffffffffu, ps2, o);
                pd2 += __shfl_xor_sync(0xffffffffu, pd2, o);
            }
            if ((lane & 3) == 0) {
                int gr = row0 + rl;
                if (gr < n) { g_as[gr] = ps1; g_ad[gr] = pd1; }
                if (gr + 8 < n) { g_as[gr + 8] = ps2; g_ad[gr + 8] = pd2; }
            }
        }

        // epilogue: write fp16
        #pragma unroll
        for (int f = 0; f < 16; f++) {
            int gr = row0 + rl;
            if (gr < n) {
                unsigned h = packh2(acc[f][0], acc[f][1]);
                *(unsigned*)(Y + (size_t)gr * HD + f * 8 + cb) = h;
            }
            int gr2 = gr + 8;
            if (gr2 < n) {
                unsigned h = packh2(acc[f][2], acc[f][3]);
                *(unsigned*)(Y + (size_t)gr2 * HD + f * 8 + cb) = h;
            }
        }
        __syncthreads();   // before buffer reuse by next prefetch
    }
}

// ====== GCN aggregation (fp16 gather, warp per dst node) — stores relu'd fp16 ======
__global__ __launch_bounds__(256) void k_gcn_agg(const float* __restrict__ bias, int n) {
    int w = (blockIdx.x * blockDim.x + threadIdx.x) >> 5;
    if (w >= n) return;
    int lane = threadIdx.x & 31;
    int beg = g_rowptr[w];
    int end = g_rowptr[w + 1];

    float di = g_dinv[w];
    float cself = di * di;
    float4 av = ldrow4h(g_Ah, w, lane);
    float4 b  = *(const float4*)(bias + lane * 4);
    float4 acc;
    acc.x = fmaf(cself, av.x, b.x);
    acc.y = fmaf(cself, av.y, b.y);
    acc.z = fmaf(cself, av.z, b.z);
    acc.w = fmaf(cself, av.w, b.w);

    for (int j0 = beg; j0 < end; j0 += 32) {
        int idx = j0 + lane;
        int s = 0;
        float c = 0.f;
        if (idx < end) { s = g_csr_src[idx]; c = g_csr_coef[idx]; }
        int m = min(32, end - j0);
        int j = 0;
        for (; j + 1 < m; j += 2) {
            int   s0 = __shfl_sync(0xffffffffu, s, j);
            float c0 = __shfl_sync(0xffffffffu, c, j);
            int   s1 = __shfl_sync(0xffffffffu, s, j + 1);
            float c1 = __shfl_sync(0xffffffffu, c, j + 1);
            float4 v0 = ldrow4h(g_Ah, s0, lane);
            float4 v1 = ldrow4h(g_Ah, s1, lane);
            acc.x = fmaf(c0, v0.x, acc.x); acc.y = fmaf(c0, v0.y, acc.y);
            acc.z = fmaf(c0, v0.z, acc.z); acc.w = fmaf(c0, v0.w, acc.w);
            acc.x = fmaf(c1, v1.x, acc.x); acc.y = fmaf(c1, v1.y, acc.y);
            acc.z = fmaf(c1, v1.z, acc.z); acc.w = fmaf(c1, v1.w, acc.w);
        }
        if (j < m) {
            int   s0 = __shfl_sync(0xffffffffu, s, j);
            float c0 = __shfl_sync(0xffffffffu, c, j);
            float4 v0 = ldrow4h(g_Ah, s0, lane);
            acc.x = fmaf(c0, v0.x, acc.x); acc.y = fmaf(c0, v0.y, acc.y);
            acc.z = fmaf(c0, v0.z, acc.z); acc.w = fmaf(c0, v0.w, acc.w);
        }
    }
    uint2 u;
    u.x = packh2(fmaxf(acc.x, 0.f), fmaxf(acc.y, 0.f));
    u.y = packh2(fmaxf(acc.z, 0.f), fmaxf(acc.w, 0.f));
    *(uint2*)(g_Bh + (size_t)w * HD + lane * 4) = u;
}

// ====== GAT: fused softmax + aggregation (warp per dst node, fp16 gather) ======
__global__ __launch_bounds__(256) void k_gat_agg(const float* __restrict__ bg, int n) {
    int w = (blockIdx.x * blockDim.x + threadIdx.x) >> 5;
    if (w >= n) return;
    int lane = threadIdx.x & 31;
    int beg = g_rowptr[w];
    int end = g_rowptr[w + 1];

    float ad_d = g_ad[w];
    float a_self = leaky(g_as[w] + ad_d);

    float mx = a_self;
    for (int idx = beg + lane; idx < end; idx += 32) {
        int s = g_csr_src[idx];
        mx = fmaxf(mx, leaky(g_as[s] + ad_d));
    }
    for (int o = 16; o; o >>= 1)
        mx = fmaxf(mx, __shfl_xor_sync(0xffffffffu, mx, o));

    float wself = expf(a_self - mx);
    float denp = 0.f;
    float4 av = ldrow4h(g_Ah, w, lane);
    float4 acc;
    acc.x = wself * av.x; acc.y = wself * av.y;
    acc.z = wself * av.z; acc.w = wself * av.w;

    for (int j0 = beg; j0 < end; j0 += 32) {
        int idx = j0 + lane;
        int s = 0;
        float ww = 0.f;
        if (idx < end) {
            s = g_csr_src[idx];
            ww = expf(leaky(g_as[s] + ad_d) - mx);
            denp += ww;
        }
        int m = min(32, end - j0);
        int j = 0;
        for (; j + 1 < m; j += 2) {
            int   s0 = __shfl_sync(0xffffffffu, s, j);
            float w0 = __shfl_sync(0xffffffffu, ww, j);
            int   s1 = __shfl_sync(0xffffffffu, s, j + 1);
            float w1 = __shfl_sync(0xffffffffu, ww, j + 1);
            float4 v0 = ldrow4h(g_Ah, s0, lane);
            float4 v1 = ldrow4h(g_Ah, s1, lane);
            acc.x = fmaf(w0, v0.x, acc.x); acc.y = fmaf(w0, v0.y, acc.y);
            acc.z = fmaf(w0, v0.z, acc.z); acc.w = fmaf(w0, v0.w, acc.w);
            acc.x = fmaf(w1, v1.x, acc.x); acc.y = fmaf(w1, v1.y, acc.y);
            acc.z = fmaf(w1, v1.z, acc.z); acc.w = fmaf(w1, v1.w, acc.w);
        }
        if (j < m) {
            int   s0 = __shfl_sync(0xffffffffu, s, j);
            float w0 = __shfl_sync(0xffffffffu, ww, j);
            float4 v0 = ldrow4h(g_Ah, s0, lane);
            acc.x = fmaf(w0, v0.x, acc.x); acc.y = fmaf(w0, v0.y, acc.y);
            acc.z = fmaf(w0, v0.z, acc.z); acc.w = fmaf(w0, v0.w, acc.w);
        }
    }
    for (int o = 16; o; o >>= 1)
        denp += __shfl_xor_sync(0xffffffffu, denp, o);
    float inv = 1.0f / (denp + wself);

    float4 b = *(const float4*)(bg + lane * 4);
    uint2 u;
    u.x = packh2(fmaf(acc.x, inv, b.x), fmaf(acc.y, inv, b.y));
    u.y = packh2(fmaf(acc.z, inv, b.z), fmaf(acc.w, inv, b.w));
    *(uint2*)(g_Bh + (size_t)w * HD + lane * 4) = u;
}

// ================= final: out = relu(Bh) @ Wc + bc (fp16 input) =================
__global__ __launch_bounds__(256) void k_out(const float* __restrict__ Wc,
                                             const float* __restrict__ bc,
                                             float* __restrict__ out, int n) {
    __shared__ float ws[128 * 16];
    for (int i = threadIdx.x; i < 128 * 16 / 4; i += 256)
        ((float4*)ws)[i] = ((const float4*)Wc)[i];
    __syncthreads();
    int i = blockIdx.x * blockDim.x + threadIdx.x;
    if (i >= n) return;

    float o16[16];
    for (int c = 0; c < 16; c++) o16[c] = bc[c];

    const __half* brow = g_Bh + (size_t)i * HD;
    #pragma unroll 4
    for (int k2 = 0; k2 < 64; k2++) {
        __half2 h = *(const __half2*)(brow + k2 * 2);
        float2 f = __half22float2(h);
        float b0 = fmaxf(f.x, 0.f);
        float b1 = fmaxf(f.y, 0.f);
        const float* w0 = ws + (k2 * 2) * 16;
        const float* w1 = w0 + 16;
        #pragma unroll
        for (int c = 0; c < 16; c++)
            o16[c] = fmaf(b0, w0[c], fmaf(b1, w1[c], o16[c]));
    }
    float* op = out + (size_t)i * 16;
    for (int c = 0; c < 16; c++) op[c] = o16[c];
}

static inline int ceildiv(int a, int b) { return (a + b - 1) / b; }

extern "C" void kernel_launch(void* const* d_in, const int* in_sizes, int n_in,
                              void* d_out, int out_size) {
    const float* x       = (const float*)d_in[0];
    const int*   ei      = (const int*)d_in[1];
    const float* ew      = (const float*)d_in[2];
    const float* W1      = (const float*)d_in[3];
    const float* b1      = (const float*)d_in[4];
    const float* W2      = (const float*)d_in[5];
    const float* b2      = (const float*)d_in[6];
    const float* Wg      = (const float*)d_in[7];
    const float* att_src = (const float*)d_in[8];
    const float* att_dst = (const float*)d_in[9];
    const float* bg      = (const float*)d_in[10];
    const float* Wc      = (const float*)d_in[11];
    const float* bc      = (const float*)d_in[12];

    int n = in_sizes[0] / HD;
    int e = in_sizes[2];
    const int* src = ei;
    const int* dst = ei + e;

    __half* dAh = nullptr;
    __half* dBh = nullptr;
    __half* dWh = nullptr;
    cudaGetSymbolAddress((void**)&dAh, g_Ah);
    cudaGetSymbolAddress((void**)&dBh, g_Bh);
    cudaGetSymbolAddress((void**)&dWh, g_Wh);

    const int SMEM = 3 * 128 * LDW * (int)sizeof(__half);   // 104448
    cudaFuncSetAttribute(k_gemm_tc<false>, cudaFuncAttributeMaxDynamicSharedMemorySize, SMEM);
    cudaFuncSetAttribute(k_gemm_tc<true>,  cudaFuncAttributeMaxDynamicSharedMemorySize, SMEM);
    cudaFuncSetAttribute(k_gemm_tc<false>, cudaFuncAttributePreferredSharedMemoryCarveout, 100);
    cudaFuncSetAttribute(k_gemm_tc<true>,  cudaFuncAttributePreferredSharedMemoryCarveout, 100);

    const int tb = 256;
    const int tot_tiles = ceildiv(n, 128);
    const int gt = (tot_tiles < 296) ? tot_tiles : 296;   // persistent-ish: 2 blocks/SM
    const int ga = ceildiv(n, 8);
    const int nb = ceildiv(n, SCAN_B);

    // 1) prep: x->fp16, W->fp16, zero counters
    k_prep<<<ceildiv(n * 32, tb), tb>>>(x, W1, W2, Wg, n);
    // 2-3) CSR build start
    k_count_deg<<<ceildiv(e, tb), tb>>>(dst, ew, e);
    k_scan1<<<nb, SCAN_B>>>(n);
    // 4) GCN layer 1 GEMM (profiled launch)
    k_gemm_tc<false><<<gt, tb, SMEM>>>(dBh, dWh, dAh, nullptr, nullptr, n, tot_tiles);
    // 5-6) CSR build finish
    k_scan3_dinv<<<ceildiv(n, tb), tb>>>(n, nb);
    k_fill<<<ceildiv(e, tb), tb>>>(src, dst, ew, e);
    // 7) GCN layer 1 aggregate (relu'd fp16 out)
    k_gcn_agg<<<ga, tb>>>(b1, n);
    // 8-9) GCN layer 2
    k_gemm_tc<false><<<gt, tb, SMEM>>>(dBh, dWh + 16384, dAh, nullptr, nullptr, n, tot_tiles);
    k_gcn_agg<<<ga, tb>>>(b2, n);
    // 10) GAT projection + fused attention dots
    k_gemm_tc<true><<<gt, tb, SMEM>>>(dBh, dWh + 32768, dAh, att_src, att_dst, n, tot_tiles);
    // 11) GAT softmax-aggregate (fp16 out)
    k_gat_agg<<<ga, tb>>>(bg, n);
    // 12) classifier
    k_out<<<ceildiv(n, tb), tb>>>(Wc, bc, (float*)d_out, n);
}

// round 15
// speedup vs baseline: 2.4198x; 1.0030x over previous
#include <cuda_runtime.h>
#include <cuda_fp16.h>
#include <cstdint>

#define HD 128
#define NMAX 100000
#define EMAX 1600000
#define SCAN_B 1024
#define LDW 136   // padded smem row stride in halves (272 B: conflict-free ldmatrix)

// -------- scratch (device globals; no allocations allowed) --------
__device__ float  g_deg[NMAX];
__device__ float  g_dinv[NMAX];
__device__ __half g_Ah[(size_t)NMAX * HD];   // GEMM outputs (gather source)
__device__ __half g_Bh[(size_t)NMAX * HD];   // x-fp16 / agg outputs (GEMM + classifier input)
__device__ __half g_Wh[3 * 128 * 128];       // pre-converted fp16 weights
__device__ float  g_as[NMAX];
__device__ float  g_ad[NMAX];
__device__ int    g_cnt[NMAX];
__device__ int    g_rowptr[NMAX + 1];
__device__ int    g_cur[NMAX + 1];
__device__ int    g_bsum[128];
__device__ int    g_csr_src[EMAX];
__device__ float  g_csr_coef[EMAX];

__device__ __forceinline__ float leaky(float x) { return x > 0.f ? x : 0.2f * x; }

__device__ __forceinline__ unsigned sptr(const void* p) {
    return (unsigned)__cvta_generic_to_shared(p);
}

__device__ __forceinline__ void ldsm_x4(unsigned& r0, unsigned& r1, unsigned& r2, unsigned& r3,
                                        unsigned addr) {
    asm volatile("ldmatrix.sync.aligned.m8n8.x4.shared.b16 {%0,%1,%2,%3}, [%4];"
                 : "=r"(r0), "=r"(r1), "=r"(r2), "=r"(r3) : "r"(addr));
}

__device__ __forceinline__ void ldsm_x4_t(unsigned& r0, unsigned& r1, unsigned& r2, unsigned& r3,
                                          unsigned addr) {
    asm volatile("ldmatrix.sync.aligned.m8n8.x4.trans.shared.b16 {%0,%1,%2,%3}, [%4];"
                 : "=r"(r0), "=r"(r1), "=r"(r2), "=r"(r3) : "r"(addr));
}

__device__ __forceinline__ void mma16816(float& c0, float& c1, float& c2, float& c3,
                                         unsigned a0, unsigned a1, unsigned a2, unsigned a3,
                                         unsigned b0, unsigned b1) {
    asm volatile("mma.sync.aligned.m16n8k16.row.col.f32.f16.f16.f32 "
                 "{%0,%1,%2,%3}, {%4,%5,%6,%7}, {%8,%9}, {%0,%1,%2,%3};"
                 : "+f"(c0), "+f"(c1), "+f"(c2), "+f"(c3)
                 : "r"(a0), "r"(a1), "r"(a2), "r"(a3), "r"(b0), "r"(b1));
}

__device__ __forceinline__ unsigned packh2(float a, float b) {
    __half2 h = __floats2half2_rn(a, b);
    return *(unsigned*)&h;
}

__device__ __forceinline__ void cpa16(unsigned dst, const void* src, int szbytes) {
    asm volatile("cp.async.cg.shared.global [%0], [%1], 16, %2;"
                 :: "r"(dst), "l"(src), "r"(szbytes));
}

// load 4 consecutive fp16 elements (lane-owned quad) of a row as float4
__device__ __forceinline__ float4 ldrow4h(const __half* __restrict__ base, int node, int lane) {
    uint2 u = *(const uint2*)(base + (size_t)node * HD + lane * 4);
    __half2 h0 = *(__half2*)&u.x;
    __half2 h1 = *(__half2*)&u.y;
    float2 f0 = __half22float2(h0);
    float2 f1 = __half22float2(h1);
    return make_float4(f0.x, f0.y, f1.x, f1.y);
}

// ========= prep: x -> fp16 (into g_Bh), W1/W2/Wg -> fp16, zero counters =========
__global__ void k_prep(const float* __restrict__ x, const float* __restrict__ W1,
                       const float* __restrict__ W2, const float* __restrict__ Wg, int n) {
    int idx = blockIdx.x * blockDim.x + threadIdx.x;
    if (idx < n * 32) {
        int node = idx >> 5;
        int c4 = idx & 31;
        float4 a = *(const float4*)(x + (size_t)node * HD + c4 * 4);
        uint2 u;
        u.x = packh2(a.x, a.y);
        u.y = packh2(a.z, a.w);
        *(uint2*)(g_Bh + (size_t)node * HD + c4 * 4) = u;
    }
    if (idx < 3 * 2048) {
        int layer = idx / 2048;
        int off = (idx % 2048) * 8;
        const float* W = (layer == 0) ? W1 : ((layer == 1) ? W2 : Wg);
        float4 a = *(const float4*)(W + off);
        float4 b = *(const float4*)(W + off + 4);
        uint4 q;
        q.x = packh2(a.x, a.y);
        q.y = packh2(a.z, a.w);
        q.z = packh2(b.x, b.y);
        q.w = packh2(b.z, b.w);
        *(uint4*)(g_Wh + layer * 16384 + off) = q;
    }
    if (idx < n) { g_cnt[idx] = 0; g_deg[idx] = 1.0f; }
    if (idx == 0) { g_rowptr[0] = 0; g_cur[0] = 0; }
}

// ================= CSR build =================
__global__ void k_count_deg(const int* __restrict__ dst, const float* __restrict__ ew, int e) {
    int i = blockIdx.x * blockDim.x + threadIdx.x;
    if (i >= e) return;
    int d = dst[i];
    atomicAdd(&g_cnt[d], 1);
    atomicAdd(&g_deg[d], ew[i]);
}

__global__ __launch_bounds__(SCAN_B) void k_scan1(int n) {
    __shared__ int s[SCAN_B];
    int t = threadIdx.x;
    int g = blockIdx.x * SCAN_B + t;
    int v = (g < n) ? g_cnt[g] : 0;
    s[t] = v;
    __syncthreads();
    for (int o = 1; o < SCAN_B; o <<= 1) {
        int x = (t >= o) ? s[t - o] : 0;
        __syncthreads();
        s[t] += x;
        __syncthreads();
    }
    if (g < n) g_rowptr[g + 1] = s[t];
    if (t == SCAN_B - 1) g_bsum[blockIdx.x] = s[t];
}

__global__ __launch_bounds__(256) void k_scan3_dinv(int n, int nb) {
    __shared__ int s[128];
    int t = threadIdx.x;
    int v = 0;
    if (t < 128) { v = (t < nb) ? g_bsum[t] : 0; s[t] = v; }
    __syncthreads();
    for (int o = 1; o < 128; o <<= 1) {
        int x = (t >= o && t < 128) ? s[t - o] : 0;
        __syncthreads();
        if (t < 128) s[t] += x;
        __syncthreads();
    }
    if (t < 128) s[t] -= v;
    __syncthreads();
    int i = blockIdx.x * blockDim.x + t;
    if (i >= n) return;
    int val = g_rowptr[i + 1] + s[i >> 10];
    g_rowptr[i + 1] = val;
    g_cur[i + 1] = val;
    float d = g_deg[i];
    g_dinv[i] = d > 0.f ? rsqrtf(d) : 0.f;
}

__global__ void k_fill(const int* __restrict__ src, const int* __restrict__ dst,
                       const float* __restrict__ ew, int e) {
    int i = blockIdx.x * blockDim.x + threadIdx.x;
    if (i >= e) return;
    int s = src[i], d = dst[i];
    int pos = atomicAdd(&g_cur[d], 1);
    g_csr_src[pos] = s;
    g_csr_coef[pos] = g_dinv[s] * ew[i] * g_dinv[d];
}

// ======= persistent tensor-core GEMM, 512 threads (16 warps) =======
// warp-tile = 16 rows x 64 cols: rs = warp>>1 selects row strip, ch = warp&1 selects col half.
// W staged once per block; X double-buffered via cp.async.
template<bool DOTS>
__global__ __launch_bounds__(512, 2) void k_gemm_tc(const __half* __restrict__ X,
                                                    const __half* __restrict__ Wh,
                                                    __half* __restrict__ Y,
                                                    const float* __restrict__ asrc,
                                                    const float* __restrict__ adst,
                                                    int n, int tot_tiles) {
    extern __shared__ __half smbuf[];
    __half* wt  = smbuf;                                  // 128 x LDW
    __half* xb0 = smbuf + 128 * LDW;                      // X buffer 0
    __half* xb1 = smbuf + 2 * 128 * LDW;                  // X buffer 1
    __shared__ float sdots[256];                          // [row][0:s,1:d] for DOTS
    const int t = threadIdx.x;
    const int bid = blockIdx.x;
    const int grid = gridDim.x;

    int myt = (bid < tot_tiles) ? ((tot_tiles - 1 - bid) / grid + 1) : 0;

    // stage W (once per block)
    for (int i = t; i < 2048; i += 512) {
        int k = i >> 4;
        int c8 = i & 15;
        cpa16(sptr(wt + k * LDW + c8 * 8), Wh + k * 128 + c8 * 8, 16);
    }
    // stage first X tile into buf0
    if (myt > 0) {
        int row0 = bid * 128;
        for (int i = t; i < 2048; i += 512) {
            int r = i >> 4;
            int c8 = i & 15;
            int gr = row0 + r;
            int grc = min(gr, n - 1);
            cpa16(sptr(xb0 + r * LDW + c8 * 8), X + (size_t)grc * HD + c8 * 8, (gr < n) ? 16 : 0);
        }
    }
    asm volatile("cp.async.commit_group;" ::: "memory");
    if (myt == 0) {
        asm volatile("cp.async.wait_group 0;" ::: "memory");
        return;
    }

    const int warp = t >> 5;
    const int lane = t & 31;
    const int rs = warp >> 1;        // row strip 0..7
    const int ch = warp & 1;         // column half 0..1
    const int mrow = rs * 16;
    const int lrow = (lane & 7) + ((lane >> 3) & 1) * 8;
    const int lcol = (lane >> 4) * 8;
    const unsigned b_addr = sptr(wt + lrow * LDW + ch * 64 + lcol);
    const int rl = mrow + (lane >> 2);
    const int cb = (lane & 3) * 2;

    int tile = bid;
    for (int it = 0; it < myt; it++, tile += grid) {
        // prefetch next tile into the other buffer
        if (it + 1 < myt) {
            int row0n = (tile + grid) * 128;
            __half* dstb = ((it + 1) & 1) ? xb1 : xb0;
            for (int i = t; i < 2048; i += 512) {
                int r = i >> 4;
                int c8 = i & 15;
                int gr = row0n + r;
                int grc = min(gr, n - 1);
                cpa16(sptr(dstb + r * LDW + c8 * 8), X + (size_t)grc * HD + c8 * 8,
                      (gr < n) ? 16 : 0);
            }
            asm volatile("cp.async.commit_group;" ::: "memory");
            asm volatile("cp.async.wait_group 1;" ::: "memory");
        } else {
            asm volatile("cp.async.wait_group 0;" ::: "memory");
        }
        if (DOTS && t < 256) sdots[t] = 0.f;
        __syncthreads();

        const __half* xs = (it & 1) ? xb1 : xb0;
        const int row0 = tile * 128;
        const unsigned a_addr = sptr(xs + (mrow + lrow) * LDW + lcol);

        float acc[8][4];
        #pragma unroll
        for (int f = 0; f < 8; f++) {
            acc[f][0] = 0.f; acc[f][1] = 0.f; acc[f][2] = 0.f; acc[f][3] = 0.f;
        }

        #pragma unroll
        for (int ks = 0; ks < 8; ks++) {
            unsigned a0, a1, a2, a3;
            ldsm_x4(a0, a1, a2, a3, a_addr + ks * 32);
            unsigned bkrow = b_addr + (unsigned)(ks * 16 * LDW * 2);
            #pragma unroll
            for (int np = 0; np < 4; np++) {
                unsigned b0, b1, b2, b3;
                ldsm_x4_t(b0, b1, b2, b3, bkrow + np * 32);
                mma16816(acc[np * 2][0], acc[np * 2][1], acc[np * 2][2], acc[np * 2][3],
                         a0, a1, a2, a3, b0, b1);
                mma16816(acc[np * 2 + 1][0], acc[np * 2 + 1][1], acc[np * 2 + 1][2],
                         acc[np * 2 + 1][3], a0, a1, a2, a3, b2, b3);
            }
        }

        // fused attention dots (GEMM3): per-row partial over this warp's 64 cols
        if (DOTS) {
            float ps1 = 0.f, pd1 = 0.f, ps2 = 0.f, pd2 = 0.f;
            #pragma unroll
            for (int f = 0; f < 8; f++) {
                int col = ch * 64 + f * 8 + cb;
                float s0 = __ldg(asrc + col);
                float s1 = __ldg(asrc + col + 1);
                float d0 = __ldg(adst + col);
                float d1 = __ldg(adst + col + 1);
                ps1 += acc[f][0] * s0 + acc[f][1] * s1;
                pd1 += acc[f][0] * d0 + acc[f][1] * d1;
                ps2 += acc[f][2] * s0 + acc[f][3] * s1;
                pd2 += acc[f][2] * d0 + acc[f][3] * d1;
            }
            for (int o = 1; o <= 2; o <<= 1) {
                ps1 += __shfl_xor_sync(0xffffffffu, ps1, o);
                pd1 += __shfl_xor_sync(0xffffffffu, pd1, o);
                ps2 += __shfl_xor_sync(0xffffffffu, ps2, o);
                pd2 += __shfl_xor_sync(0xffffffffu, pd2, o);
            }
            if ((lane & 3) == 0) {
                atomicAdd(&sdots[2 * rl], ps1);
                atomicAdd(&sdots[2 * rl + 1], pd1);
                atomicAdd(&sdots[2 * (rl + 8)], ps2);
                atomicAdd(&sdots[2 * (rl + 8) + 1], pd2);
            }
        }

        // epilogue: write fp16 (cols = ch*64 + f*8 + cb)
        #pragma unroll
        for (int f = 0; f < 8; f++) {
            int col = ch * 64 + f * 8 + cb;
            int gr = row0 + rl;
            if (gr < n) {
                unsigned h = packh2(acc[f][0], acc[f][1]);
                *(unsigned*)(Y + (size_t)gr * HD + col) = h;
            }
            int gr2 = gr + 8;
            if (gr2 < n) {
                unsigned h = packh2(acc[f][2], acc[f][3]);
                *(unsigned*)(Y + (size_t)gr2 * HD + col) = h;
            }
        }

        if (DOTS) {
            __syncthreads();
            if (t < 128) {
                int gr = row0 + t;
                if (gr < n) {
                    g_as[gr] = sdots[2 * t];
                    g_ad[gr] = sdots[2 * t + 1];
                }
            }
        }
        __syncthreads();   // buffer + sdots safe for reuse
    }
}

// ====== GCN aggregation (fp16 gather, warp per dst node) — stores relu'd fp16 ======
__global__ __launch_bounds__(256) void k_gcn_agg(const float* __restrict__ bias, int n) {
    int w = (blockIdx.x * blockDim.x + threadIdx.x) >> 5;
    if (w >= n) return;
    int lane = threadIdx.x & 31;
    int beg = g_rowptr[w];
    int end = g_rowptr[w + 1];

    float di = g_dinv[w];
    float cself = di * di;
    float4 av = ldrow4h(g_Ah, w, lane);
    float4 b  = *(const float4*)(bias + lane * 4);
    float4 acc;
    acc.x = fmaf(cself, av.x, b.x);
    acc.y = fmaf(cself, av.y, b.y);
    acc.z = fmaf(cself, av.z, b.z);
    acc.w = fmaf(cself, av.w, b.w);

    for (int j0 = beg; j0 < end; j0 += 32) {
        int idx = j0 + lane;
        int s = 0;
        float c = 0.f;
        if (idx < end) { s = g_csr_src[idx]; c = g_csr_coef[idx]; }
        int m = min(32, end - j0);
        int j = 0;
        for (; j + 1 < m; j += 2) {
            int   s0 = __shfl_sync(0xffffffffu, s, j);
            float c0 = __shfl_sync(0xffffffffu, c, j);
            int   s1 = __shfl_sync(0xffffffffu, s, j + 1);
            float c1 = __shfl_sync(0xffffffffu, c, j + 1);
            float4 v0 = ldrow4h(g_Ah, s0, lane);
            float4 v1 = ldrow4h(g_Ah, s1, lane);
            acc.x = fmaf(c0, v0.x, acc.x); acc.y = fmaf(c0, v0.y, acc.y);
            acc.z = fmaf(c0, v0.z, acc.z); acc.w = fmaf(c0, v0.w, acc.w);
            acc.x = fmaf(c1, v1.x, acc.x); acc.y = fmaf(c1, v1.y, acc.y);
            acc.z = fmaf(c1, v1.z, acc.z); acc.w = fmaf(c1, v1.w, acc.w);
        }
        if (j < m) {
            int   s0 = __shfl_sync(0xffffffffu, s, j);
            float c0 = __shfl_sync(0xffffffffu, c, j);
            float4 v0 = ldrow4h(g_Ah, s0, lane);
            acc.x = fmaf(c0, v0.x, acc.x); acc.y = fmaf(c0, v0.y, acc.y);
            acc.z = fmaf(c0, v0.z, acc.z); acc.w = fmaf(c0, v0.w, acc.w);
        }
    }
    uint2 u;
    u.x = packh2(fmaxf(acc.x, 0.f), fmaxf(acc.y, 0.f));
    u.y = packh2(fmaxf(acc.z, 0.f), fmaxf(acc.w, 0.f));
    *(uint2*)(g_Bh + (size_t)w * HD + lane * 4) = u;
}

// ====== GAT: fused softmax + aggregation (warp per dst node, fp16 gather) ======
__global__ __launch_bounds__(256) void k_gat_agg(const float* __restrict__ bg, int n) {
    int w = (blockIdx.x * blockDim.x + threadIdx.x) >> 5;
    if (w >= n) return;
    int lane = threadIdx.x & 31;
    int beg = g_rowptr[w];
    int end = g_rowptr[w + 1];

    float ad_d = g_ad[w];
    float a_self = leaky(g_as[w] + ad_d);

    float mx = a_self;
    for (int idx = beg + lane; idx < end; idx += 32) {
        int s = g_csr_src[idx];
        mx = fmaxf(mx, leaky(g_as[s] + ad_d));
    }
    for (int o = 16; o; o >>= 1)
        mx = fmaxf(mx, __shfl_xor_sync(0xffffffffu, mx, o));

    float wself = expf(a_self - mx);
    float denp = 0.f;
    float4 av = ldrow4h(g_Ah, w, lane);
    float4 acc;
    acc.x = wself * av.x; acc.y = wself * av.y;
    acc.z = wself * av.z; acc.w = wself * av.w;

    for (int j0 = beg; j0 < end; j0 += 32) {
        int idx = j0 + lane;
        int s = 0;
        float ww = 0.f;
        if (idx < end) {
            s = g_csr_src[idx];
            ww = expf(leaky(g_as[s] + ad_d) - mx);
            denp += ww;
        }
        int m = min(32, end - j0);
        int j = 0;
        for (; j + 1 < m; j += 2) {
            int   s0 = __shfl_sync(0xffffffffu, s, j);
            float w0 = __shfl_sync(0xffffffffu, ww, j);
            int   s1 = __shfl_sync(0xffffffffu, s, j + 1);
            float w1 = __shfl_sync(0xffffffffu, ww, j + 1);
            float4 v0 = ldrow4h(g_Ah, s0, lane);
            float4 v1 = ldrow4h(g_Ah, s1, lane);
            acc.x = fmaf(w0, v0.x, acc.x); acc.y = fmaf(w0, v0.y, acc.y);
            acc.z = fmaf(w0, v0.z, acc.z); acc.w = fmaf(w0, v0.w, acc.w);
            acc.x = fmaf(w1, v1.x, acc.x); acc.y = fmaf(w1, v1.y, acc.y);
            acc.z = fmaf(w1, v1.z, acc.z); acc.w = fmaf(w1, v1.w, acc.w);
        }
        if (j < m) {
            int   s0 = __shfl_sync(0xffffffffu, s, j);
            float w0 = __shfl_sync(0xffffffffu, ww, j);
            float4 v0 = ldrow4h(g_Ah, s0, lane);
            acc.x = fmaf(w0, v0.x, acc.x); acc.y = fmaf(w0, v0.y, acc.y);
            acc.z = fmaf(w0, v0.z, acc.z); acc.w = fmaf(w0, v0.w, acc.w);
        }
    }
    for (int o = 16; o; o >>= 1)
        denp += __shfl_xor_sync(0xffffffffu, denp, o);
    float inv = 1.0f / (denp + wself);

    float4 b = *(const float4*)(bg + lane * 4);
    uint2 u;
    u.x = packh2(fmaf(acc.x, inv, b.x), fmaf(acc.y, inv, b.y));
    u.y = packh2(fmaf(acc.z, inv, b.z), fmaf(acc.w, inv, b.w));
    *(uint2*)(g_Bh + (size_t)w * HD + lane * 4) = u;
}

// ================= final: out = relu(Bh) @ Wc + bc (fp16 input) =================
__global__ __launch_bounds__(256) void k_out(const float* __restrict__ Wc,
                                             const float* __restrict__ bc,
                                             float* __restrict__ out, int n) {
    __shared__ float ws[128 * 16];
    for (int i = threadIdx.x; i < 128 * 16 / 4; i += 256)
        ((float4*)ws)[i] = ((const float4*)Wc)[i];
    __syncthreads();
    int i = blockIdx.x * blockDim.x + threadIdx.x;
    if (i >= n) return;

    float o16[16];
    for (int c = 0; c < 16; c++) o16[c] = bc[c];

    const __half* brow = g_Bh + (size_t)i * HD;
    #pragma unroll 4
    for (int k2 = 0; k2 < 64; k2++) {
        __half2 h = *(const __half2*)(brow + k2 * 2);
        float2 f = __half22float2(h);
        float b0 = fmaxf(f.x, 0.f);
        float b1 = fmaxf(f.y, 0.f);
        const float* w0 = ws + (k2 * 2) * 16;
        const float* w1 = w0 + 16;
        #pragma unroll
        for (int c = 0; c < 16; c++)
            o16[c] = fmaf(b0, w0[c], fmaf(b1, w1[c], o16[c]));
    }
    float* op = out + (size_t)i * 16;
    for (int c = 0; c < 16; c++) op[c] = o16[c];
}

static inline int ceildiv(int a, int b) { return (a + b - 1) / b; }

extern "C" void kernel_launch(void* const* d_in, const int* in_sizes, int n_in,
                              void* d_out, int out_size) {
    const float* x       = (const float*)d_in[0];
    const int*   ei      = (const int*)d_in[1];
    const float* ew      = (const float*)d_in[2];
    const float* W1      = (const float*)d_in[3];
    const float* b1      = (const float*)d_in[4];
    const float* W2      = (const float*)d_in[5];
    const float* b2      = (const float*)d_in[6];
    const float* Wg      = (const float*)d_in[7];
    const float* att_src = (const float*)d_in[8];
    const float* att_dst = (const float*)d_in[9];
    const float* bg      = (const float*)d_in[10];
    const float* Wc      = (const float*)d_in[11];
    const float* bc      = (const float*)d_in[12];

    int n = in_sizes[0] / HD;
    int e = in_sizes[2];
    const int* src = ei;
    const int* dst = ei + e;

    __half* dAh = nullptr;
    __half* dBh = nullptr;
    __half* dWh = nullptr;
    cudaGetSymbolAddress((void**)&dAh, g_Ah);
    cudaGetSymbolAddress((void**)&dBh, g_Bh);
    cudaGetSymbolAddress((void**)&dWh, g_Wh);

    const int SMEM = 3 * 128 * LDW * (int)sizeof(__half);   // 104448
    cudaFuncSetAttribute(k_gemm_tc<false>, cudaFuncAttributeMaxDynamicSharedMemorySize, SMEM);
    cudaFuncSetAttribute(k_gemm_tc<true>,  cudaFuncAttributeMaxDynamicSharedMemorySize, SMEM);
    cudaFuncSetAttribute(k_gemm_tc<false>, cudaFuncAttributePreferredSharedMemoryCarveout, 100);
    cudaFuncSetAttribute(k_gemm_tc<true>,  cudaFuncAttributePreferredSharedMemoryCarveout, 100);

    const int tb = 256;
    const int tot_tiles = ceildiv(n, 128);
    const int gt = (tot_tiles < 296) ? tot_tiles : 296;   // persistent: 2 blocks/SM
    const int ga = ceildiv(n, 8);
    const int nb = ceildiv(n, SCAN_B);

    // 1) prep: x->fp16, W->fp16, zero counters
    k_prep<<<ceildiv(n * 32, tb), tb>>>(x, W1, W2, Wg, n);
    // 2-3) CSR build start
    k_count_deg<<<ceildiv(e, tb), tb>>>(dst, ew, e);
    k_scan1<<<nb, SCAN_B>>>(n);
    // 4) GCN layer 1 GEMM (profiled launch; 512 threads)
    k_gemm_tc<false><<<gt, 512, SMEM>>>(dBh, dWh, dAh, nullptr, nullptr, n, tot_tiles);
    // 5-6) CSR build finish
    k_scan3_dinv<<<ceildiv(n, tb), tb>>>(n, nb);
    k_fill<<<ceildiv(e, tb), tb>>>(src, dst, ew, e);
    // 7) GCN layer 1 aggregate (relu'd fp16 out)
    k_gcn_agg<<<ga, tb>>>(b1, n);
    // 8-9) GCN layer 2
    k_gemm_tc<false><<<gt, 512, SMEM>>>(dBh, dWh + 16384, dAh, nullptr, nullptr, n, tot_tiles);
    k_gcn_agg<<<ga, tb>>>(b2, n);
    // 10) GAT projection + fused attention dots
    k_gemm_tc<true><<<gt, 512, SMEM>>>(dBh, dWh + 32768, dAh, att_src, att_dst, n, tot_tiles);
    // 11) GAT softmax-aggregate (fp16 out)
    k_gat_agg<<<ga, tb>>>(bg, n);
    // 12) classifier
    k_out<<<ceildiv(n, tb), tb>>>(Wc, bc, (float*)d_out, n);
}

// round 16
// speedup vs baseline: 2.4511x; 1.0129x over previous
#include <cuda_runtime.h>
#include <cuda_fp16.h>
#include <cstdint>

#define HD 128
#define NMAX 100000
#define EMAX 1600000
#define SCAN_B 1024
#define LDW 136   // padded smem row stride in halves (272 B: conflict-free ldmatrix)

// -------- scratch (device globals; no allocations allowed) --------
__device__ float  g_deg[NMAX];
__device__ float  g_dinv[NMAX];
__device__ __half g_Ah[(size_t)NMAX * HD];   // GEMM outputs (gather source)
__device__ __half g_Bh[(size_t)NMAX * HD];   // x-fp16 / agg outputs (GEMM + classifier input)
__device__ __half g_Wh[3 * 128 * 128];       // pre-converted fp16 weights
__device__ float  g_as[NMAX];
__device__ float  g_ad[NMAX];
__device__ int    g_cnt[NMAX];
__device__ int    g_rowptr[NMAX + 1];
__device__ int    g_cur[NMAX + 1];
__device__ int    g_bsum[128];
__device__ int    g_csr_src[EMAX];
__device__ float  g_csr_coef[EMAX];

__device__ __forceinline__ float leaky(float x) { return x > 0.f ? x : 0.2f * x; }

__device__ __forceinline__ unsigned sptr(const void* p) {
    return (unsigned)__cvta_generic_to_shared(p);
}

__device__ __forceinline__ void ldsm_x4(unsigned& r0, unsigned& r1, unsigned& r2, unsigned& r3,
                                        unsigned addr) {
    asm volatile("ldmatrix.sync.aligned.m8n8.x4.shared.b16 {%0,%1,%2,%3}, [%4];"
                 : "=r"(r0), "=r"(r1), "=r"(r2), "=r"(r3) : "r"(addr));
}

__device__ __forceinline__ void ldsm_x4_t(unsigned& r0, unsigned& r1, unsigned& r2, unsigned& r3,
                                          unsigned addr) {
    asm volatile("ldmatrix.sync.aligned.m8n8.x4.trans.shared.b16 {%0,%1,%2,%3}, [%4];"
                 : "=r"(r0), "=r"(r1), "=r"(r2), "=r"(r3) : "r"(addr));
}

__device__ __forceinline__ void mma16816(float& c0, float& c1, float& c2, float& c3,
                                         unsigned a0, unsigned a1, unsigned a2, unsigned a3,
                                         unsigned b0, unsigned b1) {
    asm volatile("mma.sync.aligned.m16n8k16.row.col.f32.f16.f16.f32 "
                 "{%0,%1,%2,%3}, {%4,%5,%6,%7}, {%8,%9}, {%0,%1,%2,%3};"
                 : "+f"(c0), "+f"(c1), "+f"(c2), "+f"(c3)
                 : "r"(a0), "r"(a1), "r"(a2), "r"(a3), "r"(b0), "r"(b1));
}

__device__ __forceinline__ unsigned packh2(float a, float b) {
    __half2 h = __floats2half2_rn(a, b);
    return *(unsigned*)&h;
}

__device__ __forceinline__ void cpa16(unsigned dst, const void* src, int szbytes) {
    asm volatile("cp.async.cg.shared.global [%0], [%1], 16, %2;"
                 :: "r"(dst), "l"(src), "r"(szbytes));
}

// load 4 consecutive fp16 elements (lane-owned quad) of a row as float4
__device__ __forceinline__ float4 ldrow4h(const __half* __restrict__ base, int node, int lane) {
    uint2 u = *(const uint2*)(base + (size_t)node * HD + lane * 4);
    __half2 h0 = *(__half2*)&u.x;
    __half2 h1 = *(__half2*)&u.y;
    float2 f0 = __half22float2(h0);
    float2 f1 = __half22float2(h1);
    return make_float4(f0.x, f0.y, f1.x, f1.y);
}

// ========= prep (chain A): x -> fp16 (into g_Bh), W1/W2/Wg -> fp16 =========
__global__ void k_prep(const float* __restrict__ x, const float* __restrict__ W1,
                       const float* __restrict__ W2, const float* __restrict__ Wg, int n) {
    int idx = blockIdx.x * blockDim.x + threadIdx.x;
    if (idx < n * 32) {
        int node = idx >> 5;
        int c4 = idx & 31;
        float4 a = *(const float4*)(x + (size_t)node * HD + c4 * 4);
        uint2 u;
        u.x = packh2(a.x, a.y);
        u.y = packh2(a.z, a.w);
        *(uint2*)(g_Bh + (size_t)node * HD + c4 * 4) = u;
    }
    if (idx < 3 * 2048) {
        int layer = idx / 2048;
        int off = (idx % 2048) * 8;
        const float* W = (layer == 0) ? W1 : ((layer == 1) ? W2 : Wg);
        float4 a = *(const float4*)(W + off);
        float4 b = *(const float4*)(W + off + 4);
        uint4 q;
        q.x = packh2(a.x, a.y);
        q.y = packh2(a.z, a.w);
        q.z = packh2(b.x, b.y);
        q.w = packh2(b.z, b.w);
        *(uint4*)(g_Wh + layer * 16384 + off) = q;
    }
}

// ================= CSR build (chain B) =================
__global__ void k_zero(int n) {
    int i = blockIdx.x * blockDim.x + threadIdx.x;
    if (i < n) { g_cnt[i] = 0; g_deg[i] = 1.0f; }
    if (i == 0) { g_rowptr[0] = 0; g_cur[0] = 0; }
}

__global__ void k_count_deg(const int* __restrict__ dst, const float* __restrict__ ew, int e) {
    int i = blockIdx.x * blockDim.x + threadIdx.x;
    if (i >= e) return;
    int d = dst[i];
    atomicAdd(&g_cnt[d], 1);
    atomicAdd(&g_deg[d], ew[i]);
}

__global__ __launch_bounds__(SCAN_B) void k_scan1(int n) {
    __shared__ int s[SCAN_B];
    int t = threadIdx.x;
    int g = blockIdx.x * SCAN_B + t;
    int v = (g < n) ? g_cnt[g] : 0;
    s[t] = v;
    __syncthreads();
    for (int o = 1; o < SCAN_B; o <<= 1) {
        int x = (t >= o) ? s[t - o] : 0;
        __syncthreads();
        s[t] += x;
        __syncthreads();
    }
    if (g < n) g_rowptr[g + 1] = s[t];
    if (t == SCAN_B - 1) g_bsum[blockIdx.x] = s[t];
}

__global__ __launch_bounds__(256) void k_scan3_dinv(int n, int nb) {
    __shared__ int s[128];
    int t = threadIdx.x;
    int v = 0;
    if (t < 128) { v = (t < nb) ? g_bsum[t] : 0; s[t] = v; }
    __syncthreads();
    for (int o = 1; o < 128; o <<= 1) {
        int x = (t >= o && t < 128) ? s[t - o] : 0;
        __syncthreads();
        if (t < 128) s[t] += x;
        __syncthreads();
    }
    if (t < 128) s[t] -= v;
    __syncthreads();
    int i = blockIdx.x * blockDim.x + t;
    if (i >= n) return;
    int val = g_rowptr[i + 1] + s[i >> 10];
    g_rowptr[i + 1] = val;
    g_cur[i + 1] = val;
    float d = g_deg[i];
    g_dinv[i] = d > 0.f ? rsqrtf(d) : 0.f;
}

__global__ void k_fill(const int* __restrict__ src, const int* __restrict__ dst,
                       const float* __restrict__ ew, int e) {
    int i = blockIdx.x * blockDim.x + threadIdx.x;
    if (i >= e) return;
    int s = src[i], d = dst[i];
    int pos = atomicAdd(&g_cur[d], 1);
    g_csr_src[pos] = s;
    g_csr_coef[pos] = g_dinv[s] * ew[i] * g_dinv[d];
}

// ======= persistent tensor-core GEMM, 512 threads (16 warps) =======
template<bool DOTS>
__global__ __launch_bounds__(512, 2) void k_gemm_tc(const __half* __restrict__ X,
                                                    const __half* __restrict__ Wh,
                                                    __half* __restrict__ Y,
                                                    const float* __restrict__ asrc,
                                                    const float* __restrict__ adst,
                                                    int n, int tot_tiles) {
    extern __shared__ __half smbuf[];
    __half* wt  = smbuf;                                  // 128 x LDW
    __half* xb0 = smbuf + 128 * LDW;                      // X buffer 0
    __half* xb1 = smbuf + 2 * 128 * LDW;                  // X buffer 1
    __shared__ float sdots[256];
    const int t = threadIdx.x;
    const int bid = blockIdx.x;
    const int grid = gridDim.x;

    int myt = (bid < tot_tiles) ? ((tot_tiles - 1 - bid) / grid + 1) : 0;

    for (int i = t; i < 2048; i += 512) {
        int k = i >> 4;
        int c8 = i & 15;
        cpa16(sptr(wt + k * LDW + c8 * 8), Wh + k * 128 + c8 * 8, 16);
    }
    if (myt > 0) {
        int row0 = bid * 128;
        for (int i = t; i < 2048; i += 512) {
            int r = i >> 4;
            int c8 = i & 15;
            int gr = row0 + r;
            int grc = min(gr, n - 1);
            cpa16(sptr(xb0 + r * LDW + c8 * 8), X + (size_t)grc * HD + c8 * 8, (gr < n) ? 16 : 0);
        }
    }
    asm volatile("cp.async.commit_group;" ::: "memory");
    if (myt == 0) {
        asm volatile("cp.async.wait_group 0;" ::: "memory");
        return;
    }

    const int warp = t >> 5;
    const int lane = t & 31;
    const int rs = warp >> 1;
    const int ch = warp & 1;
    const int mrow = rs * 16;
    const int lrow = (lane & 7) + ((lane >> 3) & 1) * 8;
    const int lcol = (lane >> 4) * 8;
    const unsigned b_addr = sptr(wt + lrow * LDW + ch * 64 + lcol);
    const int rl = mrow + (lane >> 2);
    const int cb = (lane & 3) * 2;

    int tile = bid;
    for (int it = 0; it < myt; it++, tile += grid) {
        if (it + 1 < myt) {
            int row0n = (tile + grid) * 128;
            __half* dstb = ((it + 1) & 1) ? xb1 : xb0;
            for (int i = t; i < 2048; i += 512) {
                int r = i >> 4;
                int c8 = i & 15;
                int gr = row0n + r;
                int grc = min(gr, n - 1);
                cpa16(sptr(dstb + r * LDW + c8 * 8), X + (size_t)grc * HD + c8 * 8,
                      (gr < n) ? 16 : 0);
            }
            asm volatile("cp.async.commit_group;" ::: "memory");
            asm volatile("cp.async.wait_group 1;" ::: "memory");
        } else {
            asm volatile("cp.async.wait_group 0;" ::: "memory");
        }
        if (DOTS && t < 256) sdots[t] = 0.f;
        __syncthreads();

        const __half* xs = (it & 1) ? xb1 : xb0;
        const int row0 = tile * 128;
        const unsigned a_addr = sptr(xs + (mrow + lrow) * LDW + lcol);

        float acc[8][4];
        #pragma unroll
        for (int f = 0; f < 8; f++) {
            acc[f][0] = 0.f; acc[f][1] = 0.f; acc[f][2] = 0.f; acc[f][3] = 0.f;
        }

        #pragma unroll
        for (int ks = 0; ks < 8; ks++) {
            unsigned a0, a1, a2, a3;
            ldsm_x4(a0, a1, a2, a3, a_addr + ks * 32);
            unsigned bkrow = b_addr + (unsigned)(ks * 16 * LDW * 2);
            #pragma unroll
            for (int np = 0; np < 4; np++) {
                unsigned b0, b1, b2, b3;
                ldsm_x4_t(b0, b1, b2, b3, bkrow + np * 32);
                mma16816(acc[np * 2][0], acc[np * 2][1], acc[np * 2][2], acc[np * 2][3],
                         a0, a1, a2, a3, b0, b1);
                mma16816(acc[np * 2 + 1][0], acc[np * 2 + 1][1], acc[np * 2 + 1][2],
                         acc[np * 2 + 1][3], a0, a1, a2, a3, b2, b3);
            }
        }

        if (DOTS) {
            float ps1 = 0.f, pd1 = 0.f, ps2 = 0.f, pd2 = 0.f;
            #pragma unroll
            for (int f = 0; f < 8; f++) {
                int col = ch * 64 + f * 8 + cb;
                float s0 = __ldg(asrc + col);
                float s1 = __ldg(asrc + col + 1);
                float d0 = __ldg(adst + col);
                float d1 = __ldg(adst + col + 1);
                ps1 += acc[f][0] * s0 + acc[f][1] * s1;
                pd1 += acc[f][0] * d0 + acc[f][1] * d1;
                ps2 += acc[f][2] * s0 + acc[f][3] * s1;
                pd2 += acc[f][2] * d0 + acc[f][3] * d1;
            }
            for (int o = 1; o <= 2; o <<= 1) {
                ps1 += __shfl_xor_sync(0xffffffffu, ps1, o);
                pd1 += __shfl_xor_sync(0xffffffffu, pd1, o);
                ps2 += __shfl_xor_sync(0xffffffffu, ps2, o);
                pd2 += __shfl_xor_sync(0xffffffffu, pd2, o);
            }
            if ((lane & 3) == 0) {
                atomicAdd(&sdots[2 * rl], ps1);
                atomicAdd(&sdots[2 * rl + 1], pd1);
                atomicAdd(&sdots[2 * (rl + 8)], ps2);
                atomicAdd(&sdots[2 * (rl + 8) + 1], pd2);
            }
        }

        #pragma unroll
        for (int f = 0; f < 8; f++) {
            int col = ch * 64 + f * 8 + cb;
            int gr = row0 + rl;
            if (gr < n) {
                unsigned h = packh2(acc[f][0], acc[f][1]);
                *(unsigned*)(Y + (size_t)gr * HD + col) = h;
            }
            int gr2 = gr + 8;
            if (gr2 < n) {
                unsigned h = packh2(acc[f][2], acc[f][3]);
                *(unsigned*)(Y + (size_t)gr2 * HD + col) = h;
            }
        }

        if (DOTS) {
            __syncthreads();
            if (t < 128) {
                int gr = row0 + t;
                if (gr < n) {
                    g_as[gr] = sdots[2 * t];
                    g_ad[gr] = sdots[2 * t + 1];
                }
            }
        }
        __syncthreads();
    }
}

// ====== GCN aggregation (fp16 gather, warp per dst node) — stores relu'd fp16 ======
__global__ __launch_bounds__(256) void k_gcn_agg(const float* __restrict__ bias, int n) {
    int w = (blockIdx.x * blockDim.x + threadIdx.x) >> 5;
    if (w >= n) return;
    int lane = threadIdx.x & 31;
    int beg = g_rowptr[w];
    int end = g_rowptr[w + 1];

    float di = g_dinv[w];
    float cself = di * di;
    float4 av = ldrow4h(g_Ah, w, lane);
    float4 b  = *(const float4*)(bias + lane * 4);
    float4 acc;
    acc.x = fmaf(cself, av.x, b.x);
    acc.y = fmaf(cself, av.y, b.y);
    acc.z = fmaf(cself, av.z, b.z);
    acc.w = fmaf(cself, av.w, b.w);

    for (int j0 = beg; j0 < end; j0 += 32) {
        int idx = j0 + lane;
        int s = 0;
        float c = 0.f;
        if (idx < end) { s = g_csr_src[idx]; c = g_csr_coef[idx]; }
        int m = min(32, end - j0);
        int j = 0;
        for (; j + 1 < m; j += 2) {
            int   s0 = __shfl_sync(0xffffffffu, s, j);
            float c0 = __shfl_sync(0xffffffffu, c, j);
            int   s1 = __shfl_sync(0xffffffffu, s, j + 1);
            float c1 = __shfl_sync(0xffffffffu, c, j + 1);
            float4 v0 = ldrow4h(g_Ah, s0, lane);
            float4 v1 = ldrow4h(g_Ah, s1, lane);
            acc.x = fmaf(c0, v0.x, acc.x); acc.y = fmaf(c0, v0.y, acc.y);
            acc.z = fmaf(c0, v0.z, acc.z); acc.w = fmaf(c0, v0.w, acc.w);
            acc.x = fmaf(c1, v1.x, acc.x); acc.y = fmaf(c1, v1.y, acc.y);
            acc.z = fmaf(c1, v1.z, acc.z); acc.w = fmaf(c1, v1.w, acc.w);
        }
        if (j < m) {
            int   s0 = __shfl_sync(0xffffffffu, s, j);
            float c0 = __shfl_sync(0xffffffffu, c, j);
            float4 v0 = ldrow4h(g_Ah, s0, lane);
            acc.x = fmaf(c0, v0.x, acc.x); acc.y = fmaf(c0, v0.y, acc.y);
            acc.z = fmaf(c0, v0.z, acc.z); acc.w = fmaf(c0, v0.w, acc.w);
        }
    }
    uint2 u;
    u.x = packh2(fmaxf(acc.x, 0.f), fmaxf(acc.y, 0.f));
    u.y = packh2(fmaxf(acc.z, 0.f), fmaxf(acc.w, 0.f));
    *(uint2*)(g_Bh + (size_t)w * HD + lane * 4) = u;
}

// ====== GAT: fused softmax + aggregation (warp per dst node, fp16 gather) ======
__global__ __launch_bounds__(256) void k_gat_agg(const float* __restrict__ bg, int n) {
    int w = (blockIdx.x * blockDim.x + threadIdx.x) >> 5;
    if (w >= n) return;
    int lane = threadIdx.x & 31;
    int beg = g_rowptr[w];
    int end = g_rowptr[w + 1];

    float ad_d = g_ad[w];
    float a_self = leaky(g_as[w] + ad_d);

    float mx = a_self;
    for (int idx = beg + lane; idx < end; idx += 32) {
        int s = g_csr_src[idx];
        mx = fmaxf(mx, leaky(g_as[s] + ad_d));
    }
    for (int o = 16; o; o >>= 1)
        mx = fmaxf(mx, __shfl_xor_sync(0xffffffffu, mx, o));

    float wself = expf(a_self - mx);
    float denp = 0.f;
    float4 av = ldrow4h(g_Ah, w, lane);
    float4 acc;
    acc.x = wself * av.x; acc.y = wself * av.y;
    acc.z = wself * av.z; acc.w = wself * av.w;

    for (int j0 = beg; j0 < end; j0 += 32) {
        int idx = j0 + lane;
        int s = 0;
        float ww = 0.f;
        if (idx < end) {
            s = g_csr_src[idx];
            ww = expf(leaky(g_as[s] + ad_d) - mx);
            denp += ww;
        }
        int m = min(32, end - j0);
        int j = 0;
        for (; j + 1 < m; j += 2) {
            int   s0 = __shfl_sync(0xffffffffu, s, j);
            float w0 = __shfl_sync(0xffffffffu, ww, j);
            int   s1 = __shfl_sync(0xffffffffu, s, j + 1);
            float w1 = __shfl_sync(0xffffffffu, ww, j + 1);
            float4 v0 = ldrow4h(g_Ah, s0, lane);
            float4 v1 = ldrow4h(g_Ah, s1, lane);
            acc.x = fmaf(w0, v0.x, acc.x); acc.y = fmaf(w0, v0.y, acc.y);
            acc.z = fmaf(w0, v0.z, acc.z); acc.w = fmaf(w0, v0.w, acc.w);
            acc.x = fmaf(w1, v1.x, acc.x); acc.y = fmaf(w1, v1.y, acc.y);
            acc.z = fmaf(w1, v1.z, acc.z); acc.w = fmaf(w1, v1.w, acc.w);
        }
        if (j < m) {
            int   s0 = __shfl_sync(0xffffffffu, s, j);
            float w0 = __shfl_sync(0xffffffffu, ww, j);
            float4 v0 = ldrow4h(g_Ah, s0, lane);
            acc.x = fmaf(w0, v0.x, acc.x); acc.y = fmaf(w0, v0.y, acc.y);
            acc.z = fmaf(w0, v0.z, acc.z); acc.w = fmaf(w0, v0.w, acc.w);
        }
    }
    for (int o = 16; o; o >>= 1)
        denp += __shfl_xor_sync(0xffffffffu, denp, o);
    float inv = 1.0f / (denp + wself);

    float4 b = *(const float4*)(bg + lane * 4);
    uint2 u;
    u.x = packh2(fmaf(acc.x, inv, b.x), fmaf(acc.y, inv, b.y));
    u.y = packh2(fmaf(acc.z, inv, b.z), fmaf(acc.w, inv, b.w));
    *(uint2*)(g_Bh + (size_t)w * HD + lane * 4) = u;
}

// ================= final: out = relu(Bh) @ Wc + bc (fp16 input) =================
__global__ __launch_bounds__(256) void k_out(const float* __restrict__ Wc,
                                             const float* __restrict__ bc,
                                             float* __restrict__ out, int n) {
    __shared__ float ws[128 * 16];
    for (int i = threadIdx.x; i < 128 * 16 / 4; i += 256)
        ((float4*)ws)[i] = ((const float4*)Wc)[i];
    __syncthreads();
    int i = blockIdx.x * blockDim.x + threadIdx.x;
    if (i >= n) return;

    float o16[16];
    for (int c = 0; c < 16; c++) o16[c] = bc[c];

    const __half* brow = g_Bh + (size_t)i * HD;
    #pragma unroll 4
    for (int k2 = 0; k2 < 64; k2++) {
        __half2 h = *(const __half2*)(brow + k2 * 2);
        float2 f = __half22float2(h);
        float b0 = fmaxf(f.x, 0.f);
        float b1 = fmaxf(f.y, 0.f);
        const float* w0 = ws + (k2 * 2) * 16;
        const float* w1 = w0 + 16;
        #pragma unroll
        for (int c = 0; c < 16; c++)
            o16[c] = fmaf(b0, w0[c], fmaf(b1, w1[c], o16[c]));
    }
    float* op = out + (size_t)i * 16;
    for (int c = 0; c < 16; c++) op[c] = o16[c];
}

static inline int ceildiv(int a, int b) { return (a + b - 1) / b; }

extern "C" void kernel_launch(void* const* d_in, const int* in_sizes, int n_in,
                              void* d_out, int out_size) {
    const float* x       = (const float*)d_in[0];
    const int*   ei      = (const int*)d_in[1];
    const float* ew      = (const float*)d_in[2];
    const float* W1      = (const float*)d_in[3];
    const float* b1      = (const float*)d_in[4];
    const float* W2      = (const float*)d_in[5];
    const float* b2      = (const float*)d_in[6];
    const float* Wg      = (const float*)d_in[7];
    const float* att_src = (const float*)d_in[8];
    const float* att_dst = (const float*)d_in[9];
    const float* bg      = (const float*)d_in[10];
    const float* Wc      = (const float*)d_in[11];
    const float* bc      = (const float*)d_in[12];

    int n = in_sizes[0] / HD;
    int e = in_sizes[2];
    const int* src = ei;
    const int* dst = ei + e;

    __half* dAh = nullptr;
    __half* dBh = nullptr;
    __half* dWh = nullptr;
    cudaGetSymbolAddress((void**)&dAh, g_Ah);
    cudaGetSymbolAddress((void**)&dBh, g_Bh);
    cudaGetSymbolAddress((void**)&dWh, g_Wh);

    const int SMEM = 3 * 128 * LDW * (int)sizeof(__half);   // 104448
    cudaFuncSetAttribute(k_gemm_tc<false>, cudaFuncAttributeMaxDynamicSharedMemorySize, SMEM);
    cudaFuncSetAttribute(k_gemm_tc<true>,  cudaFuncAttributeMaxDynamicSharedMemorySize, SMEM);

    // one-time stream/event setup (host objects only; no device memory)
    static cudaStream_t sB = nullptr;
    static cudaEvent_t evFork = nullptr, evJoin = nullptr;
    if (!sB) {
        cudaStreamCreateWithFlags(&sB, cudaStreamNonBlocking);
        cudaEventCreateWithFlags(&evFork, cudaEventDisableTiming);
        cudaEventCreateWithFlags(&evJoin, cudaEventDisableTiming);
    }

    const int tb = 256;
    const int tot_tiles = ceildiv(n, 128);
    const int gt = (tot_tiles < 296) ? tot_tiles : 296;
    const int ga = ceildiv(n, 8);
    const int nb = ceildiv(n, SCAN_B);

    // ---- fork: chain B (CSR build) runs concurrently with chain A (prep + gemm1) ----
    cudaEventRecord(evFork, 0);
    cudaStreamWaitEvent(sB, evFork, 0);

    // chain B (stream sB): CSR build
    k_zero<<<ceildiv(n, tb), tb, 0, sB>>>(n);
    k_count_deg<<<ceildiv(e, tb), tb, 0, sB>>>(dst, ew, e);
    k_scan1<<<nb, SCAN_B, 0, sB>>>(n);
    k_scan3_dinv<<<ceildiv(n, tb), tb, 0, sB>>>(n, nb);
    k_fill<<<ceildiv(e, tb), tb, 0, sB>>>(src, dst, ew, e);
    cudaEventRecord(evJoin, sB);

    // chain A (default stream): prep + GCN layer 1 GEMM
    k_prep<<<ceildiv(n * 32, tb), tb>>>(x, W1, W2, Wg, n);
    k_gemm_tc<false><<<gt, 512, SMEM>>>(dBh, dWh, dAh, nullptr, nullptr, n, tot_tiles);

    // join: aggregation needs both GEMM1 output and CSR
    cudaStreamWaitEvent(0, evJoin, 0);

    // serial tail
    k_gcn_agg<<<ga, tb>>>(b1, n);
    k_gemm_tc<false><<<gt, 512, SMEM>>>(dBh, dWh + 16384, dAh, nullptr, nullptr, n, tot_tiles);
    k_gcn_agg<<<ga, tb>>>(b2, n);
    k_gemm_tc<true><<<gt, 512, SMEM>>>(dBh, dWh + 32768, dAh, att_src, att_dst, n, tot_tiles);
    k_gat_agg<<<ga, tb>>>(bg, n);
    k_out<<<ceildiv(n, tb), tb>>>(Wc, bc, (float*)d_out, n);
}